// round 8
// baseline (speedup 1.0000x reference)
#include <cuda_runtime.h>
#include <cuda_bf16.h>
#include <math.h>
#include <stdint.h>

typedef __nv_bfloat16 bf16;

// ---------------- problem constants ----------------
#define NH    22501
#define NFEAT 22400
#define HW    150
#define C     512
#define NP    22528
#define PADN  27
#define HEADS 8
#define DH    64
#define MM    256
#define LL    88
#define QKVW  1536
#define NSPLIT 8

// ---------------- fp32 scratch ----------------
__device__ float g_h   [(long)NH*C];
__device__ float g_h2  [(long)NH*C];
__device__ float g_a2  [HEADS*MM*MM];
__device__ float g_attn[(long)NP*C];
__device__ float g_outl[(long)NH*C];
__device__ float g_rowsum[HEADS*MM];
__device__ float g_colsum[HEADS*MM];
__device__ float g_fm[NSPLIT*HEADS*MM];
__device__ float g_fs[NSPLIT*HEADS*MM];
__device__ float g_scale[1];

// ---------------- bf16 hi/lo pair scratch ----------------
__device__ bf16 g_xph[(long)NP*C],     g_xpl[(long)NP*C];
__device__ bf16 g_qkvh[(long)NP*QKVW], g_qkvl[(long)NP*QKVW];
__device__ bf16 g_qlh[HEADS*MM*DH],    g_qll[HEADS*MM*DH];
__device__ bf16 g_klh[HEADS*MM*DH],    g_kll[HEADS*MM*DH];
__device__ bf16 g_a2h[HEADS*MM*MM],    g_a2l[HEADS*MM*MM];
__device__ bf16 g_zh [HEADS*MM*MM], g_zl [HEADS*MM*MM];
__device__ bf16 g_zth[HEADS*MM*MM], g_ztl[HEADS*MM*MM];
__device__ bf16 g_z2h[HEADS*MM*MM], g_z2l[HEADS*MM*MM];
__device__ bf16 g_z2th[HEADS*MM*MM], g_z2tl[HEADS*MM*MM];
__device__ bf16 g_xzh[HEADS*MM*MM], g_xzl[HEADS*MM*MM];
__device__ bf16 g_tah[HEADS*MM*MM], g_tal[HEADS*MM*MM];
__device__ bf16 g_tbh[HEADS*MM*MM], g_tbl[HEADS*MM*MM];
__device__ bf16 g_vth[(long)HEADS*DH*NP], g_vtl[(long)HEADS*DH*NP];
__device__ bf16 g_a3h[HEADS*DH*MM],    g_a3l[HEADS*DH*MM];
__device__ bf16 g_Wth[HEADS*DH*MM],    g_Wtl[HEADS*DH*MM];
__device__ bf16 g_ath[(long)NP*C],     g_atl[(long)NP*C];
__device__ bf16 g_w1ah[(long)QKVW*C],  g_w1al[(long)QKVW*C];
__device__ bf16 g_w2ah[(long)C*C],     g_w2al[(long)C*C];
__device__ bf16 g_w1bh[(long)QKVW*C],  g_w1bl[(long)QKVW*C];
__device__ bf16 g_w2bh[(long)C*C],     g_w2bl[(long)C*C];

// ---------------- small device helpers ----------------
__device__ __forceinline__ uint32_t smem_to_u32(const void* p) {
    uint32_t a;
    asm("{ .reg .u64 t; cvta.to.shared.u64 t, %1; cvt.u32.u64 %0, t; }"
        : "=r"(a) : "l"(p));
    return a;
}
__device__ __forceinline__ void ldsm4(uint32_t addr, uint32_t& r0, uint32_t& r1,
                                      uint32_t& r2, uint32_t& r3)
{
    asm volatile("ldmatrix.sync.aligned.m8n8.x4.shared.b16 {%0,%1,%2,%3}, [%4];"
                 : "=r"(r0), "=r"(r1), "=r"(r2), "=r"(r3) : "r"(addr));
}
__device__ __forceinline__ void mma_bf16(float* c, const uint32_t* a,
                                         uint32_t b0, uint32_t b1)
{
    asm volatile("mma.sync.aligned.m16n8k16.row.col.f32.bf16.bf16.f32 "
                 "{%0,%1,%2,%3},{%4,%5,%6,%7},{%8,%9},{%0,%1,%2,%3};"
                 : "+f"(c[0]), "+f"(c[1]), "+f"(c[2]), "+f"(c[3])
                 : "r"(a[0]), "r"(a[1]), "r"(a[2]), "r"(a[3]), "r"(b0), "r"(b1));
}
__device__ __forceinline__ void cpa16(uint32_t dst, const void* src, int sz)
{
    asm volatile("cp.async.cg.shared.global [%0], [%1], 16, %2;"
                 :: "r"(dst), "l"(src), "r"(sz));
}
__device__ __forceinline__ uint32_t pack2(float a, float b)   // a->low, b->high
{
    uint32_t r;
    asm("cvt.rn.bf16x2.f32 %0, %1, %2;" : "=r"(r) : "f"(b), "f"(a));
    return r;
}
__device__ __forceinline__ void split_bf(float x, float& hi, float& lo)
{
    hi = __bfloat162float(__float2bfloat16(x));
    lo = x - hi;
}
__device__ __forceinline__ float pairval(const bf16* h, const bf16* l, long i)
{
    return __bfloat162float(h[i]) + __bfloat162float(l[i]);
}

// =======================================================================
// bf16x3 GEMM, operands pre-split; B always [N,K]. cp.async 3-stage.
// Tile 128xBN x32, 256 threads, 8 warps (4m x 2n), warp tile 32 x BN/2.
// =======================================================================
#define RS      80
#define AH_OFF  0
#define AL_OFF  10240

struct EpiOut {
    float* f; float falpha; int ldf; long sF;
    bf16 *ph, *pl; float palpha; int ldp; long sP;
    bf16 *th, *tl; float talpha, tdiag; int ldt; long sT;
    const float* resid;
    const float* bias;
};

template<int BN>
__global__ void __launch_bounds__(256)
gemm_p(const bf16* __restrict__ Ah, const bf16* __restrict__ Al,
       const bf16* __restrict__ Bh, const bf16* __restrict__ Bl,
       int M, int K, int lda, int ldb, long sA, long sB,
       EpiOut ep, int ksplit)
{
    constexpr int BH_OFF = 20480;
    constexpr int BL_OFF = 20480 + BN * RS;
    constexpr int STAGE  = 20480 + 2 * BN * RS;
    constexpr int NT     = BN / 16;       // n8 tiles per warp

    extern __shared__ __align__(16) char sm[];
    const uint32_t sb0 = smem_to_u32(sm);
    const int tid = threadIdx.x, warp = tid >> 5, lane = tid & 31;
    const int wm = warp & 3, wn = warp >> 2;

    const int z = blockIdx.z;
    const int batch = z / ksplit;
    const int split = z - batch * ksplit;
    Ah += (long)batch * sA;  Al += (long)batch * sA;
    Bh += (long)batch * sB;  Bl += (long)batch * sB;

    const int row0 = blockIdx.y * 128, col0 = blockIdx.x * BN;
    const int kchunk = K / ksplit, kbase = split * kchunk, nch = kchunk >> 5;

    float acc[2][NT][4];
    #pragma unroll
    for (int i = 0; i < 2; i++)
        #pragma unroll
        for (int j = 0; j < NT; j++)
            #pragma unroll
            for (int q = 0; q < 4; q++) acc[i][j][q] = 0.f;

    auto issue = [&](int it) {
        const int stg = it % 3;
        const uint32_t sb = sb0 + stg * STAGE;
        const int kc = kbase + it * 32;
        #pragma unroll
        for (int rep = 0; rep < 2; rep++) {
            int c = tid + rep * 256;
            int row = c >> 2, seg = c & 3;
            int gm = row0 + row;
            long go = (long)gm * lda + kc + seg * 8;
            int sz = (gm < M) ? 16 : 0;
            cpa16(sb + AH_OFF + row * RS + seg * 16, Ah + go, sz);
            cpa16(sb + AL_OFF + row * RS + seg * 16, Al + go, sz);
        }
        #pragma unroll
        for (int rep = 0; rep < BN / 64; rep++) {
            int c = tid + rep * 256;
            int n = c >> 2, seg = c & 3;
            long go = (long)(col0 + n) * ldb + kc + seg * 8;
            cpa16(sb + BH_OFF + n * RS + seg * 16, Bh + go, 16);
            cpa16(sb + BL_OFF + n * RS + seg * 16, Bl + go, 16);
        }
        asm volatile("cp.async.commit_group;");
    };

    const int rsel = (lane & 7) + ((lane >> 3) & 1) * 8;
    const int ksel = ((lane >> 4) & 1) * 16;
    auto do_mma = [&](int stg) {
        uint32_t sb = sb0 + stg * STAGE;
        #pragma unroll
        for (int kk = 0; kk < 2; kk++) {
            uint32_t ah[2][4], al[2][4];
            #pragma unroll
            for (int mt = 0; mt < 2; mt++) {
                uint32_t ad = sb + AH_OFF + (wm * 32 + mt * 16 + rsel) * RS + kk * 32 + ksel;
                ldsm4(ad, ah[mt][0], ah[mt][1], ah[mt][2], ah[mt][3]);
                ldsm4(ad + (AL_OFF - AH_OFF), al[mt][0], al[mt][1], al[mt][2], al[mt][3]);
            }
            #pragma unroll
            for (int np = 0; np < BN / 32; np++) {
                uint32_t bd = sb + BH_OFF + (wn * (BN / 2) + np * 16 + rsel) * RS + kk * 32 + ksel;
                uint32_t q0, q1, q2, q3, r0, r1, r2, r3;
                ldsm4(bd, q0, q1, q2, q3);
                ldsm4(bd + (BL_OFF - BH_OFF), r0, r1, r2, r3);
                #pragma unroll
                for (int mt = 0; mt < 2; mt++) {
                    mma_bf16(acc[mt][2*np],   ah[mt], q0, q2);
                    mma_bf16(acc[mt][2*np],   ah[mt], r0, r2);
                    mma_bf16(acc[mt][2*np],   al[mt], q0, q2);
                    mma_bf16(acc[mt][2*np+1], ah[mt], q1, q3);
                    mma_bf16(acc[mt][2*np+1], ah[mt], r1, r3);
                    mma_bf16(acc[mt][2*np+1], al[mt], q1, q3);
                }
            }
        }
    };

    issue(0);
    if (nch > 1) issue(1);
    for (int it = 0; it < nch; it++) {
        if (it + 1 < nch) asm volatile("cp.async.wait_group 1;");
        else              asm volatile("cp.async.wait_group 0;");
        __syncthreads();
        if (it + 2 < nch) issue(it + 2);
        do_mma(it % 3);
    }

    // ---- epilogue ----
    const int er = lane >> 2, eq = lane & 3;
    float* F  = ep.f  ? ep.f  + (long)z     * ep.sF : (float*)0;
    bf16* Ph  = ep.ph ? ep.ph + (long)batch * ep.sP : (bf16*)0;
    bf16* Pl  = ep.pl ? ep.pl + (long)batch * ep.sP : (bf16*)0;
    bf16* Th  = ep.th ? ep.th + (long)batch * ep.sT : (bf16*)0;
    bf16* Tl  = ep.tl ? ep.tl + (long)batch * ep.sT : (bf16*)0;

    #pragma unroll
    for (int mt = 0; mt < 2; mt++)
        #pragma unroll
        for (int nt = 0; nt < NT; nt++) {
            int gr0 = row0 + wm * 32 + mt * 16 + er;
            int gc  = col0 + wn * (BN / 2) + nt * 8 + 2 * eq;
            #pragma unroll
            for (int half = 0; half < 2; half++) {
                int gr = gr0 + 8 * half;
                if (gr >= M) continue;
                float va = acc[mt][nt][2 * half], vb = acc[mt][nt][2 * half + 1];
                if (F) {
                    float o0 = ep.falpha * va, o1 = ep.falpha * vb;
                    if (ep.bias)  { o0 += ep.bias[gc]; o1 += ep.bias[gc + 1]; }
                    if (ep.resid) {
                        o0 += ep.resid[(long)gr * ep.ldf + gc];
                        o1 += ep.resid[(long)gr * ep.ldf + gc + 1];
                    }
                    *reinterpret_cast<float2*>(F + (long)gr * ep.ldf + gc) =
                        make_float2(o0, o1);
                }
                if (Ph) {
                    float s0 = ep.palpha * va, s1 = ep.palpha * vb;
                    float h0, l0, h1, l1;
                    split_bf(s0, h0, l0); split_bf(s1, h1, l1);
                    *reinterpret_cast<uint32_t*>(Ph + (long)gr * ep.ldp + gc) = pack2(h0, h1);
                    *reinterpret_cast<uint32_t*>(Pl + (long)gr * ep.ldp + gc) = pack2(l0, l1);
                }
                if (Th) {
                    #pragma unroll
                    for (int j = 0; j < 2; j++) {
                        int cc = gc + j;
                        float v = (j == 0) ? va : vb;
                        float s = ep.talpha * v + ((gr == cc) ? ep.tdiag : 0.f);
                        float hi, lo; split_bf(s, hi, lo);
                        Th[(long)cc * ep.ldt + gr] = __float2bfloat16(hi);
                        Tl[(long)cc * ep.ldt + gr] = __float2bfloat16(lo);
                    }
                }
            }
        }
}

#define GP_SMEM64  (3 * (20480 + 2 * 64 * RS))
#define GP_SMEM128 (3 * (20480 + 2 * 128 * RS))

static EpiOut epi0() { EpiOut e{}; return e; }
static void gemmP(const bf16* Ah, const bf16* Al, const bf16* Bh, const bf16* Bl,
                  int M, int N, int K, int lda, int ldb, long sA, long sB,
                  int batch, int ksplit, EpiOut ep)
{
    if (N % 128 == 0 && N >= 512) {
        dim3 g(N / 128, (M + 127) / 128, batch * ksplit), b(256);
        gemm_p<128><<<g, b, GP_SMEM128>>>(Ah, Al, Bh, Bl, M, K, lda, ldb, sA, sB, ep, ksplit);
    } else {
        dim3 g(N / 64, (M + 127) / 128, batch * ksplit), b(256);
        gemm_p<64><<<g, b, GP_SMEM64>>>(Ah, Al, Bh, Bl, M, K, lda, ldb, sA, sB, ep, ksplit);
    }
}

// =======================================================================
// flash-fused S3 path (unchanged from R7)
// =======================================================================
#define FL_RS   144
#define FL_QH   0
#define FL_QL   18432
#define FL_K(b) (36864 + (b) * 18432)
#define FL_V(b) (73728 + (b) * 18432)
#define FL_PH   110592
#define FL_PL   129024
#define FL_SMEM 147456
#define FL_NCH  ((NP / NSPLIT) / 64)

__global__ void __launch_bounds__(128)
flash3_k(const bf16* __restrict__ qlh, const bf16* __restrict__ qll,
         const bf16* __restrict__ qkvh, const bf16* __restrict__ qkvl,
         const bf16* __restrict__ vth, const bf16* __restrict__ vtl,
         float* __restrict__ pO, float* __restrict__ pm, float* __restrict__ ps)
{
    extern __shared__ __align__(16) char sm[];
    const uint32_t sb = smem_to_u32(sm);
    const int tid = threadIdx.x, warp = tid >> 5, lane = tid & 31;
    const int split = blockIdx.x, rowHalf = blockIdx.y, head = blockIdx.z;
    const int tb0 = split * (NP / NSPLIT);

    const bf16* Qh = qlh + ((long)head * MM + rowHalf * 128) * DH;
    const bf16* Ql = qll + ((long)head * MM + rowHalf * 128) * DH;
    #pragma unroll
    for (int i = 0; i < 8; i++) {
        int s = tid + 128 * i;
        int r = s >> 3, seg = s & 7;
        long go = (long)r * DH + seg * 8;
        cpa16(sb + FL_QH + r * FL_RS + seg * 16, Qh + go, 16);
        cpa16(sb + FL_QL + r * FL_RS + seg * 16, Ql + go, 16);
    }

    const bf16* Kh = qkvh + head * DH + 512;
    const bf16* Kl = qkvl + head * DH + 512;
    const bf16* Vh = vth + (long)head * DH * NP;
    const bf16* Vl = vtl + (long)head * DH * NP;

    auto kissue = [&](int j) {
        int buf = j & 1;
        int tb = tb0 + j * 64;
        uint32_t kb = sb + FL_K(buf);
        uint32_t vb = sb + FL_V(buf);
        #pragma unroll
        for (int i = 0; i < 4; i++) {
            int s = tid + 128 * i;
            int r = s >> 3, seg = s & 7;
            long gk = (long)(tb + r) * QKVW + seg * 8;
            cpa16(kb + r * FL_RS + seg * 16, Kh + gk, 16);
            cpa16(kb + 9216 + r * FL_RS + seg * 16, Kl + gk, 16);
            long gv = (long)r * NP + tb + seg * 8;
            cpa16(vb + r * FL_RS + seg * 16, Vh + gv, 16);
            cpa16(vb + 9216 + r * FL_RS + seg * 16, Vl + gv, 16);
        }
        asm volatile("cp.async.commit_group;");
    };
    kissue(0);
    kissue(1);

    const int rsel = (lane & 7) + ((lane >> 3) & 1) * 8;
    const int ksel = ((lane >> 4) & 1) * 16;
    const int er = lane >> 2, eq = lane & 3;

    float m_run[4] = {-1e30f, -1e30f, -1e30f, -1e30f};
    float s_run[4] = {0.f, 0.f, 0.f, 0.f};
    float oacc[2][8][4];
    #pragma unroll
    for (int a = 0; a < 2; a++)
        #pragma unroll
        for (int b = 0; b < 8; b++)
            #pragma unroll
            for (int c = 0; c < 4; c++) oacc[a][b][c] = 0.f;

    for (int j = 0; j < FL_NCH; j++) {
        if (j + 1 < FL_NCH) asm volatile("cp.async.wait_group 1;");
        else                asm volatile("cp.async.wait_group 0;");
        __syncthreads();
        uint32_t kb = sb + FL_K(j & 1);
        uint32_t vb = sb + FL_V(j & 1);

        float sacc[2][8][4];
        #pragma unroll
        for (int a = 0; a < 2; a++)
            #pragma unroll
            for (int b = 0; b < 8; b++)
                #pragma unroll
                for (int c = 0; c < 4; c++) sacc[a][b][c] = 0.f;

        #pragma unroll
        for (int k16 = 0; k16 < 4; k16++) {
            uint32_t ah[2][4], al[2][4];
            #pragma unroll
            for (int mt = 0; mt < 2; mt++) {
                uint32_t ad = sb + FL_QH + (warp * 32 + mt * 16 + rsel) * FL_RS + k16 * 32 + ksel;
                ldsm4(ad, ah[mt][0], ah[mt][1], ah[mt][2], ah[mt][3]);
                ldsm4(ad + (FL_QL - FL_QH), al[mt][0], al[mt][1], al[mt][2], al[mt][3]);
            }
            #pragma unroll
            for (int n16 = 0; n16 < 4; n16++) {
                uint32_t bd = kb + (n16 * 16 + rsel) * FL_RS + k16 * 32 + ksel;
                uint32_t q0, q1, q2, q3, p0, p1, p2, p3;
                ldsm4(bd, q0, q1, q2, q3);
                ldsm4(bd + 9216, p0, p1, p2, p3);
                #pragma unroll
                for (int mt = 0; mt < 2; mt++) {
                    mma_bf16(sacc[mt][2*n16],   ah[mt], q0, q2);
                    mma_bf16(sacc[mt][2*n16],   ah[mt], p0, p2);
                    mma_bf16(sacc[mt][2*n16],   al[mt], q0, q2);
                    mma_bf16(sacc[mt][2*n16+1], ah[mt], q1, q3);
                    mma_bf16(sacc[mt][2*n16+1], ah[mt], p1, p3);
                    mma_bf16(sacc[mt][2*n16+1], al[mt], q1, q3);
                }
            }
        }

        #pragma unroll
        for (int mt = 0; mt < 2; mt++) {
            float cm0 = -1e30f, cm1 = -1e30f;
            #pragma unroll
            for (int nt = 0; nt < 8; nt++) {
                cm0 = fmaxf(cm0, fmaxf(sacc[mt][nt][0], sacc[mt][nt][1]));
                cm1 = fmaxf(cm1, fmaxf(sacc[mt][nt][2], sacc[mt][nt][3]));
            }
            #pragma unroll
            for (int o = 1; o <= 2; o <<= 1) {
                cm0 = fmaxf(cm0, __shfl_xor_sync(0xffffffffu, cm0, o));
                cm1 = fmaxf(cm1, __shfl_xor_sync(0xffffffffu, cm1, o));
            }
            float mn0 = fmaxf(m_run[2*mt],     cm0);
            float mn1 = fmaxf(m_run[2*mt + 1], cm1);
            float sc0 = __expf(m_run[2*mt]     - mn0);
            float sc1 = __expf(m_run[2*mt + 1] - mn1);
            m_run[2*mt] = mn0; m_run[2*mt + 1] = mn1;
            float ls0 = 0.f, ls1 = 0.f;
            int pr = warp * 32 + mt * 16 + er;
            #pragma unroll
            for (int nt = 0; nt < 8; nt++) {
                float e0 = __expf(sacc[mt][nt][0] - mn0);
                float e1 = __expf(sacc[mt][nt][1] - mn0);
                float e2 = __expf(sacc[mt][nt][2] - mn1);
                float e3 = __expf(sacc[mt][nt][3] - mn1);
                ls0 += e0 + e1; ls1 += e2 + e3;
                oacc[mt][nt][0] *= sc0; oacc[mt][nt][1] *= sc0;
                oacc[mt][nt][2] *= sc1; oacc[mt][nt][3] *= sc1;
                int col = nt * 8 + 2 * eq;
                float h0, l0, h1, l1;
                split_bf(e0, h0, l0); split_bf(e1, h1, l1);
                *reinterpret_cast<uint32_t*>(sm + FL_PH + pr * FL_RS + col * 2) = pack2(h0, h1);
                *reinterpret_cast<uint32_t*>(sm + FL_PL + pr * FL_RS + col * 2) = pack2(l0, l1);
                split_bf(e2, h0, l0); split_bf(e3, h1, l1);
                *reinterpret_cast<uint32_t*>(sm + FL_PH + (pr + 8) * FL_RS + col * 2) = pack2(h0, h1);
                *reinterpret_cast<uint32_t*>(sm + FL_PL + (pr + 8) * FL_RS + col * 2) = pack2(l0, l1);
            }
            #pragma unroll
            for (int o = 1; o <= 2; o <<= 1) {
                ls0 += __shfl_xor_sync(0xffffffffu, ls0, o);
                ls1 += __shfl_xor_sync(0xffffffffu, ls1, o);
            }
            s_run[2*mt]     = s_run[2*mt]     * sc0 + ls0;
            s_run[2*mt + 1] = s_run[2*mt + 1] * sc1 + ls1;
        }
        __syncthreads();

        #pragma unroll
        for (int k16 = 0; k16 < 4; k16++) {
            uint32_t ph[2][4], pl[2][4];
            #pragma unroll
            for (int mt = 0; mt < 2; mt++) {
                uint32_t ad = sb + FL_PH + (warp * 32 + mt * 16 + rsel) * FL_RS + k16 * 32 + ksel;
                ldsm4(ad, ph[mt][0], ph[mt][1], ph[mt][2], ph[mt][3]);
                ldsm4(ad + (FL_PL - FL_PH), pl[mt][0], pl[mt][1], pl[mt][2], pl[mt][3]);
            }
            #pragma unroll
            for (int n16 = 0; n16 < 4; n16++) {
                uint32_t bd = vb + (n16 * 16 + rsel) * FL_RS + k16 * 32 + ksel;
                uint32_t q0, q1, q2, q3, r0, r1, r2, r3;
                ldsm4(bd, q0, q1, q2, q3);
                ldsm4(bd + 9216, r0, r1, r2, r3);
                #pragma unroll
                for (int mt = 0; mt < 2; mt++) {
                    mma_bf16(oacc[mt][2*n16],   ph[mt], q0, q2);
                    mma_bf16(oacc[mt][2*n16],   ph[mt], r0, r2);
                    mma_bf16(oacc[mt][2*n16],   pl[mt], q0, q2);
                    mma_bf16(oacc[mt][2*n16+1], ph[mt], q1, q3);
                    mma_bf16(oacc[mt][2*n16+1], ph[mt], r1, r3);
                    mma_bf16(oacc[mt][2*n16+1], pl[mt], q1, q3);
                }
            }
        }
        __syncthreads();
        if (j + 2 < FL_NCH) kissue(j + 2);
    }

    const int base = (split * HEADS + head) * MM + rowHalf * 128;
    #pragma unroll
    for (int mt = 0; mt < 2; mt++) {
        int r0 = base + warp * 32 + mt * 16 + er;
        #pragma unroll
        for (int nt = 0; nt < 8; nt++) {
            int d = nt * 8 + 2 * eq;
            *reinterpret_cast<float2*>(pO + (long)r0 * DH + d) =
                make_float2(oacc[mt][nt][0], oacc[mt][nt][1]);
            *reinterpret_cast<float2*>(pO + (long)(r0 + 8) * DH + d) =
                make_float2(oacc[mt][nt][2], oacc[mt][nt][3]);
        }
        if (eq == 0) {
            pm[r0] = m_run[2*mt];     ps[r0] = s_run[2*mt];
            pm[r0 + 8] = m_run[2*mt + 1]; ps[r0 + 8] = s_run[2*mt + 1];
        }
    }
}

__global__ void flash_merge_k(const float* __restrict__ pO, const float* __restrict__ pm,
                              const float* __restrict__ ps,
                              bf16* __restrict__ oh, bf16* __restrict__ ol)
{
    int row = blockIdx.x, head = blockIdx.y, d = threadIdx.x;
    float mx = -1e30f;
    #pragma unroll
    for (int i = 0; i < NSPLIT; i++)
        mx = fmaxf(mx, pm[(i * HEADS + head) * MM + row]);
    float den = 0.f, acc = 0.f;
    #pragma unroll
    for (int i = 0; i < NSPLIT; i++) {
        int r = (i * HEADS + head) * MM + row;
        float w = __expf(pm[r] - mx);
        den += w * ps[r];
        acc += w * pO[(long)r * DH + d];
    }
    float v = acc / den;
    float hi, lo; split_bf(v, hi, lo);
    long o = ((long)head << 14) + d * MM + row;
    oh[o] = __float2bfloat16(hi);
    ol[o] = __float2bfloat16(lo);
}

// =======================================================================
// fused S1 -> softmax -> O1 (unchanged)
// =======================================================================
#define FA_RS1  144
#define FA_AH   0
#define FA_AL   9216
#define FA_BH   18432
#define FA_BL   55296
#define FA_PH   0
#define FA_PL   33792
#define FA_WS   67584
#define FA_WST  10240
#define FA_SMEM 98304

__global__ void __launch_bounds__(128)
fused_attn1_k(const bf16* __restrict__ qh, const bf16* __restrict__ ql_,
              const bf16* __restrict__ klh, const bf16* __restrict__ kll,
              const bf16* __restrict__ Wth, const bf16* __restrict__ Wtl,
              float* __restrict__ attn)
{
    extern __shared__ __align__(16) char sm[];
    const uint32_t sb = smem_to_u32(sm);
    const int tid = threadIdx.x, warp = tid >> 5, lane = tid & 31;
    const int row0 = blockIdx.x * 64;
    const int head = blockIdx.y;

    const bf16* qsh = qh  + (long)row0 * QKVW + head * DH;
    const bf16* qsl = ql_ + (long)row0 * QKVW + head * DH;
    #pragma unroll
    for (int i = 0; i < 4; i++) {
        int s = tid + 128 * i;
        int r = s >> 3, seg = s & 7;
        long go = (long)r * QKVW + seg * 8;
        cpa16(sb + FA_AH + r * FA_RS1 + seg * 16, qsh + go, 16);
        cpa16(sb + FA_AL + r * FA_RS1 + seg * 16, qsl + go, 16);
    }
    const bf16* ksh = klh + (long)head * MM * DH;
    const bf16* ksl = kll + (long)head * MM * DH;
    #pragma unroll
    for (int i = 0; i < 16; i++) {
        int s = tid + 128 * i;
        int r = s >> 3, seg = s & 7;
        long go = (long)r * DH + seg * 8;
        cpa16(sb + FA_BH + r * FA_RS1 + seg * 16, ksh + go, 16);
        cpa16(sb + FA_BL + r * FA_RS1 + seg * 16, ksl + go, 16);
    }
    asm volatile("cp.async.commit_group;");
    asm volatile("cp.async.wait_group 0;");
    __syncthreads();

    const int rsel = (lane & 7) + ((lane >> 3) & 1) * 8;
    const int ksel = ((lane >> 4) & 1) * 16;
    float sacc[32][4];
    #pragma unroll
    for (int i = 0; i < 32; i++)
        #pragma unroll
        for (int j = 0; j < 4; j++) sacc[i][j] = 0.f;

    #pragma unroll
    for (int k16 = 0; k16 < 4; k16++) {
        uint32_t ah[4], al[4];
        uint32_t ad = sb + FA_AH + (warp * 16 + rsel) * FA_RS1 + k16 * 32 + ksel;
        ldsm4(ad, ah[0], ah[1], ah[2], ah[3]);
        ldsm4(ad + (FA_AL - FA_AH), al[0], al[1], al[2], al[3]);
        #pragma unroll
        for (int n16 = 0; n16 < 16; n16++) {
            uint32_t bd = sb + FA_BH + (n16 * 16 + rsel) * FA_RS1 + k16 * 32 + ksel;
            uint32_t q0, q1, q2, q3, p0, p1, p2, p3;
            ldsm4(bd, q0, q1, q2, q3);
            ldsm4(bd + (FA_BL - FA_BH), p0, p1, p2, p3);
            mma_bf16(sacc[2*n16],   ah, q0, q2);
            mma_bf16(sacc[2*n16],   ah, p0, p2);
            mma_bf16(sacc[2*n16],   al, q0, q2);
            mma_bf16(sacc[2*n16+1], ah, q1, q3);
            mma_bf16(sacc[2*n16+1], ah, p1, p3);
            mma_bf16(sacc[2*n16+1], al, q1, q3);
        }
    }

    float mx0 = -1e30f, mx1 = -1e30f;
    #pragma unroll
    for (int nt = 0; nt < 32; nt++) {
        #pragma unroll
        for (int j = 0; j < 4; j++) sacc[nt][j] *= 0.125f;
        mx0 = fmaxf(mx0, fmaxf(sacc[nt][0], sacc[nt][1]));
        mx1 = fmaxf(mx1, fmaxf(sacc[nt][2], sacc[nt][3]));
    }
    #pragma unroll
    for (int o = 1; o <= 2; o <<= 1) {
        mx0 = fmaxf(mx0, __shfl_xor_sync(0xffffffffu, mx0, o));
        mx1 = fmaxf(mx1, __shfl_xor_sync(0xffffffffu, mx1, o));
    }
    float sm0 = 0.f, sm1 = 0.f;
    #pragma unroll
    for (int nt = 0; nt < 32; nt++) {
        sacc[nt][0] = __expf(sacc[nt][0] - mx0);
        sacc[nt][1] = __expf(sacc[nt][1] - mx0);
        sacc[nt][2] = __expf(sacc[nt][2] - mx1);
        sacc[nt][3] = __expf(sacc[nt][3] - mx1);
        sm0 += sacc[nt][0] + sacc[nt][1];
        sm1 += sacc[nt][2] + sacc[nt][3];
    }
    #pragma unroll
    for (int o = 1; o <= 2; o <<= 1) {
        sm0 += __shfl_xor_sync(0xffffffffu, sm0, o);
        sm1 += __shfl_xor_sync(0xffffffffu, sm1, o);
    }
    __syncthreads();

    const bf16* Wsh = Wth + (long)head * DH * MM;
    const bf16* Wsl = Wtl + (long)head * DH * MM;
    auto wissue = [&](int it) {
        int stg = it % 3;
        uint32_t base = sb + FA_WS + stg * FA_WST;
        #pragma unroll
        for (int i = 0; i < 2; i++) {
            int s = tid + 128 * i;
            int r = s >> 2, seg = s & 3;
            long go = (long)r * MM + it * 32 + seg * 8;
            cpa16(base + r * 80 + seg * 16, Wsh + go, 16);
            cpa16(base + 5120 + r * 80 + seg * 16, Wsl + go, 16);
        }
        asm volatile("cp.async.commit_group;");
    };
    wissue(0); wissue(1);

    {
        int pr = warp * 16 + (lane >> 2);
        int pc = (lane & 3) * 2;
        #pragma unroll
        for (int nt = 0; nt < 32; nt++) {
            int col = nt * 8 + pc;
            float h0, l0, h1, l1;
            split_bf(sacc[nt][0], h0, l0); split_bf(sacc[nt][1], h1, l1);
            *reinterpret_cast<uint32_t*>(sm + FA_PH + pr * 528 + col * 2) = pack2(h0, h1);
            *reinterpret_cast<uint32_t*>(sm + FA_PL + pr * 528 + col * 2) = pack2(l0, l1);
            split_bf(sacc[nt][2], h0, l0); split_bf(sacc[nt][3], h1, l1);
            *reinterpret_cast<uint32_t*>(sm + FA_PH + (pr + 8) * 528 + col * 2) = pack2(h0, h1);
            *reinterpret_cast<uint32_t*>(sm + FA_PL + (pr + 8) * 528 + col * 2) = pack2(l0, l1);
        }
    }
    __syncthreads();

    float oacc[8][4];
    #pragma unroll
    for (int i = 0; i < 8; i++)
        #pragma unroll
        for (int j = 0; j < 4; j++) oacc[i][j] = 0.f;

    for (int it = 0; it < 8; it++) {
        if (it < 7) asm volatile("cp.async.wait_group 1;");
        else        asm volatile("cp.async.wait_group 0;");
        __syncthreads();
        if (it + 2 < 8) wissue(it + 2);
        uint32_t wb = sb + FA_WS + (it % 3) * FA_WST;
        #pragma unroll
        for (int k16 = 0; k16 < 2; k16++) {
            int gk = it * 2 + k16;
            uint32_t ph[4], pl[4];
            uint32_t ad = sb + FA_PH + (warp * 16 + rsel) * 528 + gk * 32 + ksel;
            ldsm4(ad, ph[0], ph[1], ph[2], ph[3]);
            ldsm4(ad + (FA_PL - FA_PH), pl[0], pl[1], pl[2], pl[3]);
            #pragma unroll
            for (int n16 = 0; n16 < 4; n16++) {
                uint32_t bd = wb + (n16 * 16 + rsel) * 80 + k16 * 32 + ksel;
                uint32_t q0, q1, q2, q3, r0, r1, r2, r3;
                ldsm4(bd, q0, q1, q2, q3);
                ldsm4(bd + 5120, r0, r1, r2, r3);
                mma_bf16(oacc[2*n16],   ph, q0, q2);
                mma_bf16(oacc[2*n16],   ph, r0, r2);
                mma_bf16(oacc[2*n16],   pl, q0, q2);
                mma_bf16(oacc[2*n16+1], ph, q1, q3);
                mma_bf16(oacc[2*n16+1], ph, r1, r3);
                mma_bf16(oacc[2*n16+1], pl, q1, q3);
            }
        }
    }

    float inv0 = 1.f / sm0, inv1 = 1.f / sm1;
    int orow = row0 + warp * 16 + (lane >> 2);
    int ocol = head * DH + (lane & 3) * 2;
    #pragma unroll
    for (int nt = 0; nt < 8; nt++) {
        int col = ocol + nt * 8;
        *reinterpret_cast<float2*>(attn + (long)orow * C + col) =
            make_float2(oacc[nt][0] * inv0, oacc[nt][1] * inv0);
        *reinterpret_cast<float2*>(attn + (long)(orow + 8) * C + col) =
            make_float2(oacc[nt][2] * inv1, oacc[nt][3] * inv1);
    }
}

// =======================================================================
// auxiliary kernels (unchanged)
// =======================================================================

__global__ void wconvT_k(const float* __restrict__ w, bf16* __restrict__ th,
                         bf16* __restrict__ tl, int K, int N)
{
    int i = blockIdx.x * 256 + threadIdx.x;
    if (i >= N * K) return;
    int n = i / K, k = i - n * K;
    float v = w[(long)k * N + n];
    float hi, lo; split_bf(v, hi, lo);
    th[i] = __float2bfloat16(hi);
    tl[i] = __float2bfloat16(lo);
}

__global__ void build_h_k(const float* __restrict__ feat, const float* __restrict__ cls,
                          float* __restrict__ h)
{
    long i = (long)blockIdx.x * 256 + threadIdx.x;
    if (i >= (long)NH * C) return;
    long t = i >> 9;
    int  c = (int)(i & 511);
    float v;
    if (t == 0) v = cls[c];
    else {
        long r = t - 1;
        if (r >= NFEAT) r -= NFEAT;
        v = feat[r * C + c];
    }
    h[i] = v;
}

__global__ void ln_pad_k(const float* __restrict__ h, bf16* __restrict__ xh,
                         bf16* __restrict__ xl,
                         const float* __restrict__ g, const float* __restrict__ b)
{
    int t = blockIdx.x, c = threadIdx.x;
    long o = (long)t * C;
    if (t < PADN) {
        *reinterpret_cast<uint32_t*>(xh + o + 2 * c) = 0u;
        *reinterpret_cast<uint32_t*>(xl + o + 2 * c) = 0u;
        return;
    }
    const float* row = h + (long)(t - PADN) * C;
    float a1 = row[2 * c], a2 = row[2 * c + 1];
    __shared__ float red[256];
    red[c] = a1 + a2; __syncthreads();
    for (int s = 128; s > 0; s >>= 1) { if (c < s) red[c] += red[c + s]; __syncthreads(); }
    float mu = red[0] * (1.f / 512.f);
    __syncthreads();
    float d1 = a1 - mu, d2 = a2 - mu;
    red[c] = d1 * d1 + d2 * d2; __syncthreads();
    for (int s = 128; s > 0; s >>= 1) { if (c < s) red[c] += red[c + s]; __syncthreads(); }
    float inv = rsqrtf(red[0] * (1.f / 512.f) + 1e-5f);
    float v1 = d1 * inv * g[2 * c] + b[2 * c];
    float v2 = d2 * inv * g[2 * c + 1] + b[2 * c + 1];
    float h1, l1, h2, l2;
    split_bf(v1, h1, l1); split_bf(v2, h2, l2);
    *reinterpret_cast<uint32_t*>(xh + o + 2 * c) = pack2(h1, h2);
    *reinterpret_cast<uint32_t*>(xl + o + 2 * c) = pack2(l1, l2);
}

__global__ void landmarks_k(const bf16* __restrict__ qh, const bf16* __restrict__ ql_,
                            bf16* __restrict__ qlh, bf16* __restrict__ qll,
                            bf16* __restrict__ klh, bf16* __restrict__ kll)
{
    int d = threadIdx.x;
    int m = blockIdx.x & 255;
    int hh = blockIdx.x >> 8;
    long base = (long)(m * LL) * QKVW + hh * DH + d;
    float sq = 0.f, sk = 0.f;
    for (int j = 0; j < LL; j++) {
        long o = base + (long)j * QKVW;
        sq += pairval(qh, ql_, o);
        sk += pairval(qh, ql_, o + 512);
    }
    float vq = sq * (0.125f / (float)LL);
    float vk = sk * (1.f / (float)LL);
    int oi = (hh * MM + m) * DH + d;
    float hi, lo;
    split_bf(vq, hi, lo); qlh[oi] = __float2bfloat16(hi); qll[oi] = __float2bfloat16(lo);
    split_bf(vk, hi, lo); klh[oi] = __float2bfloat16(hi); kll[oi] = __float2bfloat16(lo);
}

__global__ void softmax256_k(const float* __restrict__ in, float* __restrict__ fout,
                             bf16* __restrict__ ph, bf16* __restrict__ pl, long nrows)
{
    long row = (long)blockIdx.x * 8 + threadIdx.y;
    if (row >= nrows) return;
    const float* r = in + row * 256;
    int lane = threadIdx.x;
    float v[8], m = -1e30f;
    #pragma unroll
    for (int i = 0; i < 8; i++) { v[i] = r[lane + 32 * i]; m = fmaxf(m, v[i]); }
    #pragma unroll
    for (int o = 16; o; o >>= 1) m = fmaxf(m, __shfl_xor_sync(0xffffffffu, m, o));
    float s = 0.f;
    #pragma unroll
    for (int i = 0; i < 8; i++) { v[i] = __expf(v[i] - m); s += v[i]; }
    #pragma unroll
    for (int o = 16; o; o >>= 1) s += __shfl_xor_sync(0xffffffffu, s, o);
    float inv = 1.f / s;
    #pragma unroll
    for (int i = 0; i < 8; i++) {
        float val = v[i] * inv;
        long o = row * 256 + lane + 32 * i;
        if (fout) fout[o] = val;
        float hi, lo; split_bf(val, hi, lo);
        ph[o] = __float2bfloat16(hi);
        pl[o] = __float2bfloat16(lo);
    }
}

__global__ void pinv_sums_k(const float* __restrict__ a2,
                            float* __restrict__ rs, float* __restrict__ cs)
{
    int hh = blockIdx.x, j = threadIdx.x;
    const float* X = a2 + (long)hh * MM * MM;
    float r = 0.f, c = 0.f;
    for (int k = 0; k < MM; k++) { r += fabsf(X[j * MM + k]); c += fabsf(X[k * MM + j]); }
    rs[hh * MM + j] = r; cs[hh * MM + j] = c;
}
__global__ void pinv_scale_k(const float* __restrict__ rs, const float* __restrict__ cs,
                             float* __restrict__ scale)
{
    __shared__ float m1[256], m2[256];
    float a = -1e30f, b = -1e30f;
    for (int i = threadIdx.x; i < HEADS * MM; i += 256) { a = fmaxf(a, rs[i]); b = fmaxf(b, cs[i]); }
    m1[threadIdx.x] = a; m2[threadIdx.x] = b; __syncthreads();
    for (int s = 128; s > 0; s >>= 1) {
        if (threadIdx.x < s) {
            m1[threadIdx.x] = fmaxf(m1[threadIdx.x], m1[threadIdx.x + s]);
            m2[threadIdx.x] = fmaxf(m2[threadIdx.x], m2[threadIdx.x + s]);
        }
        __syncthreads();
    }
    if (threadIdx.x == 0) scale[0] = 1.f / (m1[0] * m2[0]);
}
__global__ void pinv_init_k(const float* __restrict__ a2, const float* __restrict__ scale,
                            bf16* __restrict__ zph, bf16* __restrict__ zpl,
                            bf16* __restrict__ zth, bf16* __restrict__ ztl)
{
    long i = (long)blockIdx.x * 256 + threadIdx.x;
    if (i >= (long)HEADS * MM * MM) return;
    float s = scale[0];
    long hb = i & ~65535L;
    int r = (int)((i >> 8) & 255), c = (int)(i & 255);
    float vt = a2[i] * s;
    float vp = a2[hb + ((long)c << 8) + r] * s;
    float hi, lo;
    split_bf(vt, hi, lo); zth[i] = __float2bfloat16(hi); ztl[i] = __float2bfloat16(lo);
    split_bf(vp, hi, lo); zph[i] = __float2bfloat16(hi); zpl[i] = __float2bfloat16(lo);
}

__global__ void vT_k(const bf16* __restrict__ qh, const bf16* __restrict__ ql_,
                     bf16* __restrict__ vth, bf16* __restrict__ vtl)
{
    __shared__ bf16 tile[32][33];
    int t0 = blockIdx.x * 32;
    int head = blockIdx.y >> 1;
    int lopart = blockIdx.y & 1;
    int d0 = blockIdx.z * 32;
    const bf16* src = (lopart ? ql_ : qh) + 1024 + head * 64 + d0;
    bf16* dst = (lopart ? vtl : vth) + (long)head * 64 * NP + (long)d0 * NP;
    int tx = threadIdx.x, ty = threadIdx.y;
    #pragma unroll
    for (int i = 0; i < 4; i++)
        tile[ty + 8 * i][tx] = src[(long)(t0 + ty + 8 * i) * QKVW + tx];
    __syncthreads();
    #pragma unroll
    for (int i = 0; i < 4; i++)
        dst[(long)(ty + 8 * i) * NP + t0 + tx] = tile[tx][ty + 8 * i];
}

__global__ void conv_add_k(const bf16* __restrict__ qh, const bf16* __restrict__ ql_,
                           const float* __restrict__ rw, const float* __restrict__ attnf,
                           bf16* __restrict__ ah, bf16* __restrict__ al)
{
    int t = blockIdx.x, c = threadIdx.x;
    int hh = c >> 6;
    float acc = attnf[(long)t * C + c];
    #pragma unroll
    for (int k = 0; k < 33; k++) {
        int tt = t + k - 16;
        if ((unsigned)tt < (unsigned)NP)
            acc += pairval(qh, ql_, (long)tt * QKVW + 1024 + c) * rw[hh * 33 + k];
    }
    float hi, lo; split_bf(acc, hi, lo);
    long o = (long)t * C + c;
    ah[o] = __float2bfloat16(hi);
    al[o] = __float2bfloat16(lo);
}

__global__ void ppeg_k(const float* __restrict__ h, float* __restrict__ h2,
                       const float* __restrict__ w7, const float* __restrict__ b7,
                       const float* __restrict__ w5, const float* __restrict__ b5,
                       const float* __restrict__ w3, const float* __restrict__ b3)
{
    int x = blockIdx.x, y = blockIdx.y, c = threadIdx.x;
    if (x == 0 && y == 0) h2[c] = h[c];
    float acc = h[(long)(1 + y * HW + x) * C + c];
    #pragma unroll
    for (int ky = 0; ky < 7; ky++) {
        int yy = y + ky - 3; if (yy < 0 || yy >= HW) continue;
        #pragma unroll
        for (int kx = 0; kx < 7; kx++) {
            int xx = x + kx - 3; if (xx < 0 || xx >= HW) continue;
            acc += h[(long)(1 + yy * HW + xx) * C + c] * w7[c * 49 + ky * 7 + kx];
        }
    }
    #pragma unroll
    for (int ky = 0; ky < 5; ky++) {
        int yy = y + ky - 2; if (yy < 0 || yy >= HW) continue;
        #pragma unroll
        for (int kx = 0; kx < 5; kx++) {
            int xx = x + kx - 2; if (xx < 0 || xx >= HW) continue;
            acc += h[(long)(1 + yy * HW + xx) * C + c] * w5[c * 25 + ky * 5 + kx];
        }
    }
    #pragma unroll
    for (int ky = 0; ky < 3; ky++) {
        int yy = y + ky - 1; if (yy < 0 || yy >= HW) continue;
        #pragma unroll
        for (int kx = 0; kx < 3; kx++) {
            int xx = x + kx - 1; if (xx < 0 || xx >= HW) continue;
            acc += h[(long)(1 + yy * HW + xx) * C + c] * w3[c * 9 + ky * 3 + kx];
        }
    }
    acc += b7[c] + b5[c] + b3[c];
    h2[(long)(1 + y * HW + x) * C + c] = acc;
}

// ================= host orchestration =================
struct Ptrs {
    float *h, *h2, *a2, *attn, *outl, *rowsum, *colsum, *fm, *fs, *scale;
    bf16 *xph, *xpl, *qkvh, *qkvl, *qlh, *qll, *klh, *kll,
         *a2h, *a2l, *zh, *zl, *zth, *ztl, *z2h, *z2l, *z2th, *z2tl,
         *xzh, *xzl, *tah, *tal, *tbh, *tbl, *vth, *vtl,
         *a3h, *a3l, *Wth, *Wtl, *ath, *atl,
         *w1ah, *w1al, *w2ah, *w2al, *w1bh, *w1bl, *w2bh, *w2bl;
};
#define GSYM(f, s) cudaGetSymbolAddress((void**)&p.f, s)
static void get_ptrs(Ptrs& p)
{
    GSYM(h, g_h); GSYM(h2, g_h2); GSYM(a2, g_a2);
    GSYM(attn, g_attn); GSYM(outl, g_outl);
    GSYM(rowsum, g_rowsum); GSYM(colsum, g_colsum);
    GSYM(fm, g_fm); GSYM(fs, g_fs); GSYM(scale, g_scale);
    GSYM(xph, g_xph); GSYM(xpl, g_xpl); GSYM(qkvh, g_qkvh); GSYM(qkvl, g_qkvl);
    GSYM(qlh, g_qlh); GSYM(qll, g_qll); GSYM(klh, g_klh); GSYM(kll, g_kll);
    GSYM(a2h, g_a2h); GSYM(a2l, g_a2l);
    GSYM(zh, g_zh); GSYM(zl, g_zl); GSYM(zth, g_zth); GSYM(ztl, g_ztl);
    GSYM(z2h, g_z2h); GSYM(z2l, g_z2l); GSYM(z2th, g_z2th); GSYM(z2tl, g_z2tl);
    GSYM(xzh, g_xzh); GSYM(xzl, g_xzl);
    GSYM(tah, g_tah); GSYM(tal, g_tal); GSYM(tbh, g_tbh); GSYM(tbl, g_tbl);
    GSYM(vth, g_vth); GSYM(vtl, g_vtl); GSYM(a3h, g_a3h); GSYM(a3l, g_a3l);
    GSYM(Wth, g_Wth); GSYM(Wtl, g_Wtl); GSYM(ath, g_ath); GSYM(atl, g_atl);
    GSYM(w1ah, g_w1ah); GSYM(w1al, g_w1al); GSYM(w2ah, g_w2ah); GSYM(w2al, g_w2al);
    GSYM(w1bh, g_w1bh); GSYM(w1bl, g_w1bl); GSYM(w2bh, g_w2bh); GSYM(w2bl, g_w2bl);
}

static void nystrom_layer(Ptrs& p, float* h_io,
                          const float* ln_g, const float* ln_b,
                          const bf16* w1h, const bf16* w1l,
                          const bf16* w2h, const bf16* w2l,
                          const float* b_out, const float* res_w)
{
    const long MMh = (long)MM * MM;

    // 1) LN + pad -> xp pair
    ln_pad_k<<<NP, 256>>>(h_io, p.xph, p.xpl, ln_g, ln_b);

    // 2) qkv pair = xp @ wqkv
    { EpiOut e = epi0(); e.ph = p.qkvh; e.pl = p.qkvl; e.palpha = 1.f; e.ldp = QKVW;
      gemmP(p.xph, p.xpl, w1h, w1l, NP, QKVW, C, C, C, 0, 0, 1, 1, e); }

    // 3) landmarks + vT
    landmarks_k<<<HEADS * MM, DH>>>(p.qkvh, p.qkvl, p.qlh, p.qll, p.klh, p.kll);
    vT_k<<<dim3(NP / 32, HEADS * 2, 2), dim3(32, 8)>>>(p.qkvh, p.qkvl, p.vth, p.vtl);

    // 4) a2 = softmax(ql @ kl^T)
    { EpiOut e = epi0(); e.f = p.a2; e.falpha = 1.f; e.ldf = MM; e.sF = MMh;
      gemmP(p.qlh, p.qll, p.klh, p.kll, MM, MM, DH, DH, DH,
            (long)MM * DH, (long)MM * DH, HEADS, 1, e); }
    softmax256_k<<<(HEADS * MM + 7) / 8, dim3(32, 8)>>>(p.a2, p.a2, p.a2h, p.a2l, HEADS * MM);

    // 5) pinv
    pinv_sums_k<<<HEADS, 256>>>(p.a2, p.rowsum, p.colsum);
    pinv_scale_k<<<1, 256>>>(p.rowsum, p.colsum, p.scale);
    pinv_init_k<<<(int)((HEADS * MMh + 255) / 256), 256>>>(p.a2, p.scale,
                                                           p.zh, p.zl, p.zth, p.ztl);
    bf16 *zch = p.zh, *zcl = p.zl, *zcth = p.zth, *zctl = p.ztl;
    bf16 *znh = p.z2h, *znl = p.z2l, *znth = p.z2th, *zntl = p.z2tl;
    for (int it = 0; it < 6; it++) {
        { EpiOut e = epi0();
          e.ph = p.xzh; e.pl = p.xzl; e.palpha = 1.f; e.ldp = MM; e.sP = MMh;
          e.th = p.tah; e.tl = p.tal; e.talpha = -1.f; e.tdiag = 7.f; e.ldt = MM; e.sT = MMh;
          gemmP(p.a2h, p.a2l, zcth, zctl, MM, MM, MM, MM, MM, MMh, MMh, HEADS, 1, e); }
        { EpiOut e = epi0();
          e.th = p.tbh; e.tl = p.tbl; e.talpha = -1.f; e.tdiag = 15.f; e.ldt = MM; e.sT = MMh;
          gemmP(p.xzh, p.xzl, p.tah, p.tal, MM, MM, MM, MM, MM, MMh, MMh, HEADS, 1, e); }
        { EpiOut e = epi0();
          e.th = p.tah; e.tl = p.tal; e.talpha = -1.f; e.tdiag = 13.f; e.ldt = MM; e.sT = MMh;
          gemmP(p.xzh, p.xzl, p.tbh, p.tbl, MM, MM, MM, MM, MM, MMh, MMh, HEADS, 1, e); }
        { EpiOut e = epi0();
          e.ph = znh; e.pl = znl; e.palpha = 0.25f; e.ldp = MM; e.sP = MMh;
          e.th = znth; e.tl = zntl; e.talpha = 0.25f; e.tdiag = 0.f; e.ldt = MM; e.sT = MMh;
          gemmP(zch, zcl, p.tah, p.tal, MM, MM, MM, MM, MM, MMh, MMh, HEADS, 1, e); }
        bf16* t;
        t = zch; zch = znh; znh = t;   t = zcl; zcl = znl; znl = t;
        t = zcth; zcth = znth; znth = t; t = zctl; zctl = zntl; zntl = t;
    }

    // 6) flash-fused S3 -> softmax -> a3v
    flash3_k<<<dim3(NSPLIT, 2, HEADS), 128, FL_SMEM>>>(
        p.qlh, p.qll, p.qkvh, p.qkvl, p.vth, p.vtl, p.outl, p.fm, p.fs);
    flash_merge_k<<<dim3(MM, HEADS), DH>>>(p.outl, p.fm, p.fs, p.a3h, p.a3l);

    // 7) W^T pair = (z @ a3v)^T
    { EpiOut e = epi0(); e.th = p.Wth; e.tl = p.Wtl; e.talpha = 1.f; e.tdiag = 0.f;
      e.ldt = MM; e.sT = (long)DH * MM;
      gemmP(zch, zcl, p.a3h, p.a3l, MM, DH, MM, MM, MM, MMh, (long)DH * MM, HEADS, 1, e); }

    // 8) fused S1 -> softmax -> O1 -> attn fp32
    fused_attn1_k<<<dim3(NP / 64, HEADS), 128, FA_SMEM>>>(
        p.qkvh, p.qkvl, p.klh, p.kll, p.Wth, p.Wtl, p.attn);

    // 9) attn pair = attn + conv(v)
    conv_add_k<<<NP, C>>>(p.qkvh, p.qkvl, res_w, p.attn, p.ath, p.atl);

    // 10) h += attn[PADN:] @ wout + bias
    { EpiOut e = epi0(); e.f = h_io; e.falpha = 1.f; e.ldf = C;
      e.resid = h_io; e.bias = b_out;
      gemmP(p.ath + (long)PADN * C, p.atl + (long)PADN * C, w2h, w2l,
            NH, C, C, C, C, 0, 0, 1, 1, e); }
}

extern "C" void kernel_launch(void* const* d_in, const int* in_sizes, int n_in,
                              void* d_out, int out_size)
{
    const float* features = (const float*)d_in[0];
    const float* cls      = (const float*)d_in[1];
    const float* ln1_g    = (const float*)d_in[2];
    const float* ln1_b    = (const float*)d_in[3];
    const float* qkv1_w   = (const float*)d_in[4];
    const float* out1_w   = (const float*)d_in[5];
    const float* out1_b   = (const float*)d_in[6];
    const float* res1_w   = (const float*)d_in[7];
    const float* pe_w7    = (const float*)d_in[8];
    const float* pe_b7    = (const float*)d_in[9];
    const float* pe_w5    = (const float*)d_in[10];
    const float* pe_b5    = (const float*)d_in[11];
    const float* pe_w3    = (const float*)d_in[12];
    const float* pe_b3    = (const float*)d_in[13];
    const float* ln2_g    = (const float*)d_in[14];
    const float* ln2_b    = (const float*)d_in[15];
    const float* qkv2_w   = (const float*)d_in[16];
    const float* out2_w   = (const float*)d_in[17];
    const float* out2_b   = (const float*)d_in[18];
    const float* res2_w   = (const float*)d_in[19];

    cudaFuncSetAttribute(gemm_p<64>,  cudaFuncAttributeMaxDynamicSharedMemorySize, GP_SMEM64);
    cudaFuncSetAttribute(gemm_p<128>, cudaFuncAttributeMaxDynamicSharedMemorySize, GP_SMEM128);
    cudaFuncSetAttribute(fused_attn1_k, cudaFuncAttributeMaxDynamicSharedMemorySize, FA_SMEM);
    cudaFuncSetAttribute(flash3_k, cudaFuncAttributeMaxDynamicSharedMemorySize, FL_SMEM);

    Ptrs p; get_ptrs(p);

    // launch order: build_h(1), wconv qkv1(2), ln_pad(3), qkv gemm(4) <- profiled
    build_h_k<<<(int)(((long)NH * C + 255) / 256), 256>>>(features, cls, p.h);
    wconvT_k<<<(QKVW * C + 255) / 256, 256>>>(qkv1_w, p.w1ah, p.w1al, C, QKVW);
    ln_pad_k<<<NP, 256>>>(p.h, p.xph, p.xpl, ln1_g, ln1_b);
    { EpiOut e = epi0(); e.ph = p.qkvh; e.pl = p.qkvl; e.palpha = 1.f; e.ldp = QKVW;
      gemmP(p.xph, p.xpl, p.w1ah, p.w1al, NP, QKVW, C, C, C, 0, 0, 1, 1, e); }

    // remaining weight converts (before their consumers)
    wconvT_k<<<(C * C + 255) / 256, 256>>>(out1_w, p.w2ah, p.w2al, C, C);
    wconvT_k<<<(QKVW * C + 255) / 256, 256>>>(qkv2_w, p.w1bh, p.w1bl, C, QKVW);
    wconvT_k<<<(C * C + 255) / 256, 256>>>(out2_w, p.w2bh, p.w2bl, C, C);

    // layer 1, continuing after its qkv (steps 3..10)
    {
        const long MMh = (long)MM * MM;
        landmarks_k<<<HEADS * MM, DH>>>(p.qkvh, p.qkvl, p.qlh, p.qll, p.klh, p.kll);
        vT_k<<<dim3(NP / 32, HEADS * 2, 2), dim3(32, 8)>>>(p.qkvh, p.qkvl, p.vth, p.vtl);
        { EpiOut e = epi0(); e.f = p.a2; e.falpha = 1.f; e.ldf = MM; e.sF = MMh;
          gemmP(p.qlh, p.qll, p.klh, p.kll, MM, MM, DH, DH, DH,
                (long)MM * DH, (long)MM * DH, HEADS, 1, e); }
        softmax256_k<<<(HEADS * MM + 7) / 8, dim3(32, 8)>>>(p.a2, p.a2, p.a2h, p.a2l, HEADS * MM);
        pinv_sums_k<<<HEADS, 256>>>(p.a2, p.rowsum, p.colsum);
        pinv_scale_k<<<1, 256>>>(p.rowsum, p.colsum, p.scale);
        pinv_init_k<<<(int)((HEADS * MMh + 255) / 256), 256>>>(p.a2, p.scale,
                                                               p.zh, p.zl, p.zth, p.ztl);
        bf16 *zch = p.zh, *zcl = p.zl, *zcth = p.zth, *zctl = p.ztl;
        bf16 *znh = p.z2h, *znl = p.z2l, *znth = p.z2th, *zntl = p.z2tl;
        for (int it = 0; it < 6; it++) {
            { EpiOut e = epi0();
              e.ph = p.xzh; e.pl = p.xzl; e.palpha = 1.f; e.ldp = MM; e.sP = MMh;
              e.th = p.tah; e.tl = p.tal; e.talpha = -1.f; e.tdiag = 7.f; e.ldt = MM; e.sT = MMh;
              gemmP(p.a2h, p.a2l, zcth, zctl, MM, MM, MM, MM, MM, MMh, MMh, HEADS, 1, e); }
            { EpiOut e = epi0();
              e.th = p.tbh; e.tl = p.tbl; e.talpha = -1.f; e.tdiag = 15.f; e.ldt = MM; e.sT = MMh;
              gemmP(p.xzh, p.xzl, p.tah, p.tal, MM, MM, MM, MM, MM, MMh, MMh, HEADS, 1, e); }
            { EpiOut e = epi0();
              e.th = p.tah; e.tl = p.tal; e.talpha = -1.f; e.tdiag = 13.f; e.ldt = MM; e.sT = MMh;
              gemmP(p.xzh, p.xzl, p.tbh, p.tbl, MM, MM, MM, MM, MM, MMh, MMh, HEADS, 1, e); }
            { EpiOut e = epi0();
              e.ph = znh; e.pl = znl; e.palpha = 0.25f; e.ldp = MM; e.sP = MMh;
              e.th = znth; e.tl = zntl; e.talpha = 0.25f; e.tdiag = 0.f; e.ldt = MM; e.sT = MMh;
              gemmP(zch, zcl, p.tah, p.tal, MM, MM, MM, MM, MM, MMh, MMh, HEADS, 1, e); }
            bf16* t;
            t = zch; zch = znh; znh = t;   t = zcl; zcl = znl; znl = t;
            t = zcth; zcth = znth; znth = t; t = zctl; zctl = zntl; zntl = t;
        }
        flash3_k<<<dim3(NSPLIT, 2, HEADS), 128, FL_SMEM>>>(
            p.qlh, p.qll, p.qkvh, p.qkvl, p.vth, p.vtl, p.outl, p.fm, p.fs);
        flash_merge_k<<<dim3(MM, HEADS), DH>>>(p.outl, p.fm, p.fs, p.a3h, p.a3l);
        { EpiOut e = epi0(); e.th = p.Wth; e.tl = p.Wtl; e.talpha = 1.f; e.tdiag = 0.f;
          e.ldt = MM; e.sT = (long)DH * MM;
          gemmP(zch, zcl, p.a3h, p.a3l, MM, DH, MM, MM, MM, MMh, (long)DH * MM, HEADS, 1, e); }
        fused_attn1_k<<<dim3(NP / 64, HEADS), 128, FA_SMEM>>>(
            p.qkvh, p.qkvl, p.klh, p.kll, p.Wth, p.Wtl, p.attn);
        conv_add_k<<<NP, C>>>(p.qkvh, p.qkvl, res1_w, p.attn, p.ath, p.atl);
        { EpiOut e = epi0(); e.f = p.h; e.falpha = 1.f; e.ldf = C;
          e.resid = p.h; e.bias = out1_b;
          gemmP(p.ath + (long)PADN * C, p.atl + (long)PADN * C, p.w2ah, p.w2al,
                NH, C, C, C, C, 0, 0, 1, 1, e); }
    }

    ppeg_k<<<dim3(HW, HW), C>>>(p.h, p.h2, pe_w7, pe_b7, pe_w5, pe_b5, pe_w3, pe_b3);

    nystrom_layer(p, p.h2, ln2_g, ln2_b, p.w1bh, p.w1bl, p.w2bh, p.w2bl, out2_b, res2_w);

    cudaMemcpyAsync(d_out, p.h2, (size_t)out_size * sizeof(float),
                    cudaMemcpyDeviceToDevice);
}

// round 9
// speedup vs baseline: 1.0515x; 1.0515x over previous
#include <cuda_runtime.h>
#include <cuda_bf16.h>
#include <math.h>
#include <stdint.h>

typedef __nv_bfloat16 bf16;

// ---------------- problem constants ----------------
#define NH    22501
#define NFEAT 22400
#define HW    150
#define C     512
#define NP    22528
#define PADN  27
#define HEADS 8
#define DH    64
#define MM    256
#define LL    88
#define QKVW  1536
#define NSPLIT 8

// ---------------- fp32 scratch ----------------
__device__ float g_h   [(long)NH*C];
__device__ float g_h2  [(long)NH*C];
__device__ float g_a2  [HEADS*MM*MM];
__device__ float g_attn[(long)NP*C];
__device__ float g_outl[(long)NH*C];
__device__ float g_rowsum[HEADS*MM];
__device__ float g_colsum[HEADS*MM];
__device__ float g_fm[NSPLIT*HEADS*MM];
__device__ float g_fs[NSPLIT*HEADS*MM];
__device__ float g_scale[1];

// ---------------- bf16 hi/lo pair scratch ----------------
__device__ bf16 g_xph[(long)NP*C],     g_xpl[(long)NP*C];
__device__ bf16 g_qkvh[(long)NP*QKVW], g_qkvl[(long)NP*QKVW];
__device__ bf16 g_qlh[HEADS*MM*DH],    g_qll[HEADS*MM*DH];
__device__ bf16 g_klh[HEADS*MM*DH],    g_kll[HEADS*MM*DH];
__device__ bf16 g_a2h[HEADS*MM*MM],    g_a2l[HEADS*MM*MM];
__device__ bf16 g_zh [HEADS*MM*MM], g_zl [HEADS*MM*MM];
__device__ bf16 g_zth[HEADS*MM*MM], g_ztl[HEADS*MM*MM];
__device__ bf16 g_z2h[HEADS*MM*MM], g_z2l[HEADS*MM*MM];
__device__ bf16 g_z2th[HEADS*MM*MM], g_z2tl[HEADS*MM*MM];
__device__ bf16 g_xzh[HEADS*MM*MM], g_xzl[HEADS*MM*MM];
__device__ bf16 g_tah[HEADS*MM*MM], g_tal[HEADS*MM*MM];
__device__ bf16 g_tbh[HEADS*MM*MM], g_tbl[HEADS*MM*MM];
__device__ bf16 g_vth[(long)HEADS*DH*NP], g_vtl[(long)HEADS*DH*NP];
__device__ bf16 g_a3h[HEADS*DH*MM],    g_a3l[HEADS*DH*MM];
__device__ bf16 g_Wth[HEADS*DH*MM],    g_Wtl[HEADS*DH*MM];
__device__ bf16 g_ath[(long)NP*C],     g_atl[(long)NP*C];
__device__ bf16 g_w1ah[(long)QKVW*C],  g_w1al[(long)QKVW*C];
__device__ bf16 g_w2ah[(long)C*C],     g_w2al[(long)C*C];
__device__ bf16 g_w1bh[(long)QKVW*C],  g_w1bl[(long)QKVW*C];
__device__ bf16 g_w2bh[(long)C*C],     g_w2bl[(long)C*C];

// ---------------- small device helpers ----------------
__device__ __forceinline__ uint32_t smem_to_u32(const void* p) {
    uint32_t a;
    asm("{ .reg .u64 t; cvta.to.shared.u64 t, %1; cvt.u32.u64 %0, t; }"
        : "=r"(a) : "l"(p));
    return a;
}
__device__ __forceinline__ void ldsm4(uint32_t addr, uint32_t& r0, uint32_t& r1,
                                      uint32_t& r2, uint32_t& r3)
{
    asm volatile("ldmatrix.sync.aligned.m8n8.x4.shared.b16 {%0,%1,%2,%3}, [%4];"
                 : "=r"(r0), "=r"(r1), "=r"(r2), "=r"(r3) : "r"(addr));
}
__device__ __forceinline__ void mma_bf16(float* c, const uint32_t* a,
                                         uint32_t b0, uint32_t b1)
{
    asm volatile("mma.sync.aligned.m16n8k16.row.col.f32.bf16.bf16.f32 "
                 "{%0,%1,%2,%3},{%4,%5,%6,%7},{%8,%9},{%0,%1,%2,%3};"
                 : "+f"(c[0]), "+f"(c[1]), "+f"(c[2]), "+f"(c[3])
                 : "r"(a[0]), "r"(a[1]), "r"(a[2]), "r"(a[3]), "r"(b0), "r"(b1));
}
__device__ __forceinline__ void cpa16(uint32_t dst, const void* src, int sz)
{
    asm volatile("cp.async.cg.shared.global [%0], [%1], 16, %2;"
                 :: "r"(dst), "l"(src), "r"(sz));
}
__device__ __forceinline__ uint32_t pack2(float a, float b)   // a->low, b->high
{
    uint32_t r;
    asm("cvt.rn.bf16x2.f32 %0, %1, %2;" : "=r"(r) : "f"(b), "f"(a));
    return r;
}
__device__ __forceinline__ void split_bf(float x, float& hi, float& lo)
{
    hi = __bfloat162float(__float2bfloat16(x));
    lo = x - hi;
}
__device__ __forceinline__ float pairval(const bf16* h, const bf16* l, long i)
{
    return __bfloat162float(h[i]) + __bfloat162float(l[i]);
}

// =======================================================================
// bf16x3 GEMM, operands pre-split; B always [N,K]. cp.async 3-stage.
// Tile 128x64x32, 256 threads, 8 warps (4m x 2n), warp tile 32x32.
// __launch_bounds__(256,2) caps regs at 128 -> guaranteed 2 CTAs/SM.
// =======================================================================
#define RS      80
#define AH_OFF  0
#define AL_OFF  10240
#define BH_OFF  20480
#define BL_OFF  25600
#define STAGE   30720
#define GP_SMEM (3 * STAGE)

struct EpiOut {
    float* f; float falpha; int ldf; long sF;
    bf16 *ph, *pl; float palpha; int ldp; long sP;
    bf16 *th, *tl; float talpha, tdiag; int ldt; long sT;
    const float* resid;
    const float* bias;
};

__global__ void __launch_bounds__(256, 2)
gemm_p(const bf16* __restrict__ Ah, const bf16* __restrict__ Al,
       const bf16* __restrict__ Bh, const bf16* __restrict__ Bl,
       int M, int K, int lda, int ldb, long sA, long sB,
       EpiOut ep, int ksplit)
{
    extern __shared__ __align__(16) char sm[];
    const uint32_t sb0 = smem_to_u32(sm);
    const int tid = threadIdx.x, warp = tid >> 5, lane = tid & 31;
    const int wm = warp & 3, wn = warp >> 2;

    const int z = blockIdx.z;
    const int batch = z / ksplit;
    const int split = z - batch * ksplit;
    Ah += (long)batch * sA;  Al += (long)batch * sA;
    Bh += (long)batch * sB;  Bl += (long)batch * sB;

    const int row0 = blockIdx.y * 128, col0 = blockIdx.x * 64;
    const int kchunk = K / ksplit, kbase = split * kchunk, nch = kchunk >> 5;

    float acc[2][4][4];
    #pragma unroll
    for (int i = 0; i < 2; i++)
        #pragma unroll
        for (int j = 0; j < 4; j++)
            #pragma unroll
            for (int q = 0; q < 4; q++) acc[i][j][q] = 0.f;

    auto issue = [&](int it) {
        const int stg = it % 3;
        const uint32_t sb = sb0 + stg * STAGE;
        const int kc = kbase + it * 32;
        #pragma unroll
        for (int rep = 0; rep < 2; rep++) {
            int c = tid + rep * 256;
            int row = c >> 2, seg = c & 3;
            int gm = row0 + row;
            long go = (long)gm * lda + kc + seg * 8;
            int sz = (gm < M) ? 16 : 0;
            cpa16(sb + AH_OFF + row * RS + seg * 16, Ah + go, sz);
            cpa16(sb + AL_OFF + row * RS + seg * 16, Al + go, sz);
        }
        {
            int n = tid >> 2, seg = tid & 3;
            long go = (long)(col0 + n) * ldb + kc + seg * 8;
            cpa16(sb + BH_OFF + n * RS + seg * 16, Bh + go, 16);
            cpa16(sb + BL_OFF + n * RS + seg * 16, Bl + go, 16);
        }
        asm volatile("cp.async.commit_group;");
    };

    const int rsel = (lane & 7) + ((lane >> 3) & 1) * 8;
    const int ksel = ((lane >> 4) & 1) * 16;
    auto do_mma = [&](int stg) {
        uint32_t sb = sb0 + stg * STAGE;
        #pragma unroll
        for (int kk = 0; kk < 2; kk++) {
            uint32_t ah[2][4], al[2][4];
            #pragma unroll
            for (int mt = 0; mt < 2; mt++) {
                uint32_t ad = sb + AH_OFF + (wm * 32 + mt * 16 + rsel) * RS + kk * 32 + ksel;
                ldsm4(ad, ah[mt][0], ah[mt][1], ah[mt][2], ah[mt][3]);
                ldsm4(ad + (AL_OFF - AH_OFF), al[mt][0], al[mt][1], al[mt][2], al[mt][3]);
            }
            #pragma unroll
            for (int np = 0; np < 2; np++) {
                uint32_t bd = sb + BH_OFF + (wn * 32 + np * 16 + rsel) * RS + kk * 32 + ksel;
                uint32_t q0, q1, q2, q3, r0, r1, r2, r3;
                ldsm4(bd, q0, q1, q2, q3);
                ldsm4(bd + (BL_OFF - BH_OFF), r0, r1, r2, r3);
                #pragma unroll
                for (int mt = 0; mt < 2; mt++) {
                    mma_bf16(acc[mt][2*np],   ah[mt], q0, q2);
                    mma_bf16(acc[mt][2*np],   ah[mt], r0, r2);
                    mma_bf16(acc[mt][2*np],   al[mt], q0, q2);
                    mma_bf16(acc[mt][2*np+1], ah[mt], q1, q3);
                    mma_bf16(acc[mt][2*np+1], ah[mt], r1, r3);
                    mma_bf16(acc[mt][2*np+1], al[mt], q1, q3);
                }
            }
        }
    };

    issue(0);
    if (nch > 1) issue(1);
    for (int it = 0; it < nch; it++) {
        if (it + 1 < nch) asm volatile("cp.async.wait_group 1;");
        else              asm volatile("cp.async.wait_group 0;");
        __syncthreads();
        if (it + 2 < nch) issue(it + 2);
        do_mma(it % 3);
    }

    // ---- epilogue ----
    const int er = lane >> 2, eq = lane & 3;
    float* F  = ep.f  ? ep.f  + (long)z     * ep.sF : (float*)0;
    bf16* Ph  = ep.ph ? ep.ph + (long)batch * ep.sP : (bf16*)0;
    bf16* Pl  = ep.pl ? ep.pl + (long)batch * ep.sP : (bf16*)0;
    bf16* Th  = ep.th ? ep.th + (long)batch * ep.sT : (bf16*)0;
    bf16* Tl  = ep.tl ? ep.tl + (long)batch * ep.sT : (bf16*)0;

    #pragma unroll
    for (int mt = 0; mt < 2; mt++)
        #pragma unroll
        for (int nt = 0; nt < 4; nt++) {
            int gr0 = row0 + wm * 32 + mt * 16 + er;
            int gc  = col0 + wn * 32 + nt * 8 + 2 * eq;
            #pragma unroll
            for (int half = 0; half < 2; half++) {
                int gr = gr0 + 8 * half;
                if (gr >= M) continue;
                float va = acc[mt][nt][2 * half], vb = acc[mt][nt][2 * half + 1];
                if (F) {
                    float o0 = ep.falpha * va, o1 = ep.falpha * vb;
                    if (ep.bias)  { o0 += ep.bias[gc]; o1 += ep.bias[gc + 1]; }
                    if (ep.resid) {
                        o0 += ep.resid[(long)gr * ep.ldf + gc];
                        o1 += ep.resid[(long)gr * ep.ldf + gc + 1];
                    }
                    *reinterpret_cast<float2*>(F + (long)gr * ep.ldf + gc) =
                        make_float2(o0, o1);
                }
                if (Ph) {
                    float s0 = ep.palpha * va, s1 = ep.palpha * vb;
                    float h0, l0, h1, l1;
                    split_bf(s0, h0, l0); split_bf(s1, h1, l1);
                    *reinterpret_cast<uint32_t*>(Ph + (long)gr * ep.ldp + gc) = pack2(h0, h1);
                    *reinterpret_cast<uint32_t*>(Pl + (long)gr * ep.ldp + gc) = pack2(l0, l1);
                }
                if (Th) {
                    #pragma unroll
                    for (int j = 0; j < 2; j++) {
                        int cc = gc + j;
                        float v = (j == 0) ? va : vb;
                        float s = ep.talpha * v + ((gr == cc) ? ep.tdiag : 0.f);
                        float hi, lo; split_bf(s, hi, lo);
                        Th[(long)cc * ep.ldt + gr] = __float2bfloat16(hi);
                        Tl[(long)cc * ep.ldt + gr] = __float2bfloat16(lo);
                    }
                }
            }
        }
}

static EpiOut epi0() { EpiOut e{}; return e; }
static void gemmP(const bf16* Ah, const bf16* Al, const bf16* Bh, const bf16* Bl,
                  int M, int N, int K, int lda, int ldb, long sA, long sB,
                  int batch, int ksplit, EpiOut ep)
{
    dim3 g(N / 64, (M + 127) / 128, batch * ksplit), b(256);
    gemm_p<<<g, b, GP_SMEM>>>(Ah, Al, Bh, Bl, M, K, lda, ldb, sA, sB, ep, ksplit);
}

// =======================================================================
// flash-fused S3 path (unchanged from R7)
// =======================================================================
#define FL_RS   144
#define FL_QH   0
#define FL_QL   18432
#define FL_K(b) (36864 + (b) * 18432)
#define FL_V(b) (73728 + (b) * 18432)
#define FL_PH   110592
#define FL_PL   129024
#define FL_SMEM 147456
#define FL_NCH  ((NP / NSPLIT) / 64)

__global__ void __launch_bounds__(128)
flash3_k(const bf16* __restrict__ qlh, const bf16* __restrict__ qll,
         const bf16* __restrict__ qkvh, const bf16* __restrict__ qkvl,
         const bf16* __restrict__ vth, const bf16* __restrict__ vtl,
         float* __restrict__ pO, float* __restrict__ pm, float* __restrict__ ps)
{
    extern __shared__ __align__(16) char sm[];
    const uint32_t sb = smem_to_u32(sm);
    const int tid = threadIdx.x, warp = tid >> 5, lane = tid & 31;
    const int split = blockIdx.x, rowHalf = blockIdx.y, head = blockIdx.z;
    const int tb0 = split * (NP / NSPLIT);

    const bf16* Qh = qlh + ((long)head * MM + rowHalf * 128) * DH;
    const bf16* Ql = qll + ((long)head * MM + rowHalf * 128) * DH;
    #pragma unroll
    for (int i = 0; i < 8; i++) {
        int s = tid + 128 * i;
        int r = s >> 3, seg = s & 7;
        long go = (long)r * DH + seg * 8;
        cpa16(sb + FL_QH + r * FL_RS + seg * 16, Qh + go, 16);
        cpa16(sb + FL_QL + r * FL_RS + seg * 16, Ql + go, 16);
    }

    const bf16* Kh = qkvh + head * DH + 512;
    const bf16* Kl = qkvl + head * DH + 512;
    const bf16* Vh = vth + (long)head * DH * NP;
    const bf16* Vl = vtl + (long)head * DH * NP;

    auto kissue = [&](int j) {
        int buf = j & 1;
        int tb = tb0 + j * 64;
        uint32_t kb = sb + FL_K(buf);
        uint32_t vb = sb + FL_V(buf);
        #pragma unroll
        for (int i = 0; i < 4; i++) {
            int s = tid + 128 * i;
            int r = s >> 3, seg = s & 7;
            long gk = (long)(tb + r) * QKVW + seg * 8;
            cpa16(kb + r * FL_RS + seg * 16, Kh + gk, 16);
            cpa16(kb + 9216 + r * FL_RS + seg * 16, Kl + gk, 16);
            long gv = (long)r * NP + tb + seg * 8;
            cpa16(vb + r * FL_RS + seg * 16, Vh + gv, 16);
            cpa16(vb + 9216 + r * FL_RS + seg * 16, Vl + gv, 16);
        }
        asm volatile("cp.async.commit_group;");
    };
    kissue(0);
    kissue(1);

    const int rsel = (lane & 7) + ((lane >> 3) & 1) * 8;
    const int ksel = ((lane >> 4) & 1) * 16;
    const int er = lane >> 2, eq = lane & 3;

    float m_run[4] = {-1e30f, -1e30f, -1e30f, -1e30f};
    float s_run[4] = {0.f, 0.f, 0.f, 0.f};
    float oacc[2][8][4];
    #pragma unroll
    for (int a = 0; a < 2; a++)
        #pragma unroll
        for (int b = 0; b < 8; b++)
            #pragma unroll
            for (int c = 0; c < 4; c++) oacc[a][b][c] = 0.f;

    for (int j = 0; j < FL_NCH; j++) {
        if (j + 1 < FL_NCH) asm volatile("cp.async.wait_group 1;");
        else                asm volatile("cp.async.wait_group 0;");
        __syncthreads();
        uint32_t kb = sb + FL_K(j & 1);
        uint32_t vb = sb + FL_V(j & 1);

        float sacc[2][8][4];
        #pragma unroll
        for (int a = 0; a < 2; a++)
            #pragma unroll
            for (int b = 0; b < 8; b++)
                #pragma unroll
                for (int c = 0; c < 4; c++) sacc[a][b][c] = 0.f;

        #pragma unroll
        for (int k16 = 0; k16 < 4; k16++) {
            uint32_t ah[2][4], al[2][4];
            #pragma unroll
            for (int mt = 0; mt < 2; mt++) {
                uint32_t ad = sb + FL_QH + (warp * 32 + mt * 16 + rsel) * FL_RS + k16 * 32 + ksel;
                ldsm4(ad, ah[mt][0], ah[mt][1], ah[mt][2], ah[mt][3]);
                ldsm4(ad + (FL_QL - FL_QH), al[mt][0], al[mt][1], al[mt][2], al[mt][3]);
            }
            #pragma unroll
            for (int n16 = 0; n16 < 4; n16++) {
                uint32_t bd = kb + (n16 * 16 + rsel) * FL_RS + k16 * 32 + ksel;
                uint32_t q0, q1, q2, q3, p0, p1, p2, p3;
                ldsm4(bd, q0, q1, q2, q3);
                ldsm4(bd + 9216, p0, p1, p2, p3);
                #pragma unroll
                for (int mt = 0; mt < 2; mt++) {
                    mma_bf16(sacc[mt][2*n16],   ah[mt], q0, q2);
                    mma_bf16(sacc[mt][2*n16],   ah[mt], p0, p2);
                    mma_bf16(sacc[mt][2*n16],   al[mt], q0, q2);
                    mma_bf16(sacc[mt][2*n16+1], ah[mt], q1, q3);
                    mma_bf16(sacc[mt][2*n16+1], ah[mt], p1, p3);
                    mma_bf16(sacc[mt][2*n16+1], al[mt], q1, q3);
                }
            }
        }

        #pragma unroll
        for (int mt = 0; mt < 2; mt++) {
            float cm0 = -1e30f, cm1 = -1e30f;
            #pragma unroll
            for (int nt = 0; nt < 8; nt++) {
                cm0 = fmaxf(cm0, fmaxf(sacc[mt][nt][0], sacc[mt][nt][1]));
                cm1 = fmaxf(cm1, fmaxf(sacc[mt][nt][2], sacc[mt][nt][3]));
            }
            #pragma unroll
            for (int o = 1; o <= 2; o <<= 1) {
                cm0 = fmaxf(cm0, __shfl_xor_sync(0xffffffffu, cm0, o));
                cm1 = fmaxf(cm1, __shfl_xor_sync(0xffffffffu, cm1, o));
            }
            float mn0 = fmaxf(m_run[2*mt],     cm0);
            float mn1 = fmaxf(m_run[2*mt + 1], cm1);
            float sc0 = __expf(m_run[2*mt]     - mn0);
            float sc1 = __expf(m_run[2*mt + 1] - mn1);
            m_run[2*mt] = mn0; m_run[2*mt + 1] = mn1;
            float ls0 = 0.f, ls1 = 0.f;
            int pr = warp * 32 + mt * 16 + er;
            #pragma unroll
            for (int nt = 0; nt < 8; nt++) {
                float e0 = __expf(sacc[mt][nt][0] - mn0);
                float e1 = __expf(sacc[mt][nt][1] - mn0);
                float e2 = __expf(sacc[mt][nt][2] - mn1);
                float e3 = __expf(sacc[mt][nt][3] - mn1);
                ls0 += e0 + e1; ls1 += e2 + e3;
                oacc[mt][nt][0] *= sc0; oacc[mt][nt][1] *= sc0;
                oacc[mt][nt][2] *= sc1; oacc[mt][nt][3] *= sc1;
                int col = nt * 8 + 2 * eq;
                float h0, l0, h1, l1;
                split_bf(e0, h0, l0); split_bf(e1, h1, l1);
                *reinterpret_cast<uint32_t*>(sm + FL_PH + pr * FL_RS + col * 2) = pack2(h0, h1);
                *reinterpret_cast<uint32_t*>(sm + FL_PL + pr * FL_RS + col * 2) = pack2(l0, l1);
                split_bf(e2, h0, l0); split_bf(e3, h1, l1);
                *reinterpret_cast<uint32_t*>(sm + FL_PH + (pr + 8) * FL_RS + col * 2) = pack2(h0, h1);
                *reinterpret_cast<uint32_t*>(sm + FL_PL + (pr + 8) * FL_RS + col * 2) = pack2(l0, l1);
            }
            #pragma unroll
            for (int o = 1; o <= 2; o <<= 1) {
                ls0 += __shfl_xor_sync(0xffffffffu, ls0, o);
                ls1 += __shfl_xor_sync(0xffffffffu, ls1, o);
            }
            s_run[2*mt]     = s_run[2*mt]     * sc0 + ls0;
            s_run[2*mt + 1] = s_run[2*mt + 1] * sc1 + ls1;
        }
        __syncthreads();

        #pragma unroll
        for (int k16 = 0; k16 < 4; k16++) {
            uint32_t ph[2][4], pl[2][4];
            #pragma unroll
            for (int mt = 0; mt < 2; mt++) {
                uint32_t ad = sb + FL_PH + (warp * 32 + mt * 16 + rsel) * FL_RS + k16 * 32 + ksel;
                ldsm4(ad, ph[mt][0], ph[mt][1], ph[mt][2], ph[mt][3]);
                ldsm4(ad + (FL_PL - FL_PH), pl[mt][0], pl[mt][1], pl[mt][2], pl[mt][3]);
            }
            #pragma unroll
            for (int n16 = 0; n16 < 4; n16++) {
                uint32_t bd = vb + (n16 * 16 + rsel) * FL_RS + k16 * 32 + ksel;
                uint32_t q0, q1, q2, q3, r0, r1, r2, r3;
                ldsm4(bd, q0, q1, q2, q3);
                ldsm4(bd + 9216, r0, r1, r2, r3);
                #pragma unroll
                for (int mt = 0; mt < 2; mt++) {
                    mma_bf16(oacc[mt][2*n16],   ph[mt], q0, q2);
                    mma_bf16(oacc[mt][2*n16],   ph[mt], r0, r2);
                    mma_bf16(oacc[mt][2*n16],   pl[mt], q0, q2);
                    mma_bf16(oacc[mt][2*n16+1], ph[mt], q1, q3);
                    mma_bf16(oacc[mt][2*n16+1], ph[mt], r1, r3);
                    mma_bf16(oacc[mt][2*n16+1], pl[mt], q1, q3);
                }
            }
        }
        __syncthreads();
        if (j + 2 < FL_NCH) kissue(j + 2);
    }

    const int base = (split * HEADS + head) * MM + rowHalf * 128;
    #pragma unroll
    for (int mt = 0; mt < 2; mt++) {
        int r0 = base + warp * 32 + mt * 16 + er;
        #pragma unroll
        for (int nt = 0; nt < 8; nt++) {
            int d = nt * 8 + 2 * eq;
            *reinterpret_cast<float2*>(pO + (long)r0 * DH + d) =
                make_float2(oacc[mt][nt][0], oacc[mt][nt][1]);
            *reinterpret_cast<float2*>(pO + (long)(r0 + 8) * DH + d) =
                make_float2(oacc[mt][nt][2], oacc[mt][nt][3]);
        }
        if (eq == 0) {
            pm[r0] = m_run[2*mt];     ps[r0] = s_run[2*mt];
            pm[r0 + 8] = m_run[2*mt + 1]; ps[r0 + 8] = s_run[2*mt + 1];
        }
    }
}

__global__ void flash_merge_k(const float* __restrict__ pO, const float* __restrict__ pm,
                              const float* __restrict__ ps,
                              bf16* __restrict__ oh, bf16* __restrict__ ol)
{
    int row = blockIdx.x, head = blockIdx.y, d = threadIdx.x;
    float mx = -1e30f;
    #pragma unroll
    for (int i = 0; i < NSPLIT; i++)
        mx = fmaxf(mx, pm[(i * HEADS + head) * MM + row]);
    float den = 0.f, acc = 0.f;
    #pragma unroll
    for (int i = 0; i < NSPLIT; i++) {
        int r = (i * HEADS + head) * MM + row;
        float w = __expf(pm[r] - mx);
        den += w * ps[r];
        acc += w * pO[(long)r * DH + d];
    }
    float v = acc / den;
    float hi, lo; split_bf(v, hi, lo);
    long o = ((long)head << 14) + d * MM + row;
    oh[o] = __float2bfloat16(hi);
    ol[o] = __float2bfloat16(lo);
}

// =======================================================================
// fused S1 -> softmax -> O1 (unchanged)
// =======================================================================
#define FA_RS1  144
#define FA_AH   0
#define FA_AL   9216
#define FA_BH   18432
#define FA_BL   55296
#define FA_PH   0
#define FA_PL   33792
#define FA_WS   67584
#define FA_WST  10240
#define FA_SMEM 98304

__global__ void __launch_bounds__(128)
fused_attn1_k(const bf16* __restrict__ qh, const bf16* __restrict__ ql_,
              const bf16* __restrict__ klh, const bf16* __restrict__ kll,
              const bf16* __restrict__ Wth, const bf16* __restrict__ Wtl,
              float* __restrict__ attn)
{
    extern __shared__ __align__(16) char sm[];
    const uint32_t sb = smem_to_u32(sm);
    const int tid = threadIdx.x, warp = tid >> 5, lane = tid & 31;
    const int row0 = blockIdx.x * 64;
    const int head = blockIdx.y;

    const bf16* qsh = qh  + (long)row0 * QKVW + head * DH;
    const bf16* qsl = ql_ + (long)row0 * QKVW + head * DH;
    #pragma unroll
    for (int i = 0; i < 4; i++) {
        int s = tid + 128 * i;
        int r = s >> 3, seg = s & 7;
        long go = (long)r * QKVW + seg * 8;
        cpa16(sb + FA_AH + r * FA_RS1 + seg * 16, qsh + go, 16);
        cpa16(sb + FA_AL + r * FA_RS1 + seg * 16, qsl + go, 16);
    }
    const bf16* ksh = klh + (long)head * MM * DH;
    const bf16* ksl = kll + (long)head * MM * DH;
    #pragma unroll
    for (int i = 0; i < 16; i++) {
        int s = tid + 128 * i;
        int r = s >> 3, seg = s & 7;
        long go = (long)r * DH + seg * 8;
        cpa16(sb + FA_BH + r * FA_RS1 + seg * 16, ksh + go, 16);
        cpa16(sb + FA_BL + r * FA_RS1 + seg * 16, ksl + go, 16);
    }
    asm volatile("cp.async.commit_group;");
    asm volatile("cp.async.wait_group 0;");
    __syncthreads();

    const int rsel = (lane & 7) + ((lane >> 3) & 1) * 8;
    const int ksel = ((lane >> 4) & 1) * 16;
    float sacc[32][4];
    #pragma unroll
    for (int i = 0; i < 32; i++)
        #pragma unroll
        for (int j = 0; j < 4; j++) sacc[i][j] = 0.f;

    #pragma unroll
    for (int k16 = 0; k16 < 4; k16++) {
        uint32_t ah[4], al[4];
        uint32_t ad = sb + FA_AH + (warp * 16 + rsel) * FA_RS1 + k16 * 32 + ksel;
        ldsm4(ad, ah[0], ah[1], ah[2], ah[3]);
        ldsm4(ad + (FA_AL - FA_AH), al[0], al[1], al[2], al[3]);
        #pragma unroll
        for (int n16 = 0; n16 < 16; n16++) {
            uint32_t bd = sb + FA_BH + (n16 * 16 + rsel) * FA_RS1 + k16 * 32 + ksel;
            uint32_t q0, q1, q2, q3, p0, p1, p2, p3;
            ldsm4(bd, q0, q1, q2, q3);
            ldsm4(bd + (FA_BL - FA_BH), p0, p1, p2, p3);
            mma_bf16(sacc[2*n16],   ah, q0, q2);
            mma_bf16(sacc[2*n16],   ah, p0, p2);
            mma_bf16(sacc[2*n16],   al, q0, q2);
            mma_bf16(sacc[2*n16+1], ah, q1, q3);
            mma_bf16(sacc[2*n16+1], ah, p1, p3);
            mma_bf16(sacc[2*n16+1], al, q1, q3);
        }
    }

    float mx0 = -1e30f, mx1 = -1e30f;
    #pragma unroll
    for (int nt = 0; nt < 32; nt++) {
        #pragma unroll
        for (int j = 0; j < 4; j++) sacc[nt][j] *= 0.125f;
        mx0 = fmaxf(mx0, fmaxf(sacc[nt][0], sacc[nt][1]));
        mx1 = fmaxf(mx1, fmaxf(sacc[nt][2], sacc[nt][3]));
    }
    #pragma unroll
    for (int o = 1; o <= 2; o <<= 1) {
        mx0 = fmaxf(mx0, __shfl_xor_sync(0xffffffffu, mx0, o));
        mx1 = fmaxf(mx1, __shfl_xor_sync(0xffffffffu, mx1, o));
    }
    float sm0 = 0.f, sm1 = 0.f;
    #pragma unroll
    for (int nt = 0; nt < 32; nt++) {
        sacc[nt][0] = __expf(sacc[nt][0] - mx0);
        sacc[nt][1] = __expf(sacc[nt][1] - mx0);
        sacc[nt][2] = __expf(sacc[nt][2] - mx1);
        sacc[nt][3] = __expf(sacc[nt][3] - mx1);
        sm0 += sacc[nt][0] + sacc[nt][1];
        sm1 += sacc[nt][2] + sacc[nt][3];
    }
    #pragma unroll
    for (int o = 1; o <= 2; o <<= 1) {
        sm0 += __shfl_xor_sync(0xffffffffu, sm0, o);
        sm1 += __shfl_xor_sync(0xffffffffu, sm1, o);
    }
    __syncthreads();

    const bf16* Wsh = Wth + (long)head * DH * MM;
    const bf16* Wsl = Wtl + (long)head * DH * MM;
    auto wissue = [&](int it) {
        int stg = it % 3;
        uint32_t base = sb + FA_WS + stg * FA_WST;
        #pragma unroll
        for (int i = 0; i < 2; i++) {
            int s = tid + 128 * i;
            int r = s >> 2, seg = s & 3;
            long go = (long)r * MM + it * 32 + seg * 8;
            cpa16(base + r * 80 + seg * 16, Wsh + go, 16);
            cpa16(base + 5120 + r * 80 + seg * 16, Wsl + go, 16);
        }
        asm volatile("cp.async.commit_group;");
    };
    wissue(0); wissue(1);

    {
        int pr = warp * 16 + (lane >> 2);
        int pc = (lane & 3) * 2;
        #pragma unroll
        for (int nt = 0; nt < 32; nt++) {
            int col = nt * 8 + pc;
            float h0, l0, h1, l1;
            split_bf(sacc[nt][0], h0, l0); split_bf(sacc[nt][1], h1, l1);
            *reinterpret_cast<uint32_t*>(sm + FA_PH + pr * 528 + col * 2) = pack2(h0, h1);
            *reinterpret_cast<uint32_t*>(sm + FA_PL + pr * 528 + col * 2) = pack2(l0, l1);
            split_bf(sacc[nt][2], h0, l0); split_bf(sacc[nt][3], h1, l1);
            *reinterpret_cast<uint32_t*>(sm + FA_PH + (pr + 8) * 528 + col * 2) = pack2(h0, h1);
            *reinterpret_cast<uint32_t*>(sm + FA_PL + (pr + 8) * 528 + col * 2) = pack2(l0, l1);
        }
    }
    __syncthreads();

    float oacc[8][4];
    #pragma unroll
    for (int i = 0; i < 8; i++)
        #pragma unroll
        for (int j = 0; j < 4; j++) oacc[i][j] = 0.f;

    for (int it = 0; it < 8; it++) {
        if (it < 7) asm volatile("cp.async.wait_group 1;");
        else        asm volatile("cp.async.wait_group 0;");
        __syncthreads();
        if (it + 2 < 8) wissue(it + 2);
        uint32_t wb = sb + FA_WS + (it % 3) * FA_WST;
        #pragma unroll
        for (int k16 = 0; k16 < 2; k16++) {
            int gk = it * 2 + k16;
            uint32_t ph[4], pl[4];
            uint32_t ad = sb + FA_PH + (warp * 16 + rsel) * 528 + gk * 32 + ksel;
            ldsm4(ad, ph[0], ph[1], ph[2], ph[3]);
            ldsm4(ad + (FA_PL - FA_PH), pl[0], pl[1], pl[2], pl[3]);
            #pragma unroll
            for (int n16 = 0; n16 < 4; n16++) {
                uint32_t bd = wb + (n16 * 16 + rsel) * 80 + k16 * 32 + ksel;
                uint32_t q0, q1, q2, q3, r0, r1, r2, r3;
                ldsm4(bd, q0, q1, q2, q3);
                ldsm4(bd + 5120, r0, r1, r2, r3);
                mma_bf16(oacc[2*n16],   ph, q0, q2);
                mma_bf16(oacc[2*n16],   ph, r0, r2);
                mma_bf16(oacc[2*n16],   pl, q0, q2);
                mma_bf16(oacc[2*n16+1], ph, q1, q3);
                mma_bf16(oacc[2*n16+1], ph, r1, r3);
                mma_bf16(oacc[2*n16+1], pl, q1, q3);
            }
        }
    }

    float inv0 = 1.f / sm0, inv1 = 1.f / sm1;
    int orow = row0 + warp * 16 + (lane >> 2);
    int ocol = head * DH + (lane & 3) * 2;
    #pragma unroll
    for (int nt = 0; nt < 8; nt++) {
        int col = ocol + nt * 8;
        *reinterpret_cast<float2*>(attn + (long)orow * C + col) =
            make_float2(oacc[nt][0] * inv0, oacc[nt][1] * inv0);
        *reinterpret_cast<float2*>(attn + (long)(orow + 8) * C + col) =
            make_float2(oacc[nt][2] * inv1, oacc[nt][3] * inv1);
    }
}

// =======================================================================
// auxiliary kernels (unchanged)
// =======================================================================

__global__ void wconvT_k(const float* __restrict__ w, bf16* __restrict__ th,
                         bf16* __restrict__ tl, int K, int N)
{
    int i = blockIdx.x * 256 + threadIdx.x;
    if (i >= N * K) return;
    int n = i / K, k = i - n * K;
    float v = w[(long)k * N + n];
    float hi, lo; split_bf(v, hi, lo);
    th[i] = __float2bfloat16(hi);
    tl[i] = __float2bfloat16(lo);
}

__global__ void build_h_k(const float* __restrict__ feat, const float* __restrict__ cls,
                          float* __restrict__ h)
{
    long i = (long)blockIdx.x * 256 + threadIdx.x;
    if (i >= (long)NH * C) return;
    long t = i >> 9;
    int  c = (int)(i & 511);
    float v;
    if (t == 0) v = cls[c];
    else {
        long r = t - 1;
        if (r >= NFEAT) r -= NFEAT;
        v = feat[r * C + c];
    }
    h[i] = v;
}

__global__ void ln_pad_k(const float* __restrict__ h, bf16* __restrict__ xh,
                         bf16* __restrict__ xl,
                         const float* __restrict__ g, const float* __restrict__ b)
{
    int t = blockIdx.x, c = threadIdx.x;
    long o = (long)t * C;
    if (t < PADN) {
        *reinterpret_cast<uint32_t*>(xh + o + 2 * c) = 0u;
        *reinterpret_cast<uint32_t*>(xl + o + 2 * c) = 0u;
        return;
    }
    const float* row = h + (long)(t - PADN) * C;
    float a1 = row[2 * c], a2 = row[2 * c + 1];
    __shared__ float red[256];
    red[c] = a1 + a2; __syncthreads();
    for (int s = 128; s > 0; s >>= 1) { if (c < s) red[c] += red[c + s]; __syncthreads(); }
    float mu = red[0] * (1.f / 512.f);
    __syncthreads();
    float d1 = a1 - mu, d2 = a2 - mu;
    red[c] = d1 * d1 + d2 * d2; __syncthreads();
    for (int s = 128; s > 0; s >>= 1) { if (c < s) red[c] += red[c + s]; __syncthreads(); }
    float inv = rsqrtf(red[0] * (1.f / 512.f) + 1e-5f);
    float v1 = d1 * inv * g[2 * c] + b[2 * c];
    float v2 = d2 * inv * g[2 * c + 1] + b[2 * c + 1];
    float h1, l1, h2, l2;
    split_bf(v1, h1, l1); split_bf(v2, h2, l2);
    *reinterpret_cast<uint32_t*>(xh + o + 2 * c) = pack2(h1, h2);
    *reinterpret_cast<uint32_t*>(xl + o + 2 * c) = pack2(l1, l2);
}

__global__ void landmarks_k(const bf16* __restrict__ qh, const bf16* __restrict__ ql_,
                            bf16* __restrict__ qlh, bf16* __restrict__ qll,
                            bf16* __restrict__ klh, bf16* __restrict__ kll)
{
    int d = threadIdx.x;
    int m = blockIdx.x & 255;
    int hh = blockIdx.x >> 8;
    long base = (long)(m * LL) * QKVW + hh * DH + d;
    float sq = 0.f, sk = 0.f;
    for (int j = 0; j < LL; j++) {
        long o = base + (long)j * QKVW;
        sq += pairval(qh, ql_, o);
        sk += pairval(qh, ql_, o + 512);
    }
    float vq = sq * (0.125f / (float)LL);
    float vk = sk * (1.f / (float)LL);
    int oi = (hh * MM + m) * DH + d;
    float hi, lo;
    split_bf(vq, hi, lo); qlh[oi] = __float2bfloat16(hi); qll[oi] = __float2bfloat16(lo);
    split_bf(vk, hi, lo); klh[oi] = __float2bfloat16(hi); kll[oi] = __float2bfloat16(lo);
}

__global__ void softmax256_k(const float* __restrict__ in, float* __restrict__ fout,
                             bf16* __restrict__ ph, bf16* __restrict__ pl, long nrows)
{
    long row = (long)blockIdx.x * 8 + threadIdx.y;
    if (row >= nrows) return;
    const float* r = in + row * 256;
    int lane = threadIdx.x;
    float v[8], m = -1e30f;
    #pragma unroll
    for (int i = 0; i < 8; i++) { v[i] = r[lane + 32 * i]; m = fmaxf(m, v[i]); }
    #pragma unroll
    for (int o = 16; o; o >>= 1) m = fmaxf(m, __shfl_xor_sync(0xffffffffu, m, o));
    float s = 0.f;
    #pragma unroll
    for (int i = 0; i < 8; i++) { v[i] = __expf(v[i] - m); s += v[i]; }
    #pragma unroll
    for (int o = 16; o; o >>= 1) s += __shfl_xor_sync(0xffffffffu, s, o);
    float inv = 1.f / s;
    #pragma unroll
    for (int i = 0; i < 8; i++) {
        float val = v[i] * inv;
        long o = row * 256 + lane + 32 * i;
        if (fout) fout[o] = val;
        float hi, lo; split_bf(val, hi, lo);
        ph[o] = __float2bfloat16(hi);
        pl[o] = __float2bfloat16(lo);
    }
}

__global__ void pinv_sums_k(const float* __restrict__ a2,
                            float* __restrict__ rs, float* __restrict__ cs)
{
    int hh = blockIdx.x, j = threadIdx.x;
    const float* X = a2 + (long)hh * MM * MM;
    float r = 0.f, c = 0.f;
    for (int k = 0; k < MM; k++) { r += fabsf(X[j * MM + k]); c += fabsf(X[k * MM + j]); }
    rs[hh * MM + j] = r; cs[hh * MM + j] = c;
}
__global__ void pinv_scale_k(const float* __restrict__ rs, const float* __restrict__ cs,
                             float* __restrict__ scale)
{
    __shared__ float m1[256], m2[256];
    float a = -1e30f, b = -1e30f;
    for (int i = threadIdx.x; i < HEADS * MM; i += 256) { a = fmaxf(a, rs[i]); b = fmaxf(b, cs[i]); }
    m1[threadIdx.x] = a; m2[threadIdx.x] = b; __syncthreads();
    for (int s = 128; s > 0; s >>= 1) {
        if (threadIdx.x < s) {
            m1[threadIdx.x] = fmaxf(m1[threadIdx.x], m1[threadIdx.x + s]);
            m2[threadIdx.x] = fmaxf(m2[threadIdx.x], m2[threadIdx.x + s]);
        }
        __syncthreads();
    }
    if (threadIdx.x == 0) scale[0] = 1.f / (m1[0] * m2[0]);
}
__global__ void pinv_init_k(const float* __restrict__ a2, const float* __restrict__ scale,
                            bf16* __restrict__ zph, bf16* __restrict__ zpl,
                            bf16* __restrict__ zth, bf16* __restrict__ ztl)
{
    long i = (long)blockIdx.x * 256 + threadIdx.x;
    if (i >= (long)HEADS * MM * MM) return;
    float s = scale[0];
    long hb = i & ~65535L;
    int r = (int)((i >> 8) & 255), c = (int)(i & 255);
    float vt = a2[i] * s;
    float vp = a2[hb + ((long)c << 8) + r] * s;
    float hi, lo;
    split_bf(vt, hi, lo); zth[i] = __float2bfloat16(hi); ztl[i] = __float2bfloat16(lo);
    split_bf(vp, hi, lo); zph[i] = __float2bfloat16(hi); zpl[i] = __float2bfloat16(lo);
}

__global__ void vT_k(const bf16* __restrict__ qh, const bf16* __restrict__ ql_,
                     bf16* __restrict__ vth, bf16* __restrict__ vtl)
{
    __shared__ bf16 tile[32][33];
    int t0 = blockIdx.x * 32;
    int head = blockIdx.y >> 1;
    int lopart = blockIdx.y & 1;
    int d0 = blockIdx.z * 32;
    const bf16* src = (lopart ? ql_ : qh) + 1024 + head * 64 + d0;
    bf16* dst = (lopart ? vtl : vth) + (long)head * 64 * NP + (long)d0 * NP;
    int tx = threadIdx.x, ty = threadIdx.y;
    #pragma unroll
    for (int i = 0; i < 4; i++)
        tile[ty + 8 * i][tx] = src[(long)(t0 + ty + 8 * i) * QKVW + tx];
    __syncthreads();
    #pragma unroll
    for (int i = 0; i < 4; i++)
        dst[(long)(ty + 8 * i) * NP + t0 + tx] = tile[tx][ty + 8 * i];
}

__global__ void conv_add_k(const bf16* __restrict__ qh, const bf16* __restrict__ ql_,
                           const float* __restrict__ rw, const float* __restrict__ attnf,
                           bf16* __restrict__ ah, bf16* __restrict__ al)
{
    int t = blockIdx.x, c = threadIdx.x;
    int hh = c >> 6;
    float acc = attnf[(long)t * C + c];
    #pragma unroll
    for (int k = 0; k < 33; k++) {
        int tt = t + k - 16;
        if ((unsigned)tt < (unsigned)NP)
            acc += pairval(qh, ql_, (long)tt * QKVW + 1024 + c) * rw[hh * 33 + k];
    }
    float hi, lo; split_bf(acc, hi, lo);
    long o = (long)t * C + c;
    ah[o] = __float2bfloat16(hi);
    al[o] = __float2bfloat16(lo);
}

__global__ void ppeg_k(const float* __restrict__ h, float* __restrict__ h2,
                       const float* __restrict__ w7, const float* __restrict__ b7,
                       const float* __restrict__ w5, const float* __restrict__ b5,
                       const float* __restrict__ w3, const float* __restrict__ b3)
{
    int x = blockIdx.x, y = blockIdx.y, c = threadIdx.x;
    if (x == 0 && y == 0) h2[c] = h[c];
    float acc = h[(long)(1 + y * HW + x) * C + c];
    #pragma unroll
    for (int ky = 0; ky < 7; ky++) {
        int yy = y + ky - 3; if (yy < 0 || yy >= HW) continue;
        #pragma unroll
        for (int kx = 0; kx < 7; kx++) {
            int xx = x + kx - 3; if (xx < 0 || xx >= HW) continue;
            acc += h[(long)(1 + yy * HW + xx) * C + c] * w7[c * 49 + ky * 7 + kx];
        }
    }
    #pragma unroll
    for (int ky = 0; ky < 5; ky++) {
        int yy = y + ky - 2; if (yy < 0 || yy >= HW) continue;
        #pragma unroll
        for (int kx = 0; kx < 5; kx++) {
            int xx = x + kx - 2; if (xx < 0 || xx >= HW) continue;
            acc += h[(long)(1 + yy * HW + xx) * C + c] * w5[c * 25 + ky * 5 + kx];
        }
    }
    #pragma unroll
    for (int ky = 0; ky < 3; ky++) {
        int yy = y + ky - 1; if (yy < 0 || yy >= HW) continue;
        #pragma unroll
        for (int kx = 0; kx < 3; kx++) {
            int xx = x + kx - 1; if (xx < 0 || xx >= HW) continue;
            acc += h[(long)(1 + yy * HW + xx) * C + c] * w3[c * 9 + ky * 3 + kx];
        }
    }
    acc += b7[c] + b5[c] + b3[c];
    h2[(long)(1 + y * HW + x) * C + c] = acc;
}

// ================= host orchestration =================
struct Ptrs {
    float *h, *h2, *a2, *attn, *outl, *rowsum, *colsum, *fm, *fs, *scale;
    bf16 *xph, *xpl, *qkvh, *qkvl, *qlh, *qll, *klh, *kll,
         *a2h, *a2l, *zh, *zl, *zth, *ztl, *z2h, *z2l, *z2th, *z2tl,
         *xzh, *xzl, *tah, *tal, *tbh, *tbl, *vth, *vtl,
         *a3h, *a3l, *Wth, *Wtl, *ath, *atl,
         *w1ah, *w1al, *w2ah, *w2al, *w1bh, *w1bl, *w2bh, *w2bl;
};
#define GSYM(f, s) cudaGetSymbolAddress((void**)&p.f, s)
static void get_ptrs(Ptrs& p)
{
    GSYM(h, g_h); GSYM(h2, g_h2); GSYM(a2, g_a2);
    GSYM(attn, g_attn); GSYM(outl, g_outl);
    GSYM(rowsum, g_rowsum); GSYM(colsum, g_colsum);
    GSYM(fm, g_fm); GSYM(fs, g_fs); GSYM(scale, g_scale);
    GSYM(xph, g_xph); GSYM(xpl, g_xpl); GSYM(qkvh, g_qkvh); GSYM(qkvl, g_qkvl);
    GSYM(qlh, g_qlh); GSYM(qll, g_qll); GSYM(klh, g_klh); GSYM(kll, g_kll);
    GSYM(a2h, g_a2h); GSYM(a2l, g_a2l);
    GSYM(zh, g_zh); GSYM(zl, g_zl); GSYM(zth, g_zth); GSYM(ztl, g_ztl);
    GSYM(z2h, g_z2h); GSYM(z2l, g_z2l); GSYM(z2th, g_z2th); GSYM(z2tl, g_z2tl);
    GSYM(xzh, g_xzh); GSYM(xzl, g_xzl);
    GSYM(tah, g_tah); GSYM(tal, g_tal); GSYM(tbh, g_tbh); GSYM(tbl, g_tbl);
    GSYM(vth, g_vth); GSYM(vtl, g_vtl); GSYM(a3h, g_a3h); GSYM(a3l, g_a3l);
    GSYM(Wth, g_Wth); GSYM(Wtl, g_Wtl); GSYM(ath, g_ath); GSYM(atl, g_atl);
    GSYM(w1ah, g_w1ah); GSYM(w1al, g_w1al); GSYM(w2ah, g_w2ah); GSYM(w2al, g_w2al);
    GSYM(w1bh, g_w1bh); GSYM(w1bl, g_w1bl); GSYM(w2bh, g_w2bh); GSYM(w2bl, g_w2bl);
}

static void nystrom_tail(Ptrs& p, float* h_io,
                         const bf16* w2h, const bf16* w2l,
                         const float* b_out, const float* res_w)
{
    const long MMh = (long)MM * MM;

    landmarks_k<<<HEADS * MM, DH>>>(p.qkvh, p.qkvl, p.qlh, p.qll, p.klh, p.kll);
    vT_k<<<dim3(NP / 32, HEADS * 2, 2), dim3(32, 8)>>>(p.qkvh, p.qkvl, p.vth, p.vtl);

    { EpiOut e = epi0(); e.f = p.a2; e.falpha = 1.f; e.ldf = MM; e.sF = MMh;
      gemmP(p.qlh, p.qll, p.klh, p.kll, MM, MM, DH, DH, DH,
            (long)MM * DH, (long)MM * DH, HEADS, 1, e); }
    softmax256_k<<<(HEADS * MM + 7) / 8, dim3(32, 8)>>>(p.a2, p.a2, p.a2h, p.a2l, HEADS * MM);

    pinv_sums_k<<<HEADS, 256>>>(p.a2, p.rowsum, p.colsum);
    pinv_scale_k<<<1, 256>>>(p.rowsum, p.colsum, p.scale);
    pinv_init_k<<<(int)((HEADS * MMh + 255) / 256), 256>>>(p.a2, p.scale,
                                                           p.zh, p.zl, p.zth, p.ztl);
    bf16 *zch = p.zh, *zcl = p.zl, *zcth = p.zth, *zctl = p.ztl;
    bf16 *znh = p.z2h, *znl = p.z2l, *znth = p.z2th, *zntl = p.z2tl;
    for (int it = 0; it < 6; it++) {
        { EpiOut e = epi0();
          e.ph = p.xzh; e.pl = p.xzl; e.palpha = 1.f; e.ldp = MM; e.sP = MMh;
          e.th = p.tah; e.tl = p.tal; e.talpha = -1.f; e.tdiag = 7.f; e.ldt = MM; e.sT = MMh;
          gemmP(p.a2h, p.a2l, zcth, zctl, MM, MM, MM, MM, MM, MMh, MMh, HEADS, 1, e); }
        { EpiOut e = epi0();
          e.th = p.tbh; e.tl = p.tbl; e.talpha = -1.f; e.tdiag = 15.f; e.ldt = MM; e.sT = MMh;
          gemmP(p.xzh, p.xzl, p.tah, p.tal, MM, MM, MM, MM, MM, MMh, MMh, HEADS, 1, e); }
        { EpiOut e = epi0();
          e.th = p.tah; e.tl = p.tal; e.talpha = -1.f; e.tdiag = 13.f; e.ldt = MM; e.sT = MMh;
          gemmP(p.xzh, p.xzl, p.tbh, p.tbl, MM, MM, MM, MM, MM, MMh, MMh, HEADS, 1, e); }
        { EpiOut e = epi0();
          e.ph = znh; e.pl = znl; e.palpha = 0.25f; e.ldp = MM; e.sP = MMh;
          e.th = znth; e.tl = zntl; e.talpha = 0.25f; e.tdiag = 0.f; e.ldt = MM; e.sT = MMh;
          gemmP(zch, zcl, p.tah, p.tal, MM, MM, MM, MM, MM, MMh, MMh, HEADS, 1, e); }
        bf16* t;
        t = zch; zch = znh; znh = t;   t = zcl; zcl = znl; znl = t;
        t = zcth; zcth = znth; znth = t; t = zctl; zctl = zntl; zntl = t;
    }

    flash3_k<<<dim3(NSPLIT, 2, HEADS), 128, FL_SMEM>>>(
        p.qlh, p.qll, p.qkvh, p.qkvl, p.vth, p.vtl, p.outl, p.fm, p.fs);
    flash_merge_k<<<dim3(MM, HEADS), DH>>>(p.outl, p.fm, p.fs, p.a3h, p.a3l);

    { EpiOut e = epi0(); e.th = p.Wth; e.tl = p.Wtl; e.talpha = 1.f; e.tdiag = 0.f;
      e.ldt = MM; e.sT = (long)DH * MM;
      gemmP(zch, zcl, p.a3h, p.a3l, MM, DH, MM, MM, MM, MMh, (long)DH * MM, HEADS, 1, e); }

    fused_attn1_k<<<dim3(NP / 64, HEADS), 128, FA_SMEM>>>(
        p.qkvh, p.qkvl, p.klh, p.kll, p.Wth, p.Wtl, p.attn);

    conv_add_k<<<NP, C>>>(p.qkvh, p.qkvl, res_w, p.attn, p.ath, p.atl);

    { EpiOut e = epi0(); e.f = h_io; e.falpha = 1.f; e.ldf = C;
      e.resid = h_io; e.bias = b_out;
      gemmP(p.ath + (long)PADN * C, p.atl + (long)PADN * C, w2h, w2l,
            NH, C, C, C, C, 0, 0, 1, 1, e); }
}

extern "C" void kernel_launch(void* const* d_in, const int* in_sizes, int n_in,
                              void* d_out, int out_size)
{
    const float* features = (const float*)d_in[0];
    const float* cls      = (const float*)d_in[1];
    const float* ln1_g    = (const float*)d_in[2];
    const float* ln1_b    = (const float*)d_in[3];
    const float* qkv1_w   = (const float*)d_in[4];
    const float* out1_w   = (const float*)d_in[5];
    const float* out1_b   = (const float*)d_in[6];
    const float* res1_w   = (const float*)d_in[7];
    const float* pe_w7    = (const float*)d_in[8];
    const float* pe_b7    = (const float*)d_in[9];
    const float* pe_w5    = (const float*)d_in[10];
    const float* pe_b5    = (const float*)d_in[11];
    const float* pe_w3    = (const float*)d_in[12];
    const float* pe_b3    = (const float*)d_in[13];
    const float* ln2_g    = (const float*)d_in[14];
    const float* ln2_b    = (const float*)d_in[15];
    const float* qkv2_w   = (const float*)d_in[16];
    const float* out2_w   = (const float*)d_in[17];
    const float* out2_b   = (const float*)d_in[18];
    const float* res2_w   = (const float*)d_in[19];

    cudaFuncSetAttribute(gemm_p, cudaFuncAttributeMaxDynamicSharedMemorySize, GP_SMEM);
    cudaFuncSetAttribute(fused_attn1_k, cudaFuncAttributeMaxDynamicSharedMemorySize, FA_SMEM);
    cudaFuncSetAttribute(flash3_k, cudaFuncAttributeMaxDynamicSharedMemorySize, FL_SMEM);

    Ptrs p; get_ptrs(p);

    // launch order: build_h(1), wconv qkv1(2), ln_pad(3), qkv gemm(4) <- profiled
    build_h_k<<<(int)(((long)NH * C + 255) / 256), 256>>>(features, cls, p.h);
    wconvT_k<<<(QKVW * C + 255) / 256, 256>>>(qkv1_w, p.w1ah, p.w1al, C, QKVW);
    ln_pad_k<<<NP, 256>>>(p.h, p.xph, p.xpl, ln1_g, ln1_b);
    { EpiOut e = epi0(); e.ph = p.qkvh; e.pl = p.qkvl; e.palpha = 1.f; e.ldp = QKVW;
      gemmP(p.xph, p.xpl, p.w1ah, p.w1al, NP, QKVW, C, C, C, 0, 0, 1, 1, e); }

    // remaining weight converts
    wconvT_k<<<(C * C + 255) / 256, 256>>>(out1_w, p.w2ah, p.w2al, C, C);
    wconvT_k<<<(QKVW * C + 255) / 256, 256>>>(qkv2_w, p.w1bh, p.w1bl, C, QKVW);
    wconvT_k<<<(C * C + 255) / 256, 256>>>(out2_w, p.w2bh, p.w2bl, C, C);

    // layer 1 tail (after its qkv)
    nystrom_tail(p, p.h, p.w2ah, p.w2al, out1_b, res1_w);

    // PPEG
    ppeg_k<<<dim3(HW, HW), C>>>(p.h, p.h2, pe_w7, pe_b7, pe_w5, pe_b5, pe_w3, pe_b3);

    // layer 2
    ln_pad_k<<<NP, 256>>>(p.h2, p.xph, p.xpl, ln2_g, ln2_b);
    { EpiOut e = epi0(); e.ph = p.qkvh; e.pl = p.qkvl; e.palpha = 1.f; e.ldp = QKVW;
      gemmP(p.xph, p.xpl, p.w1bh, p.w1bl, NP, QKVW, C, C, C, 0, 0, 1, 1, e); }
    nystrom_tail(p, p.h2, p.w2bh, p.w2bl, out2_b, res2_w);

    cudaMemcpyAsync(d_out, p.h2, (size_t)out_size * sizeof(float),
                    cudaMemcpyDeviceToDevice);
}

// round 10
// speedup vs baseline: 1.0561x; 1.0043x over previous
#include <cuda_runtime.h>
#include <cuda_bf16.h>
#include <math.h>
#include <stdint.h>

typedef __nv_bfloat16 bf16;

// ---------------- problem constants ----------------
#define NH    22501
#define NFEAT 22400
#define HW    150
#define C     512
#define NP    22528
#define PADN  27
#define HEADS 8
#define DH    64
#define MM    256
#define LL    88
#define QKVW  1536
#define NSPLIT 8

// ---------------- fp32 scratch ----------------
__device__ float g_h   [(long)NH*C];
__device__ float g_h2  [(long)NH*C];
__device__ float g_a2  [HEADS*MM*MM];
__device__ float g_attn[(long)NP*C];
__device__ float g_outl[(long)NH*C];
__device__ float g_rowsum[HEADS*MM];
__device__ float g_colsum[HEADS*MM];
__device__ float g_fm[NSPLIT*HEADS*MM];
__device__ float g_fs[NSPLIT*HEADS*MM];
__device__ float g_scale[1];

// ---------------- bf16 hi/lo pair scratch ----------------
__device__ bf16 g_xph[(long)NP*C],     g_xpl[(long)NP*C];
__device__ bf16 g_qkvh[(long)NP*QKVW], g_qkvl[(long)NP*QKVW];
__device__ bf16 g_qlh[HEADS*MM*DH],    g_qll[HEADS*MM*DH];
__device__ bf16 g_klh[HEADS*MM*DH],    g_kll[HEADS*MM*DH];
__device__ bf16 g_a2h[HEADS*MM*MM],    g_a2l[HEADS*MM*MM];
__device__ bf16 g_zh [HEADS*MM*MM], g_zl [HEADS*MM*MM];
__device__ bf16 g_zth[HEADS*MM*MM], g_ztl[HEADS*MM*MM];
__device__ bf16 g_z2h[HEADS*MM*MM], g_z2l[HEADS*MM*MM];
__device__ bf16 g_z2th[HEADS*MM*MM], g_z2tl[HEADS*MM*MM];
__device__ bf16 g_xzh[HEADS*MM*MM], g_xzl[HEADS*MM*MM];
__device__ bf16 g_tah[HEADS*MM*MM], g_tal[HEADS*MM*MM];
__device__ bf16 g_tbh[HEADS*MM*MM], g_tbl[HEADS*MM*MM];
__device__ bf16 g_vth[(long)HEADS*DH*NP], g_vtl[(long)HEADS*DH*NP];
__device__ bf16 g_a3h[HEADS*DH*MM],    g_a3l[HEADS*DH*MM];
__device__ bf16 g_Wth[HEADS*DH*MM],    g_Wtl[HEADS*DH*MM];
__device__ bf16 g_ath[(long)NP*C],     g_atl[(long)NP*C];
__device__ bf16 g_w1ah[(long)QKVW*C],  g_w1al[(long)QKVW*C];
__device__ bf16 g_w2ah[(long)C*C],     g_w2al[(long)C*C];
__device__ bf16 g_w1bh[(long)QKVW*C],  g_w1bl[(long)QKVW*C];
__device__ bf16 g_w2bh[(long)C*C],     g_w2bl[(long)C*C];

// ---------------- small device helpers ----------------
__device__ __forceinline__ uint32_t smem_to_u32(const void* p) {
    uint32_t a;
    asm("{ .reg .u64 t; cvta.to.shared.u64 t, %1; cvt.u32.u64 %0, t; }"
        : "=r"(a) : "l"(p));
    return a;
}
__device__ __forceinline__ void ldsm4(uint32_t addr, uint32_t& r0, uint32_t& r1,
                                      uint32_t& r2, uint32_t& r3)
{
    asm volatile("ldmatrix.sync.aligned.m8n8.x4.shared.b16 {%0,%1,%2,%3}, [%4];"
                 : "=r"(r0), "=r"(r1), "=r"(r2), "=r"(r3) : "r"(addr));
}
__device__ __forceinline__ void mma_bf16(float* c, const uint32_t* a,
                                         uint32_t b0, uint32_t b1)
{
    asm volatile("mma.sync.aligned.m16n8k16.row.col.f32.bf16.bf16.f32 "
                 "{%0,%1,%2,%3},{%4,%5,%6,%7},{%8,%9},{%0,%1,%2,%3};"
                 : "+f"(c[0]), "+f"(c[1]), "+f"(c[2]), "+f"(c[3])
                 : "r"(a[0]), "r"(a[1]), "r"(a[2]), "r"(a[3]), "r"(b0), "r"(b1));
}
__device__ __forceinline__ void cpa16(uint32_t dst, const void* src, int sz)
{
    asm volatile("cp.async.cg.shared.global [%0], [%1], 16, %2;"
                 :: "r"(dst), "l"(src), "r"(sz));
}
__device__ __forceinline__ uint32_t pack2(float a, float b)   // a->low, b->high
{
    uint32_t r;
    asm("cvt.rn.bf16x2.f32 %0, %1, %2;" : "=r"(r) : "f"(b), "f"(a));
    return r;
}
__device__ __forceinline__ void split_bf(float x, float& hi, float& lo)
{
    hi = __bfloat162float(__float2bfloat16(x));
    lo = x - hi;
}
__device__ __forceinline__ float pairval(const bf16* h, const bf16* l, long i)
{
    return __bfloat162float(h[i]) + __bfloat162float(l[i]);
}

struct EpiOut {
    float* f; float falpha; int ldf; long sF;
    bf16 *ph, *pl; float palpha; int ldp; long sP;
    bf16 *th, *tl; float talpha, tdiag; int ldt; long sT;
    const float* resid;
    const float* bias;
};

// shared epilogue writer for one 2-value fragment slice
__device__ __forceinline__ void epi_write(const EpiOut& ep, float* F,
                                          bf16* Ph, bf16* Pl, bf16* Th, bf16* Tl,
                                          int gr, int gc, float va, float vb)
{
    if (F) {
        float o0 = ep.falpha * va, o1 = ep.falpha * vb;
        if (ep.bias)  { o0 += ep.bias[gc]; o1 += ep.bias[gc + 1]; }
        if (ep.resid) {
            o0 += ep.resid[(long)gr * ep.ldf + gc];
            o1 += ep.resid[(long)gr * ep.ldf + gc + 1];
        }
        *reinterpret_cast<float2*>(F + (long)gr * ep.ldf + gc) = make_float2(o0, o1);
    }
    if (Ph) {
        float s0 = ep.palpha * va, s1 = ep.palpha * vb;
        float h0, l0, h1, l1;
        split_bf(s0, h0, l0); split_bf(s1, h1, l1);
        *reinterpret_cast<uint32_t*>(Ph + (long)gr * ep.ldp + gc) = pack2(h0, h1);
        *reinterpret_cast<uint32_t*>(Pl + (long)gr * ep.ldp + gc) = pack2(l0, l1);
    }
    if (Th) {
        #pragma unroll
        for (int j = 0; j < 2; j++) {
            int cc = gc + j;
            float v = (j == 0) ? va : vb;
            float s = ep.talpha * v + ((gr == cc) ? ep.tdiag : 0.f);
            float hi, lo; split_bf(s, hi, lo);
            Th[(long)cc * ep.ldt + gr] = __float2bfloat16(hi);
            Tl[(long)cc * ep.ldt + gr] = __float2bfloat16(lo);
        }
    }
}

// =======================================================================
// gemm_p: 128x64x32 tile, 3-stage, 8 warps (4m x 2n), warp 32x32.
// Used for small-M batched GEMMs (pinv / a2 / W).
// =======================================================================
#define RS      80
#define AH_OFF  0
#define AL_OFF  10240
#define BH_OFF  20480
#define BL_OFF  25600
#define STAGE   30720
#define GP_SMEM (3 * STAGE)

__global__ void __launch_bounds__(256, 2)
gemm_p(const bf16* __restrict__ Ah, const bf16* __restrict__ Al,
       const bf16* __restrict__ Bh, const bf16* __restrict__ Bl,
       int M, int K, int lda, int ldb, long sA, long sB,
       EpiOut ep, int ksplit)
{
    extern __shared__ __align__(16) char sm[];
    const uint32_t sb0 = smem_to_u32(sm);
    const int tid = threadIdx.x, warp = tid >> 5, lane = tid & 31;
    const int wm = warp & 3, wn = warp >> 2;

    const int z = blockIdx.z;
    const int batch = z / ksplit;
    Ah += (long)batch * sA;  Al += (long)batch * sA;
    Bh += (long)batch * sB;  Bl += (long)batch * sB;

    const int row0 = blockIdx.y * 128, col0 = blockIdx.x * 64;
    const int nch = K >> 5;

    float acc[2][4][4];
    #pragma unroll
    for (int i = 0; i < 2; i++)
        #pragma unroll
        for (int j = 0; j < 4; j++)
            #pragma unroll
            for (int q = 0; q < 4; q++) acc[i][j][q] = 0.f;

    auto issue = [&](int it) {
        const int stg = it % 3;
        const uint32_t sb = sb0 + stg * STAGE;
        const int kc = it * 32;
        #pragma unroll
        for (int rep = 0; rep < 2; rep++) {
            int c = tid + rep * 256;
            int row = c >> 2, seg = c & 3;
            int gm = row0 + row;
            long go = (long)gm * lda + kc + seg * 8;
            int sz = (gm < M) ? 16 : 0;
            cpa16(sb + AH_OFF + row * RS + seg * 16, Ah + go, sz);
            cpa16(sb + AL_OFF + row * RS + seg * 16, Al + go, sz);
        }
        {
            int n = tid >> 2, seg = tid & 3;
            long go = (long)(col0 + n) * ldb + kc + seg * 8;
            cpa16(sb + BH_OFF + n * RS + seg * 16, Bh + go, 16);
            cpa16(sb + BL_OFF + n * RS + seg * 16, Bl + go, 16);
        }
        asm volatile("cp.async.commit_group;");
    };

    const int rsel = (lane & 7) + ((lane >> 3) & 1) * 8;
    const int ksel = ((lane >> 4) & 1) * 16;
    auto do_mma = [&](int stg) {
        uint32_t sb = sb0 + stg * STAGE;
        #pragma unroll
        for (int kk = 0; kk < 2; kk++) {
            uint32_t ah[2][4], al[2][4];
            #pragma unroll
            for (int mt = 0; mt < 2; mt++) {
                uint32_t ad = sb + AH_OFF + (wm * 32 + mt * 16 + rsel) * RS + kk * 32 + ksel;
                ldsm4(ad, ah[mt][0], ah[mt][1], ah[mt][2], ah[mt][3]);
                ldsm4(ad + (AL_OFF - AH_OFF), al[mt][0], al[mt][1], al[mt][2], al[mt][3]);
            }
            #pragma unroll
            for (int np = 0; np < 2; np++) {
                uint32_t bd = sb + BH_OFF + (wn * 32 + np * 16 + rsel) * RS + kk * 32 + ksel;
                uint32_t q0, q1, q2, q3, r0, r1, r2, r3;
                ldsm4(bd, q0, q1, q2, q3);
                ldsm4(bd + (BL_OFF - BH_OFF), r0, r1, r2, r3);
                #pragma unroll
                for (int mt = 0; mt < 2; mt++) {
                    mma_bf16(acc[mt][2*np],   ah[mt], q0, q2);
                    mma_bf16(acc[mt][2*np],   ah[mt], r0, r2);
                    mma_bf16(acc[mt][2*np],   al[mt], q0, q2);
                    mma_bf16(acc[mt][2*np+1], ah[mt], q1, q3);
                    mma_bf16(acc[mt][2*np+1], ah[mt], r1, r3);
                    mma_bf16(acc[mt][2*np+1], al[mt], q1, q3);
                }
            }
        }
    };

    issue(0);
    if (nch > 1) issue(1);
    for (int it = 0; it < nch; it++) {
        if (it + 1 < nch) asm volatile("cp.async.wait_group 1;");
        else              asm volatile("cp.async.wait_group 0;");
        __syncthreads();
        if (it + 2 < nch) issue(it + 2);
        do_mma(it % 3);
    }

    const int er = lane >> 2, eq = lane & 3;
    float* F  = ep.f  ? ep.f  + (long)z     * ep.sF : (float*)0;
    bf16* Ph  = ep.ph ? ep.ph + (long)batch * ep.sP : (bf16*)0;
    bf16* Pl  = ep.pl ? ep.pl + (long)batch * ep.sP : (bf16*)0;
    bf16* Th  = ep.th ? ep.th + (long)batch * ep.sT : (bf16*)0;
    bf16* Tl  = ep.tl ? ep.tl + (long)batch * ep.sT : (bf16*)0;

    #pragma unroll
    for (int mt = 0; mt < 2; mt++)
        #pragma unroll
        for (int nt = 0; nt < 4; nt++) {
            int gr0 = row0 + wm * 32 + mt * 16 + er;
            int gc  = col0 + wn * 32 + nt * 8 + 2 * eq;
            #pragma unroll
            for (int half = 0; half < 2; half++) {
                int gr = gr0 + 8 * half;
                if (gr >= M) continue;
                epi_write(ep, F, Ph, Pl, Th, Tl, gr, gc,
                          acc[mt][nt][2 * half], acc[mt][nt][2 * half + 1]);
            }
        }
}

// =======================================================================
// gemm_p2: 256x64x32 tile, 2-stage, 8 warps (4m x 2n), warp 64x32.
// 12 LDSM -> 48 mma per warp-k16 (4 mma/LDSM). Used for big-M GEMMs.
// =======================================================================
#define P2_AH   0
#define P2_AL   20480
#define P2_BH   40960
#define P2_BL   46080
#define P2_STG  51200
#define GP2_SMEM (2 * P2_STG)

__global__ void __launch_bounds__(256, 2)
gemm_p2(const bf16* __restrict__ Ah, const bf16* __restrict__ Al,
        const bf16* __restrict__ Bh, const bf16* __restrict__ Bl,
        int M, int K, int lda, int ldb,
        EpiOut ep)
{
    extern __shared__ __align__(16) char sm[];
    const uint32_t sb0 = smem_to_u32(sm);
    const int tid = threadIdx.x, warp = tid >> 5, lane = tid & 31;
    const int wm = warp & 3, wn = warp >> 2;

    const int row0 = blockIdx.y * 256, col0 = blockIdx.x * 64;
    const int nch = K >> 5;

    float acc[4][4][4];
    #pragma unroll
    for (int i = 0; i < 4; i++)
        #pragma unroll
        for (int j = 0; j < 4; j++)
            #pragma unroll
            for (int q = 0; q < 4; q++) acc[i][j][q] = 0.f;

    auto issue = [&](int it) {
        const uint32_t sb = sb0 + (it & 1) * P2_STG;
        const int kc = it * 32;
        #pragma unroll
        for (int rep = 0; rep < 4; rep++) {
            int c = tid + rep * 256;
            int row = c >> 2, seg = c & 3;
            int gm = row0 + row;
            long go = (long)gm * lda + kc + seg * 8;
            int sz = (gm < M) ? 16 : 0;
            cpa16(sb + P2_AH + row * RS + seg * 16, Ah + go, sz);
            cpa16(sb + P2_AL + row * RS + seg * 16, Al + go, sz);
        }
        {
            int n = tid >> 2, seg = tid & 3;
            long go = (long)(col0 + n) * ldb + kc + seg * 8;
            cpa16(sb + P2_BH + n * RS + seg * 16, Bh + go, 16);
            cpa16(sb + P2_BL + n * RS + seg * 16, Bl + go, 16);
        }
        asm volatile("cp.async.commit_group;");
    };

    const int rsel = (lane & 7) + ((lane >> 3) & 1) * 8;
    const int ksel = ((lane >> 4) & 1) * 16;
    auto do_mma = [&](int stg) {
        uint32_t sb = sb0 + stg * P2_STG;
        #pragma unroll
        for (int kk = 0; kk < 2; kk++) {
            uint32_t ah[4][4], al[4][4];
            #pragma unroll
            for (int mt = 0; mt < 4; mt++) {
                uint32_t ad = sb + P2_AH + (wm * 64 + mt * 16 + rsel) * RS + kk * 32 + ksel;
                ldsm4(ad, ah[mt][0], ah[mt][1], ah[mt][2], ah[mt][3]);
                ldsm4(ad + (P2_AL - P2_AH), al[mt][0], al[mt][1], al[mt][2], al[mt][3]);
            }
            #pragma unroll
            for (int np = 0; np < 2; np++) {
                uint32_t bd = sb + P2_BH + (wn * 32 + np * 16 + rsel) * RS + kk * 32 + ksel;
                uint32_t q0, q1, q2, q3, r0, r1, r2, r3;
                ldsm4(bd, q0, q1, q2, q3);
                ldsm4(bd + (P2_BL - P2_BH), r0, r1, r2, r3);
                #pragma unroll
                for (int mt = 0; mt < 4; mt++) {
                    mma_bf16(acc[mt][2*np],   ah[mt], q0, q2);
                    mma_bf16(acc[mt][2*np],   ah[mt], r0, r2);
                    mma_bf16(acc[mt][2*np],   al[mt], q0, q2);
                    mma_bf16(acc[mt][2*np+1], ah[mt], q1, q3);
                    mma_bf16(acc[mt][2*np+1], ah[mt], r1, r3);
                    mma_bf16(acc[mt][2*np+1], al[mt], q1, q3);
                }
            }
        }
    };

    issue(0);
    for (int it = 0; it < nch; it++) {
        if (it + 1 < nch) { issue(it + 1); asm volatile("cp.async.wait_group 1;"); }
        else              { asm volatile("cp.async.wait_group 0;"); }
        __syncthreads();
        do_mma(it & 1);
        __syncthreads();   // all reads of this buffer done before it is re-issued
    }

    const int er = lane >> 2, eq = lane & 3;
    float* F  = ep.f;
    bf16* Ph  = ep.ph;  bf16* Pl = ep.pl;
    bf16* Th  = ep.th;  bf16* Tl = ep.tl;

    #pragma unroll
    for (int mt = 0; mt < 4; mt++)
        #pragma unroll
        for (int nt = 0; nt < 4; nt++) {
            int gr0 = row0 + wm * 64 + mt * 16 + er;
            int gc  = col0 + wn * 32 + nt * 8 + 2 * eq;
            #pragma unroll
            for (int half = 0; half < 2; half++) {
                int gr = gr0 + 8 * half;
                if (gr >= M) continue;
                epi_write(ep, F, Ph, Pl, Th, Tl, gr, gc,
                          acc[mt][nt][2 * half], acc[mt][nt][2 * half + 1]);
            }
        }
}

static EpiOut epi0() { EpiOut e{}; return e; }
static void gemmP(const bf16* Ah, const bf16* Al, const bf16* Bh, const bf16* Bl,
                  int M, int N, int K, int lda, int ldb, long sA, long sB,
                  int batch, int ksplit, EpiOut ep)
{
    if (batch == 1 && M >= 512) {
        dim3 g(N / 64, (M + 255) / 256, 1), b(256);
        gemm_p2<<<g, b, GP2_SMEM>>>(Ah, Al, Bh, Bl, M, K, lda, ldb, ep);
    } else {
        dim3 g(N / 64, (M + 127) / 128, batch * ksplit), b(256);
        gemm_p<<<g, b, GP_SMEM>>>(Ah, Al, Bh, Bl, M, K, lda, ldb, sA, sB, ep, ksplit);
    }
}

// =======================================================================
// flash-fused S3 path (unchanged)
// =======================================================================
#define FL_RS   144
#define FL_QH   0
#define FL_QL   18432
#define FL_K(b) (36864 + (b) * 18432)
#define FL_V(b) (73728 + (b) * 18432)
#define FL_PH   110592
#define FL_PL   129024
#define FL_SMEM 147456
#define FL_NCH  ((NP / NSPLIT) / 64)

__global__ void __launch_bounds__(128)
flash3_k(const bf16* __restrict__ qlh, const bf16* __restrict__ qll,
         const bf16* __restrict__ qkvh, const bf16* __restrict__ qkvl,
         const bf16* __restrict__ vth, const bf16* __restrict__ vtl,
         float* __restrict__ pO, float* __restrict__ pm, float* __restrict__ ps)
{
    extern __shared__ __align__(16) char sm[];
    const uint32_t sb = smem_to_u32(sm);
    const int tid = threadIdx.x, warp = tid >> 5, lane = tid & 31;
    const int split = blockIdx.x, rowHalf = blockIdx.y, head = blockIdx.z;
    const int tb0 = split * (NP / NSPLIT);

    const bf16* Qh = qlh + ((long)head * MM + rowHalf * 128) * DH;
    const bf16* Ql = qll + ((long)head * MM + rowHalf * 128) * DH;
    #pragma unroll
    for (int i = 0; i < 8; i++) {
        int s = tid + 128 * i;
        int r = s >> 3, seg = s & 7;
        long go = (long)r * DH + seg * 8;
        cpa16(sb + FL_QH + r * FL_RS + seg * 16, Qh + go, 16);
        cpa16(sb + FL_QL + r * FL_RS + seg * 16, Ql + go, 16);
    }

    const bf16* Kh = qkvh + head * DH + 512;
    const bf16* Kl = qkvl + head * DH + 512;
    const bf16* Vh = vth + (long)head * DH * NP;
    const bf16* Vl = vtl + (long)head * DH * NP;

    auto kissue = [&](int j) {
        int buf = j & 1;
        int tb = tb0 + j * 64;
        uint32_t kb = sb + FL_K(buf);
        uint32_t vb = sb + FL_V(buf);
        #pragma unroll
        for (int i = 0; i < 4; i++) {
            int s = tid + 128 * i;
            int r = s >> 3, seg = s & 7;
            long gk = (long)(tb + r) * QKVW + seg * 8;
            cpa16(kb + r * FL_RS + seg * 16, Kh + gk, 16);
            cpa16(kb + 9216 + r * FL_RS + seg * 16, Kl + gk, 16);
            long gv = (long)r * NP + tb + seg * 8;
            cpa16(vb + r * FL_RS + seg * 16, Vh + gv, 16);
            cpa16(vb + 9216 + r * FL_RS + seg * 16, Vl + gv, 16);
        }
        asm volatile("cp.async.commit_group;");
    };
    kissue(0);
    kissue(1);

    const int rsel = (lane & 7) + ((lane >> 3) & 1) * 8;
    const int ksel = ((lane >> 4) & 1) * 16;
    const int er = lane >> 2, eq = lane & 3;

    float m_run[4] = {-1e30f, -1e30f, -1e30f, -1e30f};
    float s_run[4] = {0.f, 0.f, 0.f, 0.f};
    float oacc[2][8][4];
    #pragma unroll
    for (int a = 0; a < 2; a++)
        #pragma unroll
        for (int b = 0; b < 8; b++)
            #pragma unroll
            for (int c = 0; c < 4; c++) oacc[a][b][c] = 0.f;

    for (int j = 0; j < FL_NCH; j++) {
        if (j + 1 < FL_NCH) asm volatile("cp.async.wait_group 1;");
        else                asm volatile("cp.async.wait_group 0;");
        __syncthreads();
        uint32_t kb = sb + FL_K(j & 1);
        uint32_t vb = sb + FL_V(j & 1);

        float sacc[2][8][4];
        #pragma unroll
        for (int a = 0; a < 2; a++)
            #pragma unroll
            for (int b = 0; b < 8; b++)
                #pragma unroll
                for (int c = 0; c < 4; c++) sacc[a][b][c] = 0.f;

        #pragma unroll
        for (int k16 = 0; k16 < 4; k16++) {
            uint32_t ah[2][4], al[2][4];
            #pragma unroll
            for (int mt = 0; mt < 2; mt++) {
                uint32_t ad = sb + FL_QH + (warp * 32 + mt * 16 + rsel) * FL_RS + k16 * 32 + ksel;
                ldsm4(ad, ah[mt][0], ah[mt][1], ah[mt][2], ah[mt][3]);
                ldsm4(ad + (FL_QL - FL_QH), al[mt][0], al[mt][1], al[mt][2], al[mt][3]);
            }
            #pragma unroll
            for (int n16 = 0; n16 < 4; n16++) {
                uint32_t bd = kb + (n16 * 16 + rsel) * FL_RS + k16 * 32 + ksel;
                uint32_t q0, q1, q2, q3, p0, p1, p2, p3;
                ldsm4(bd, q0, q1, q2, q3);
                ldsm4(bd + 9216, p0, p1, p2, p3);
                #pragma unroll
                for (int mt = 0; mt < 2; mt++) {
                    mma_bf16(sacc[mt][2*n16],   ah[mt], q0, q2);
                    mma_bf16(sacc[mt][2*n16],   ah[mt], p0, p2);
                    mma_bf16(sacc[mt][2*n16],   al[mt], q0, q2);
                    mma_bf16(sacc[mt][2*n16+1], ah[mt], q1, q3);
                    mma_bf16(sacc[mt][2*n16+1], ah[mt], p1, p3);
                    mma_bf16(sacc[mt][2*n16+1], al[mt], q1, q3);
                }
            }
        }

        #pragma unroll
        for (int mt = 0; mt < 2; mt++) {
            float cm0 = -1e30f, cm1 = -1e30f;
            #pragma unroll
            for (int nt = 0; nt < 8; nt++) {
                cm0 = fmaxf(cm0, fmaxf(sacc[mt][nt][0], sacc[mt][nt][1]));
                cm1 = fmaxf(cm1, fmaxf(sacc[mt][nt][2], sacc[mt][nt][3]));
            }
            #pragma unroll
            for (int o = 1; o <= 2; o <<= 1) {
                cm0 = fmaxf(cm0, __shfl_xor_sync(0xffffffffu, cm0, o));
                cm1 = fmaxf(cm1, __shfl_xor_sync(0xffffffffu, cm1, o));
            }
            float mn0 = fmaxf(m_run[2*mt],     cm0);
            float mn1 = fmaxf(m_run[2*mt + 1], cm1);
            float sc0 = __expf(m_run[2*mt]     - mn0);
            float sc1 = __expf(m_run[2*mt + 1] - mn1);
            m_run[2*mt] = mn0; m_run[2*mt + 1] = mn1;
            float ls0 = 0.f, ls1 = 0.f;
            int pr = warp * 32 + mt * 16 + er;
            #pragma unroll
            for (int nt = 0; nt < 8; nt++) {
                float e0 = __expf(sacc[mt][nt][0] - mn0);
                float e1 = __expf(sacc[mt][nt][1] - mn0);
                float e2 = __expf(sacc[mt][nt][2] - mn1);
                float e3 = __expf(sacc[mt][nt][3] - mn1);
                ls0 += e0 + e1; ls1 += e2 + e3;
                oacc[mt][nt][0] *= sc0; oacc[mt][nt][1] *= sc0;
                oacc[mt][nt][2] *= sc1; oacc[mt][nt][3] *= sc1;
                int col = nt * 8 + 2 * eq;
                float h0, l0, h1, l1;
                split_bf(e0, h0, l0); split_bf(e1, h1, l1);
                *reinterpret_cast<uint32_t*>(sm + FL_PH + pr * FL_RS + col * 2) = pack2(h0, h1);
                *reinterpret_cast<uint32_t*>(sm + FL_PL + pr * FL_RS + col * 2) = pack2(l0, l1);
                split_bf(e2, h0, l0); split_bf(e3, h1, l1);
                *reinterpret_cast<uint32_t*>(sm + FL_PH + (pr + 8) * FL_RS + col * 2) = pack2(h0, h1);
                *reinterpret_cast<uint32_t*>(sm + FL_PL + (pr + 8) * FL_RS + col * 2) = pack2(l0, l1);
            }
            #pragma unroll
            for (int o = 1; o <= 2; o <<= 1) {
                ls0 += __shfl_xor_sync(0xffffffffu, ls0, o);
                ls1 += __shfl_xor_sync(0xffffffffu, ls1, o);
            }
            s_run[2*mt]     = s_run[2*mt]     * sc0 + ls0;
            s_run[2*mt + 1] = s_run[2*mt + 1] * sc1 + ls1;
        }
        __syncthreads();

        #pragma unroll
        for (int k16 = 0; k16 < 4; k16++) {
            uint32_t ph[2][4], pl[2][4];
            #pragma unroll
            for (int mt = 0; mt < 2; mt++) {
                uint32_t ad = sb + FL_PH + (warp * 32 + mt * 16 + rsel) * FL_RS + k16 * 32 + ksel;
                ldsm4(ad, ph[mt][0], ph[mt][1], ph[mt][2], ph[mt][3]);
                ldsm4(ad + (FL_PL - FL_PH), pl[mt][0], pl[mt][1], pl[mt][2], pl[mt][3]);
            }
            #pragma unroll
            for (int n16 = 0; n16 < 4; n16++) {
                uint32_t bd = vb + (n16 * 16 + rsel) * FL_RS + k16 * 32 + ksel;
                uint32_t q0, q1, q2, q3, r0, r1, r2, r3;
                ldsm4(bd, q0, q1, q2, q3);
                ldsm4(bd + 9216, r0, r1, r2, r3);
                #pragma unroll
                for (int mt = 0; mt < 2; mt++) {
                    mma_bf16(oacc[mt][2*n16],   ph[mt], q0, q2);
                    mma_bf16(oacc[mt][2*n16],   ph[mt], r0, r2);
                    mma_bf16(oacc[mt][2*n16],   pl[mt], q0, q2);
                    mma_bf16(oacc[mt][2*n16+1], ph[mt], q1, q3);
                    mma_bf16(oacc[mt][2*n16+1], ph[mt], r1, r3);
                    mma_bf16(oacc[mt][2*n16+1], pl[mt], q1, q3);
                }
            }
        }
        __syncthreads();
        if (j + 2 < FL_NCH) kissue(j + 2);
    }

    const int base = (split * HEADS + head) * MM + rowHalf * 128;
    #pragma unroll
    for (int mt = 0; mt < 2; mt++) {
        int r0 = base + warp * 32 + mt * 16 + er;
        #pragma unroll
        for (int nt = 0; nt < 8; nt++) {
            int d = nt * 8 + 2 * eq;
            *reinterpret_cast<float2*>(pO + (long)r0 * DH + d) =
                make_float2(oacc[mt][nt][0], oacc[mt][nt][1]);
            *reinterpret_cast<float2*>(pO + (long)(r0 + 8) * DH + d) =
                make_float2(oacc[mt][nt][2], oacc[mt][nt][3]);
        }
        if (eq == 0) {
            pm[r0] = m_run[2*mt];     ps[r0] = s_run[2*mt];
            pm[r0 + 8] = m_run[2*mt + 1]; ps[r0 + 8] = s_run[2*mt + 1];
        }
    }
}

__global__ void flash_merge_k(const float* __restrict__ pO, const float* __restrict__ pm,
                              const float* __restrict__ ps,
                              bf16* __restrict__ oh, bf16* __restrict__ ol)
{
    int row = blockIdx.x, head = blockIdx.y, d = threadIdx.x;
    float mx = -1e30f;
    #pragma unroll
    for (int i = 0; i < NSPLIT; i++)
        mx = fmaxf(mx, pm[(i * HEADS + head) * MM + row]);
    float den = 0.f, acc = 0.f;
    #pragma unroll
    for (int i = 0; i < NSPLIT; i++) {
        int r = (i * HEADS + head) * MM + row;
        float w = __expf(pm[r] - mx);
        den += w * ps[r];
        acc += w * pO[(long)r * DH + d];
    }
    float v = acc / den;
    float hi, lo; split_bf(v, hi, lo);
    long o = ((long)head << 14) + d * MM + row;
    oh[o] = __float2bfloat16(hi);
    ol[o] = __float2bfloat16(lo);
}

// =======================================================================
// fused S1 -> softmax -> O1 (unchanged)
// =======================================================================
#define FA_RS1  144
#define FA_AH   0
#define FA_AL   9216
#define FA_BH   18432
#define FA_BL   55296
#define FA_PH   0
#define FA_PL   33792
#define FA_WS   67584
#define FA_WST  10240
#define FA_SMEM 98304

__global__ void __launch_bounds__(128)
fused_attn1_k(const bf16* __restrict__ qh, const bf16* __restrict__ ql_,
              const bf16* __restrict__ klh, const bf16* __restrict__ kll,
              const bf16* __restrict__ Wth, const bf16* __restrict__ Wtl,
              float* __restrict__ attn)
{
    extern __shared__ __align__(16) char sm[];
    const uint32_t sb = smem_to_u32(sm);
    const int tid = threadIdx.x, warp = tid >> 5, lane = tid & 31;
    const int row0 = blockIdx.x * 64;
    const int head = blockIdx.y;

    const bf16* qsh = qh  + (long)row0 * QKVW + head * DH;
    const bf16* qsl = ql_ + (long)row0 * QKVW + head * DH;
    #pragma unroll
    for (int i = 0; i < 4; i++) {
        int s = tid + 128 * i;
        int r = s >> 3, seg = s & 7;
        long go = (long)r * QKVW + seg * 8;
        cpa16(sb + FA_AH + r * FA_RS1 + seg * 16, qsh + go, 16);
        cpa16(sb + FA_AL + r * FA_RS1 + seg * 16, qsl + go, 16);
    }
    const bf16* ksh = klh + (long)head * MM * DH;
    const bf16* ksl = kll + (long)head * MM * DH;
    #pragma unroll
    for (int i = 0; i < 16; i++) {
        int s = tid + 128 * i;
        int r = s >> 3, seg = s & 7;
        long go = (long)r * DH + seg * 8;
        cpa16(sb + FA_BH + r * FA_RS1 + seg * 16, ksh + go, 16);
        cpa16(sb + FA_BL + r * FA_RS1 + seg * 16, ksl + go, 16);
    }
    asm volatile("cp.async.commit_group;");
    asm volatile("cp.async.wait_group 0;");
    __syncthreads();

    const int rsel = (lane & 7) + ((lane >> 3) & 1) * 8;
    const int ksel = ((lane >> 4) & 1) * 16;
    float sacc[32][4];
    #pragma unroll
    for (int i = 0; i < 32; i++)
        #pragma unroll
        for (int j = 0; j < 4; j++) sacc[i][j] = 0.f;

    #pragma unroll
    for (int k16 = 0; k16 < 4; k16++) {
        uint32_t ah[4], al[4];
        uint32_t ad = sb + FA_AH + (warp * 16 + rsel) * FA_RS1 + k16 * 32 + ksel;
        ldsm4(ad, ah[0], ah[1], ah[2], ah[3]);
        ldsm4(ad + (FA_AL - FA_AH), al[0], al[1], al[2], al[3]);
        #pragma unroll
        for (int n16 = 0; n16 < 16; n16++) {
            uint32_t bd = sb + FA_BH + (n16 * 16 + rsel) * FA_RS1 + k16 * 32 + ksel;
            uint32_t q0, q1, q2, q3, p0, p1, p2, p3;
            ldsm4(bd, q0, q1, q2, q3);
            ldsm4(bd + (FA_BL - FA_BH), p0, p1, p2, p3);
            mma_bf16(sacc[2*n16],   ah, q0, q2);
            mma_bf16(sacc[2*n16],   ah, p0, p2);
            mma_bf16(sacc[2*n16],   al, q0, q2);
            mma_bf16(sacc[2*n16+1], ah, q1, q3);
            mma_bf16(sacc[2*n16+1], ah, p1, p3);
            mma_bf16(sacc[2*n16+1], al, q1, q3);
        }
    }

    float mx0 = -1e30f, mx1 = -1e30f;
    #pragma unroll
    for (int nt = 0; nt < 32; nt++) {
        #pragma unroll
        for (int j = 0; j < 4; j++) sacc[nt][j] *= 0.125f;
        mx0 = fmaxf(mx0, fmaxf(sacc[nt][0], sacc[nt][1]));
        mx1 = fmaxf(mx1, fmaxf(sacc[nt][2], sacc[nt][3]));
    }
    #pragma unroll
    for (int o = 1; o <= 2; o <<= 1) {
        mx0 = fmaxf(mx0, __shfl_xor_sync(0xffffffffu, mx0, o));
        mx1 = fmaxf(mx1, __shfl_xor_sync(0xffffffffu, mx1, o));
    }
    float sm0 = 0.f, sm1 = 0.f;
    #pragma unroll
    for (int nt = 0; nt < 32; nt++) {
        sacc[nt][0] = __expf(sacc[nt][0] - mx0);
        sacc[nt][1] = __expf(sacc[nt][1] - mx0);
        sacc[nt][2] = __expf(sacc[nt][2] - mx1);
        sacc[nt][3] = __expf(sacc[nt][3] - mx1);
        sm0 += sacc[nt][0] + sacc[nt][1];
        sm1 += sacc[nt][2] + sacc[nt][3];
    }
    #pragma unroll
    for (int o = 1; o <= 2; o <<= 1) {
        sm0 += __shfl_xor_sync(0xffffffffu, sm0, o);
        sm1 += __shfl_xor_sync(0xffffffffu, sm1, o);
    }
    __syncthreads();

    const bf16* Wsh = Wth + (long)head * DH * MM;
    const bf16* Wsl = Wtl + (long)head * DH * MM;
    auto wissue = [&](int it) {
        int stg = it % 3;
        uint32_t base = sb + FA_WS + stg * FA_WST;
        #pragma unroll
        for (int i = 0; i < 2; i++) {
            int s = tid + 128 * i;
            int r = s >> 2, seg = s & 3;
            long go = (long)r * MM + it * 32 + seg * 8;
            cpa16(base + r * 80 + seg * 16, Wsh + go, 16);
            cpa16(base + 5120 + r * 80 + seg * 16, Wsl + go, 16);
        }
        asm volatile("cp.async.commit_group;");
    };
    wissue(0); wissue(1);

    {
        int pr = warp * 16 + (lane >> 2);
        int pc = (lane & 3) * 2;
        #pragma unroll
        for (int nt = 0; nt < 32; nt++) {
            int col = nt * 8 + pc;
            float h0, l0, h1, l1;
            split_bf(sacc[nt][0], h0, l0); split_bf(sacc[nt][1], h1, l1);
            *reinterpret_cast<uint32_t*>(sm + FA_PH + pr * 528 + col * 2) = pack2(h0, h1);
            *reinterpret_cast<uint32_t*>(sm + FA_PL + pr * 528 + col * 2) = pack2(l0, l1);
            split_bf(sacc[nt][2], h0, l0); split_bf(sacc[nt][3], h1, l1);
            *reinterpret_cast<uint32_t*>(sm + FA_PH + (pr + 8) * 528 + col * 2) = pack2(h0, h1);
            *reinterpret_cast<uint32_t*>(sm + FA_PL + (pr + 8) * 528 + col * 2) = pack2(l0, l1);
        }
    }
    __syncthreads();

    float oacc[8][4];
    #pragma unroll
    for (int i = 0; i < 8; i++)
        #pragma unroll
        for (int j = 0; j < 4; j++) oacc[i][j] = 0.f;

    for (int it = 0; it < 8; it++) {
        if (it < 7) asm volatile("cp.async.wait_group 1;");
        else        asm volatile("cp.async.wait_group 0;");
        __syncthreads();
        if (it + 2 < 8) wissue(it + 2);
        uint32_t wb = sb + FA_WS + (it % 3) * FA_WST;
        #pragma unroll
        for (int k16 = 0; k16 < 2; k16++) {
            int gk = it * 2 + k16;
            uint32_t ph[4], pl[4];
            uint32_t ad = sb + FA_PH + (warp * 16 + rsel) * 528 + gk * 32 + ksel;
            ldsm4(ad, ph[0], ph[1], ph[2], ph[3]);
            ldsm4(ad + (FA_PL - FA_PH), pl[0], pl[1], pl[2], pl[3]);
            #pragma unroll
            for (int n16 = 0; n16 < 4; n16++) {
                uint32_t bd = wb + (n16 * 16 + rsel) * 80 + k16 * 32 + ksel;
                uint32_t q0, q1, q2, q3, r0, r1, r2, r3;
                ldsm4(bd, q0, q1, q2, q3);
                ldsm4(bd + 5120, r0, r1, r2, r3);
                mma_bf16(oacc[2*n16],   ph, q0, q2);
                mma_bf16(oacc[2*n16],   ph, r0, r2);
                mma_bf16(oacc[2*n16],   pl, q0, q2);
                mma_bf16(oacc[2*n16+1], ph, q1, q3);
                mma_bf16(oacc[2*n16+1], ph, r1, r3);
                mma_bf16(oacc[2*n16+1], pl, q1, q3);
            }
        }
    }

    float inv0 = 1.f / sm0, inv1 = 1.f / sm1;
    int orow = row0 + warp * 16 + (lane >> 2);
    int ocol = head * DH + (lane & 3) * 2;
    #pragma unroll
    for (int nt = 0; nt < 8; nt++) {
        int col = ocol + nt * 8;
        *reinterpret_cast<float2*>(attn + (long)orow * C + col) =
            make_float2(oacc[nt][0] * inv0, oacc[nt][1] * inv0);
        *reinterpret_cast<float2*>(attn + (long)(orow + 8) * C + col) =
            make_float2(oacc[nt][2] * inv1, oacc[nt][3] * inv1);
    }
}

// =======================================================================
// auxiliary kernels (unchanged)
// =======================================================================

__global__ void wconvT_k(const float* __restrict__ w, bf16* __restrict__ th,
                         bf16* __restrict__ tl, int K, int N)
{
    int i = blockIdx.x * 256 + threadIdx.x;
    if (i >= N * K) return;
    int n = i / K, k = i - n * K;
    float v = w[(long)k * N + n];
    float hi, lo; split_bf(v, hi, lo);
    th[i] = __float2bfloat16(hi);
    tl[i] = __float2bfloat16(lo);
}

__global__ void build_h_k(const float* __restrict__ feat, const float* __restrict__ cls,
                          float* __restrict__ h)
{
    long i = (long)blockIdx.x * 256 + threadIdx.x;
    if (i >= (long)NH * C) return;
    long t = i >> 9;
    int  c = (int)(i & 511);
    float v;
    if (t == 0) v = cls[c];
    else {
        long r = t - 1;
        if (r >= NFEAT) r -= NFEAT;
        v = feat[r * C + c];
    }
    h[i] = v;
}

__global__ void ln_pad_k(const float* __restrict__ h, bf16* __restrict__ xh,
                         bf16* __restrict__ xl,
                         const float* __restrict__ g, const float* __restrict__ b)
{
    int t = blockIdx.x, c = threadIdx.x;
    long o = (long)t * C;
    if (t < PADN) {
        *reinterpret_cast<uint32_t*>(xh + o + 2 * c) = 0u;
        *reinterpret_cast<uint32_t*>(xl + o + 2 * c) = 0u;
        return;
    }
    const float* row = h + (long)(t - PADN) * C;
    float a1 = row[2 * c], a2 = row[2 * c + 1];
    __shared__ float red[256];
    red[c] = a1 + a2; __syncthreads();
    for (int s = 128; s > 0; s >>= 1) { if (c < s) red[c] += red[c + s]; __syncthreads(); }
    float mu = red[0] * (1.f / 512.f);
    __syncthreads();
    float d1 = a1 - mu, d2 = a2 - mu;
    red[c] = d1 * d1 + d2 * d2; __syncthreads();
    for (int s = 128; s > 0; s >>= 1) { if (c < s) red[c] += red[c + s]; __syncthreads(); }
    float inv = rsqrtf(red[0] * (1.f / 512.f) + 1e-5f);
    float v1 = d1 * inv * g[2 * c] + b[2 * c];
    float v2 = d2 * inv * g[2 * c + 1] + b[2 * c + 1];
    float h1, l1, h2, l2;
    split_bf(v1, h1, l1); split_bf(v2, h2, l2);
    *reinterpret_cast<uint32_t*>(xh + o + 2 * c) = pack2(h1, h2);
    *reinterpret_cast<uint32_t*>(xl + o + 2 * c) = pack2(l1, l2);
}

__global__ void landmarks_k(const bf16* __restrict__ qh, const bf16* __restrict__ ql_,
                            bf16* __restrict__ qlh, bf16* __restrict__ qll,
                            bf16* __restrict__ klh, bf16* __restrict__ kll)
{
    int d = threadIdx.x;
    int m = blockIdx.x & 255;
    int hh = blockIdx.x >> 8;
    long base = (long)(m * LL) * QKVW + hh * DH + d;
    float sq = 0.f, sk = 0.f;
    for (int j = 0; j < LL; j++) {
        long o = base + (long)j * QKVW;
        sq += pairval(qh, ql_, o);
        sk += pairval(qh, ql_, o + 512);
    }
    float vq = sq * (0.125f / (float)LL);
    float vk = sk * (1.f / (float)LL);
    int oi = (hh * MM + m) * DH + d;
    float hi, lo;
    split_bf(vq, hi, lo); qlh[oi] = __float2bfloat16(hi); qll[oi] = __float2bfloat16(lo);
    split_bf(vk, hi, lo); klh[oi] = __float2bfloat16(hi); kll[oi] = __float2bfloat16(lo);
}

__global__ void softmax256_k(const float* __restrict__ in, float* __restrict__ fout,
                             bf16* __restrict__ ph, bf16* __restrict__ pl, long nrows)
{
    long row = (long)blockIdx.x * 8 + threadIdx.y;
    if (row >= nrows) return;
    const float* r = in + row * 256;
    int lane = threadIdx.x;
    float v[8], m = -1e30f;
    #pragma unroll
    for (int i = 0; i < 8; i++) { v[i] = r[lane + 32 * i]; m = fmaxf(m, v[i]); }
    #pragma unroll
    for (int o = 16; o; o >>= 1) m = fmaxf(m, __shfl_xor_sync(0xffffffffu, m, o));
    float s = 0.f;
    #pragma unroll
    for (int i = 0; i < 8; i++) { v[i] = __expf(v[i] - m); s += v[i]; }
    #pragma unroll
    for (int o = 16; o; o >>= 1) s += __shfl_xor_sync(0xffffffffu, s, o);
    float inv = 1.f / s;
    #pragma unroll
    for (int i = 0; i < 8; i++) {
        float val = v[i] * inv;
        long o = row * 256 + lane + 32 * i;
        if (fout) fout[o] = val;
        float hi, lo; split_bf(val, hi, lo);
        ph[o] = __float2bfloat16(hi);
        pl[o] = __float2bfloat16(lo);
    }
}

__global__ void pinv_sums_k(const float* __restrict__ a2,
                            float* __restrict__ rs, float* __restrict__ cs)
{
    int hh = blockIdx.x, j = threadIdx.x;
    const float* X = a2 + (long)hh * MM * MM;
    float r = 0.f, c = 0.f;
    for (int k = 0; k < MM; k++) { r += fabsf(X[j * MM + k]); c += fabsf(X[k * MM + j]); }
    rs[hh * MM + j] = r; cs[hh * MM + j] = c;
}
__global__ void pinv_scale_k(const float* __restrict__ rs, const float* __restrict__ cs,
                             float* __restrict__ scale)
{
    __shared__ float m1[256], m2[256];
    float a = -1e30f, b = -1e30f;
    for (int i = threadIdx.x; i < HEADS * MM; i += 256) { a = fmaxf(a, rs[i]); b = fmaxf(b, cs[i]); }
    m1[threadIdx.x] = a; m2[threadIdx.x] = b; __syncthreads();
    for (int s = 128; s > 0; s >>= 1) {
        if (threadIdx.x < s) {
            m1[threadIdx.x] = fmaxf(m1[threadIdx.x], m1[threadIdx.x + s]);
            m2[threadIdx.x] = fmaxf(m2[threadIdx.x], m2[threadIdx.x + s]);
        }
        __syncthreads();
    }
    if (threadIdx.x == 0) scale[0] = 1.f / (m1[0] * m2[0]);
}
__global__ void pinv_init_k(const float* __restrict__ a2, const float* __restrict__ scale,
                            bf16* __restrict__ zph, bf16* __restrict__ zpl,
                            bf16* __restrict__ zth, bf16* __restrict__ ztl)
{
    long i = (long)blockIdx.x * 256 + threadIdx.x;
    if (i >= (long)HEADS * MM * MM) return;
    float s = scale[0];
    long hb = i & ~65535L;
    int r = (int)((i >> 8) & 255), c = (int)(i & 255);
    float vt = a2[i] * s;
    float vp = a2[hb + ((long)c << 8) + r] * s;
    float hi, lo;
    split_bf(vt, hi, lo); zth[i] = __float2bfloat16(hi); ztl[i] = __float2bfloat16(lo);
    split_bf(vp, hi, lo); zph[i] = __float2bfloat16(hi); zpl[i] = __float2bfloat16(lo);
}

__global__ void vT_k(const bf16* __restrict__ qh, const bf16* __restrict__ ql_,
                     bf16* __restrict__ vth, bf16* __restrict__ vtl)
{
    __shared__ bf16 tile[32][33];
    int t0 = blockIdx.x * 32;
    int head = blockIdx.y >> 1;
    int lopart = blockIdx.y & 1;
    int d0 = blockIdx.z * 32;
    const bf16* src = (lopart ? ql_ : qh) + 1024 + head * 64 + d0;
    bf16* dst = (lopart ? vtl : vth) + (long)head * 64 * NP + (long)d0 * NP;
    int tx = threadIdx.x, ty = threadIdx.y;
    #pragma unroll
    for (int i = 0; i < 4; i++)
        tile[ty + 8 * i][tx] = src[(long)(t0 + ty + 8 * i) * QKVW + tx];
    __syncthreads();
    #pragma unroll
    for (int i = 0; i < 4; i++)
        dst[(long)(ty + 8 * i) * NP + t0 + tx] = tile[tx][ty + 8 * i];
}

__global__ void conv_add_k(const bf16* __restrict__ qh, const bf16* __restrict__ ql_,
                           const float* __restrict__ rw, const float* __restrict__ attnf,
                           bf16* __restrict__ ah, bf16* __restrict__ al)
{
    int t = blockIdx.x, c = threadIdx.x;
    int hh = c >> 6;
    float acc = attnf[(long)t * C + c];
    #pragma unroll
    for (int k = 0; k < 33; k++) {
        int tt = t + k - 16;
        if ((unsigned)tt < (unsigned)NP)
            acc += pairval(qh, ql_, (long)tt * QKVW + 1024 + c) * rw[hh * 33 + k];
    }
    float hi, lo; split_bf(acc, hi, lo);
    long o = (long)t * C + c;
    ah[o] = __float2bfloat16(hi);
    al[o] = __float2bfloat16(lo);
}

__global__ void ppeg_k(const float* __restrict__ h, float* __restrict__ h2,
                       const float* __restrict__ w7, const float* __restrict__ b7,
                       const float* __restrict__ w5, const float* __restrict__ b5,
                       const float* __restrict__ w3, const float* __restrict__ b3)
{
    int x = blockIdx.x, y = blockIdx.y, c = threadIdx.x;
    if (x == 0 && y == 0) h2[c] = h[c];
    float acc = h[(long)(1 + y * HW + x) * C + c];
    #pragma unroll
    for (int ky = 0; ky < 7; ky++) {
        int yy = y + ky - 3; if (yy < 0 || yy >= HW) continue;
        #pragma unroll
        for (int kx = 0; kx < 7; kx++) {
            int xx = x + kx - 3; if (xx < 0 || xx >= HW) continue;
            acc += h[(long)(1 + yy * HW + xx) * C + c] * w7[c * 49 + ky * 7 + kx];
        }
    }
    #pragma unroll
    for (int ky = 0; ky < 5; ky++) {
        int yy = y + ky - 2; if (yy < 0 || yy >= HW) continue;
        #pragma unroll
        for (int kx = 0; kx < 5; kx++) {
            int xx = x + kx - 2; if (xx < 0 || xx >= HW) continue;
            acc += h[(long)(1 + yy * HW + xx) * C + c] * w5[c * 25 + ky * 5 + kx];
        }
    }
    #pragma unroll
    for (int ky = 0; ky < 3; ky++) {
        int yy = y + ky - 1; if (yy < 0 || yy >= HW) continue;
        #pragma unroll
        for (int kx = 0; kx < 3; kx++) {
            int xx = x + kx - 1; if (xx < 0 || xx >= HW) continue;
            acc += h[(long)(1 + yy * HW + xx) * C + c] * w3[c * 9 + ky * 3 + kx];
        }
    }
    acc += b7[c] + b5[c] + b3[c];
    h2[(long)(1 + y * HW + x) * C + c] = acc;
}

// ================= host orchestration =================
struct Ptrs {
    float *h, *h2, *a2, *attn, *outl, *rowsum, *colsum, *fm, *fs, *scale;
    bf16 *xph, *xpl, *qkvh, *qkvl, *qlh, *qll, *klh, *kll,
         *a2h, *a2l, *zh, *zl, *zth, *ztl, *z2h, *z2l, *z2th, *z2tl,
         *xzh, *xzl, *tah, *tal, *tbh, *tbl, *vth, *vtl,
         *a3h, *a3l, *Wth, *Wtl, *ath, *atl,
         *w1ah, *w1al, *w2ah, *w2al, *w1bh, *w1bl, *w2bh, *w2bl;
};
#define GSYM(f, s) cudaGetSymbolAddress((void**)&p.f, s)
static void get_ptrs(Ptrs& p)
{
    GSYM(h, g_h); GSYM(h2, g_h2); GSYM(a2, g_a2);
    GSYM(attn, g_attn); GSYM(outl, g_outl);
    GSYM(rowsum, g_rowsum); GSYM(colsum, g_colsum);
    GSYM(fm, g_fm); GSYM(fs, g_fs); GSYM(scale, g_scale);
    GSYM(xph, g_xph); GSYM(xpl, g_xpl); GSYM(qkvh, g_qkvh); GSYM(qkvl, g_qkvl);
    GSYM(qlh, g_qlh); GSYM(qll, g_qll); GSYM(klh, g_klh); GSYM(kll, g_kll);
    GSYM(a2h, g_a2h); GSYM(a2l, g_a2l);
    GSYM(zh, g_zh); GSYM(zl, g_zl); GSYM(zth, g_zth); GSYM(ztl, g_ztl);
    GSYM(z2h, g_z2h); GSYM(z2l, g_z2l); GSYM(z2th, g_z2th); GSYM(z2tl, g_z2tl);
    GSYM(xzh, g_xzh); GSYM(xzl, g_xzl);
    GSYM(tah, g_tah); GSYM(tal, g_tal); GSYM(tbh, g_tbh); GSYM(tbl, g_tbl);
    GSYM(vth, g_vth); GSYM(vtl, g_vtl); GSYM(a3h, g_a3h); GSYM(a3l, g_a3l);
    GSYM(Wth, g_Wth); GSYM(Wtl, g_Wtl); GSYM(ath, g_ath); GSYM(atl, g_atl);
    GSYM(w1ah, g_w1ah); GSYM(w1al, g_w1al); GSYM(w2ah, g_w2ah); GSYM(w2al, g_w2al);
    GSYM(w1bh, g_w1bh); GSYM(w1bl, g_w1bl); GSYM(w2bh, g_w2bh); GSYM(w2bl, g_w2bl);
}

static void nystrom_tail(Ptrs& p, float* h_io,
                         const bf16* w2h, const bf16* w2l,
                         const float* b_out, const float* res_w)
{
    const long MMh = (long)MM * MM;

    landmarks_k<<<HEADS * MM, DH>>>(p.qkvh, p.qkvl, p.qlh, p.qll, p.klh, p.kll);
    vT_k<<<dim3(NP / 32, HEADS * 2, 2), dim3(32, 8)>>>(p.qkvh, p.qkvl, p.vth, p.vtl);

    { EpiOut e = epi0(); e.f = p.a2; e.falpha = 1.f; e.ldf = MM; e.sF = MMh;
      gemmP(p.qlh, p.qll, p.klh, p.kll, MM, MM, DH, DH, DH,
            (long)MM * DH, (long)MM * DH, HEADS, 1, e); }
    softmax256_k<<<(HEADS * MM + 7) / 8, dim3(32, 8)>>>(p.a2, p.a2, p.a2h, p.a2l, HEADS * MM);

    pinv_sums_k<<<HEADS, 256>>>(p.a2, p.rowsum, p.colsum);
    pinv_scale_k<<<1, 256>>>(p.rowsum, p.colsum, p.scale);
    pinv_init_k<<<(int)((HEADS * MMh + 255) / 256), 256>>>(p.a2, p.scale,
                                                           p.zh, p.zl, p.zth, p.ztl);
    bf16 *zch = p.zh, *zcl = p.zl, *zcth = p.zth, *zctl = p.ztl;
    bf16 *znh = p.z2h, *znl = p.z2l, *znth = p.z2th, *zntl = p.z2tl;
    for (int it = 0; it < 6; it++) {
        { EpiOut e = epi0();
          e.ph = p.xzh; e.pl = p.xzl; e.palpha = 1.f; e.ldp = MM; e.sP = MMh;
          e.th = p.tah; e.tl = p.tal; e.talpha = -1.f; e.tdiag = 7.f; e.ldt = MM; e.sT = MMh;
          gemmP(p.a2h, p.a2l, zcth, zctl, MM, MM, MM, MM, MM, MMh, MMh, HEADS, 1, e); }
        { EpiOut e = epi0();
          e.th = p.tbh; e.tl = p.tbl; e.talpha = -1.f; e.tdiag = 15.f; e.ldt = MM; e.sT = MMh;
          gemmP(p.xzh, p.xzl, p.tah, p.tal, MM, MM, MM, MM, MM, MMh, MMh, HEADS, 1, e); }
        { EpiOut e = epi0();
          e.th = p.tah; e.tl = p.tal; e.talpha = -1.f; e.tdiag = 13.f; e.ldt = MM; e.sT = MMh;
          gemmP(p.xzh, p.xzl, p.tbh, p.tbl, MM, MM, MM, MM, MM, MMh, MMh, HEADS, 1, e); }
        { EpiOut e = epi0();
          e.ph = znh; e.pl = znl; e.palpha = 0.25f; e.ldp = MM; e.sP = MMh;
          e.th = znth; e.tl = zntl; e.talpha = 0.25f; e.tdiag = 0.f; e.ldt = MM; e.sT = MMh;
          gemmP(zch, zcl, p.tah, p.tal, MM, MM, MM, MM, MM, MMh, MMh, HEADS, 1, e); }
        bf16* t;
        t = zch; zch = znh; znh = t;   t = zcl; zcl = znl; znl = t;
        t = zcth; zcth = znth; znth = t; t = zctl; zctl = zntl; zntl = t;
    }

    flash3_k<<<dim3(NSPLIT, 2, HEADS), 128, FL_SMEM>>>(
        p.qlh, p.qll, p.qkvh, p.qkvl, p.vth, p.vtl, p.outl, p.fm, p.fs);
    flash_merge_k<<<dim3(MM, HEADS), DH>>>(p.outl, p.fm, p.fs, p.a3h, p.a3l);

    { EpiOut e = epi0(); e.th = p.Wth; e.tl = p.Wtl; e.talpha = 1.f; e.tdiag = 0.f;
      e.ldt = MM; e.sT = (long)DH * MM;
      gemmP(zch, zcl, p.a3h, p.a3l, MM, DH, MM, MM, MM, MMh, (long)DH * MM, HEADS, 1, e); }

    fused_attn1_k<<<dim3(NP / 64, HEADS), 128, FA_SMEM>>>(
        p.qkvh, p.qkvl, p.klh, p.kll, p.Wth, p.Wtl, p.attn);

    conv_add_k<<<NP, C>>>(p.qkvh, p.qkvl, res_w, p.attn, p.ath, p.atl);

    { EpiOut e = epi0(); e.f = h_io; e.falpha = 1.f; e.ldf = C;
      e.resid = h_io; e.bias = b_out;
      gemmP(p.ath + (long)PADN * C, p.atl + (long)PADN * C, w2h, w2l,
            NH, C, C, C, C, 0, 0, 1, 1, e); }
}

extern "C" void kernel_launch(void* const* d_in, const int* in_sizes, int n_in,
                              void* d_out, int out_size)
{
    const float* features = (const float*)d_in[0];
    const float* cls      = (const float*)d_in[1];
    const float* ln1_g    = (const float*)d_in[2];
    const float* ln1_b    = (const float*)d_in[3];
    const float* qkv1_w   = (const float*)d_in[4];
    const float* out1_w   = (const float*)d_in[5];
    const float* out1_b   = (const float*)d_in[6];
    const float* res1_w   = (const float*)d_in[7];
    const float* pe_w7    = (const float*)d_in[8];
    const float* pe_b7    = (const float*)d_in[9];
    const float* pe_w5    = (const float*)d_in[10];
    const float* pe_b5    = (const float*)d_in[11];
    const float* pe_w3    = (const float*)d_in[12];
    const float* pe_b3    = (const float*)d_in[13];
    const float* ln2_g    = (const float*)d_in[14];
    const float* ln2_b    = (const float*)d_in[15];
    const float* qkv2_w   = (const float*)d_in[16];
    const float* out2_w   = (const float*)d_in[17];
    const float* out2_b   = (const float*)d_in[18];
    const float* res2_w   = (const float*)d_in[19];

    cudaFuncSetAttribute(gemm_p,  cudaFuncAttributeMaxDynamicSharedMemorySize, GP_SMEM);
    cudaFuncSetAttribute(gemm_p2, cudaFuncAttributeMaxDynamicSharedMemorySize, GP2_SMEM);
    cudaFuncSetAttribute(fused_attn1_k, cudaFuncAttributeMaxDynamicSharedMemorySize, FA_SMEM);
    cudaFuncSetAttribute(flash3_k, cudaFuncAttributeMaxDynamicSharedMemorySize, FL_SMEM);

    Ptrs p; get_ptrs(p);

    // launch order: build_h(1), wconv qkv1(2), ln_pad(3), qkv gemm(4) <- profiled
    build_h_k<<<(int)(((long)NH * C + 255) / 256), 256>>>(features, cls, p.h);
    wconvT_k<<<(QKVW * C + 255) / 256, 256>>>(qkv1_w, p.w1ah, p.w1al, C, QKVW);
    ln_pad_k<<<NP, 256>>>(p.h, p.xph, p.xpl, ln1_g, ln1_b);
    { EpiOut e = epi0(); e.ph = p.qkvh; e.pl = p.qkvl; e.palpha = 1.f; e.ldp = QKVW;
      gemmP(p.xph, p.xpl, p.w1ah, p.w1al, NP, QKVW, C, C, C, 0, 0, 1, 1, e); }

    // remaining weight converts
    wconvT_k<<<(C * C + 255) / 256, 256>>>(out1_w, p.w2ah, p.w2al, C, C);
    wconvT_k<<<(QKVW * C + 255) / 256, 256>>>(qkv2_w, p.w1bh, p.w1bl, C, QKVW);
    wconvT_k<<<(C * C + 255) / 256, 256>>>(out2_w, p.w2bh, p.w2bl, C, C);

    // layer 1 tail (after its qkv)
    nystrom_tail(p, p.h, p.w2ah, p.w2al, out1_b, res1_w);

    // PPEG
    ppeg_k<<<dim3(HW, HW), C>>>(p.h, p.h2, pe_w7, pe_b7, pe_w5, pe_b5, pe_w3, pe_b3);

    // layer 2
    ln_pad_k<<<NP, 256>>>(p.h2, p.xph, p.xpl, ln2_g, ln2_b);
    { EpiOut e = epi0(); e.ph = p.qkvh; e.pl = p.qkvl; e.palpha = 1.f; e.ldp = QKVW;
      gemmP(p.xph, p.xpl, p.w1bh, p.w1bl, NP, QKVW, C, C, C, 0, 0, 1, 1, e); }
    nystrom_tail(p, p.h2, p.w2bh, p.w2bl, out2_b, res2_w);

    cudaMemcpyAsync(d_out, p.h2, (size_t)out_size * sizeof(float),
                    cudaMemcpyDeviceToDevice);
}

// round 11
// speedup vs baseline: 1.3271x; 1.2567x over previous
#include <cuda_runtime.h>
#include <cuda_bf16.h>
#include <math.h>
#include <stdint.h>

typedef __nv_bfloat16 bf16;

// ---------------- problem constants ----------------
#define NH    22501
#define NFEAT 22400
#define HW    150
#define C     512
#define NP    22528
#define PADN  27
#define HEADS 8
#define DH    64
#define MM    256
#define LL    88
#define QKVW  1536
#define NSPLIT 8

// ---------------- fp32 scratch ----------------
__device__ float g_h   [(long)NH*C];
__device__ float g_h2  [(long)NH*C];
__device__ float g_a2  [HEADS*MM*MM];
__device__ float g_attn[(long)NP*C];
__device__ float g_outl[(long)NH*C];
__device__ float g_rowsum[HEADS*MM];
__device__ float g_colsum[HEADS*MM];
__device__ float g_fm[NSPLIT*HEADS*MM];
__device__ float g_fs[NSPLIT*HEADS*MM];
__device__ float g_scale[1];

// ---------------- bf16 hi/lo pair scratch ----------------
__device__ bf16 g_xph[(long)NP*C],     g_xpl[(long)NP*C];
__device__ bf16 g_qkvh[(long)NP*QKVW], g_qkvl[(long)NP*QKVW];
__device__ bf16 g_qlh[HEADS*MM*DH],    g_qll[HEADS*MM*DH];
__device__ bf16 g_klh[HEADS*MM*DH],    g_kll[HEADS*MM*DH];
__device__ bf16 g_a2h[HEADS*MM*MM],    g_a2l[HEADS*MM*MM];
__device__ bf16 g_zh [HEADS*MM*MM], g_zl [HEADS*MM*MM];
__device__ bf16 g_zth[HEADS*MM*MM], g_ztl[HEADS*MM*MM];
__device__ bf16 g_z2h[HEADS*MM*MM], g_z2l[HEADS*MM*MM];
__device__ bf16 g_z2th[HEADS*MM*MM], g_z2tl[HEADS*MM*MM];
__device__ bf16 g_xzh[HEADS*MM*MM], g_xzl[HEADS*MM*MM];
__device__ bf16 g_tah[HEADS*MM*MM], g_tal[HEADS*MM*MM];
__device__ bf16 g_tbh[HEADS*MM*MM], g_tbl[HEADS*MM*MM];
__device__ bf16 g_vth[(long)HEADS*DH*NP], g_vtl[(long)HEADS*DH*NP];
__device__ bf16 g_a3h[HEADS*DH*MM],    g_a3l[HEADS*DH*MM];
__device__ bf16 g_Wth[HEADS*DH*MM],    g_Wtl[HEADS*DH*MM];
__device__ bf16 g_ath[(long)NP*C],     g_atl[(long)NP*C];
__device__ bf16 g_w1ah[(long)QKVW*C],  g_w1al[(long)QKVW*C];
__device__ bf16 g_w2ah[(long)C*C],     g_w2al[(long)C*C];
__device__ bf16 g_w1bh[(long)QKVW*C],  g_w1bl[(long)QKVW*C];
__device__ bf16 g_w2bh[(long)C*C],     g_w2bl[(long)C*C];

// ---------------- small device helpers ----------------
__device__ __forceinline__ uint32_t smem_to_u32(const void* p) {
    uint32_t a;
    asm("{ .reg .u64 t; cvta.to.shared.u64 t, %1; cvt.u32.u64 %0, t; }"
        : "=r"(a) : "l"(p));
    return a;
}
__device__ __forceinline__ void ldsm4(uint32_t addr, uint32_t& r0, uint32_t& r1,
                                      uint32_t& r2, uint32_t& r3)
{
    asm volatile("ldmatrix.sync.aligned.m8n8.x4.shared.b16 {%0,%1,%2,%3}, [%4];"
                 : "=r"(r0), "=r"(r1), "=r"(r2), "=r"(r3) : "r"(addr));
}
__device__ __forceinline__ void mma_bf16(float* c, const uint32_t* a,
                                         uint32_t b0, uint32_t b1)
{
    asm volatile("mma.sync.aligned.m16n8k16.row.col.f32.bf16.bf16.f32 "
                 "{%0,%1,%2,%3},{%4,%5,%6,%7},{%8,%9},{%0,%1,%2,%3};"
                 : "+f"(c[0]), "+f"(c[1]), "+f"(c[2]), "+f"(c[3])
                 : "r"(a[0]), "r"(a[1]), "r"(a[2]), "r"(a[3]), "r"(b0), "r"(b1));
}
__device__ __forceinline__ void cpa16(uint32_t dst, const void* src, int sz)
{
    asm volatile("cp.async.cg.shared.global [%0], [%1], 16, %2;"
                 :: "r"(dst), "l"(src), "r"(sz));
}
__device__ __forceinline__ uint32_t pack2(float a, float b)   // a->low, b->high
{
    uint32_t r;
    asm("cvt.rn.bf16x2.f32 %0, %1, %2;" : "=r"(r) : "f"(b), "f"(a));
    return r;
}
__device__ __forceinline__ void split_bf(float x, float& hi, float& lo)
{
    hi = __bfloat162float(__float2bfloat16(x));
    lo = x - hi;
}
__device__ __forceinline__ float pairval(const bf16* h, const bf16* l, long i)
{
    return __bfloat162float(h[i]) + __bfloat162float(l[i]);
}

struct EpiOut {
    float* f; float falpha; int ldf; long sF;
    bf16 *ph, *pl; float palpha; int ldp; long sP;
    bf16 *th, *tl; float talpha, tdiag; int ldt; long sT;
    const float* resid;
    const float* bias;
};

// shared epilogue writer for one 2-value fragment slice
__device__ __forceinline__ void epi_write(const EpiOut& ep, float* F,
                                          bf16* Ph, bf16* Pl, bf16* Th, bf16* Tl,
                                          int gr, int gc, float va, float vb)
{
    if (F) {
        float o0 = ep.falpha * va, o1 = ep.falpha * vb;
        if (ep.bias)  { o0 += ep.bias[gc]; o1 += ep.bias[gc + 1]; }
        if (ep.resid) {
            o0 += ep.resid[(long)gr * ep.ldf + gc];
            o1 += ep.resid[(long)gr * ep.ldf + gc + 1];
        }
        *reinterpret_cast<float2*>(F + (long)gr * ep.ldf + gc) = make_float2(o0, o1);
    }
    if (Ph) {
        float s0 = ep.palpha * va, s1 = ep.palpha * vb;
        float h0, l0, h1, l1;
        split_bf(s0, h0, l0); split_bf(s1, h1, l1);
        *reinterpret_cast<uint32_t*>(Ph + (long)gr * ep.ldp + gc) = pack2(h0, h1);
        *reinterpret_cast<uint32_t*>(Pl + (long)gr * ep.ldp + gc) = pack2(l0, l1);
    }
    if (Th) {
        #pragma unroll
        for (int j = 0; j < 2; j++) {
            int cc = gc + j;
            float v = (j == 0) ? va : vb;
            float s = ep.talpha * v + ((gr == cc) ? ep.tdiag : 0.f);
            float hi, lo; split_bf(s, hi, lo);
            Th[(long)cc * ep.ldt + gr] = __float2bfloat16(hi);
            Tl[(long)cc * ep.ldt + gr] = __float2bfloat16(lo);
        }
    }
}

// =======================================================================
// gemm_p: 128x64x32 tile, 3-stage, 8 warps (4m x 2n), warp 32x32.
// Used for small-M batched GEMMs (pinv / a2 / W).
// =======================================================================
#define RS      80
#define AH_OFF  0
#define AL_OFF  10240
#define BH_OFF  20480
#define BL_OFF  25600
#define STAGE   30720
#define GP_SMEM (3 * STAGE)

__global__ void __launch_bounds__(256, 2)
gemm_p(const bf16* __restrict__ Ah, const bf16* __restrict__ Al,
       const bf16* __restrict__ Bh, const bf16* __restrict__ Bl,
       int M, int K, int lda, int ldb, long sA, long sB,
       EpiOut ep, int ksplit)
{
    extern __shared__ __align__(16) char sm[];
    const uint32_t sb0 = smem_to_u32(sm);
    const int tid = threadIdx.x, warp = tid >> 5, lane = tid & 31;
    const int wm = warp & 3, wn = warp >> 2;

    const int z = blockIdx.z;
    const int batch = z / ksplit;
    Ah += (long)batch * sA;  Al += (long)batch * sA;
    Bh += (long)batch * sB;  Bl += (long)batch * sB;

    const int row0 = blockIdx.y * 128, col0 = blockIdx.x * 64;
    const int nch = K >> 5;

    float acc[2][4][4];
    #pragma unroll
    for (int i = 0; i < 2; i++)
        #pragma unroll
        for (int j = 0; j < 4; j++)
            #pragma unroll
            for (int q = 0; q < 4; q++) acc[i][j][q] = 0.f;

    auto issue = [&](int it) {
        const int stg = it % 3;
        const uint32_t sb = sb0 + stg * STAGE;
        const int kc = it * 32;
        #pragma unroll
        for (int rep = 0; rep < 2; rep++) {
            int c = tid + rep * 256;
            int row = c >> 2, seg = c & 3;
            int gm = row0 + row;
            long go = (long)gm * lda + kc + seg * 8;
            int sz = (gm < M) ? 16 : 0;
            cpa16(sb + AH_OFF + row * RS + seg * 16, Ah + go, sz);
            cpa16(sb + AL_OFF + row * RS + seg * 16, Al + go, sz);
        }
        {
            int n = tid >> 2, seg = tid & 3;
            long go = (long)(col0 + n) * ldb + kc + seg * 8;
            cpa16(sb + BH_OFF + n * RS + seg * 16, Bh + go, 16);
            cpa16(sb + BL_OFF + n * RS + seg * 16, Bl + go, 16);
        }
        asm volatile("cp.async.commit_group;");
    };

    const int rsel = (lane & 7) + ((lane >> 3) & 1) * 8;
    const int ksel = ((lane >> 4) & 1) * 16;
    auto do_mma = [&](int stg) {
        uint32_t sb = sb0 + stg * STAGE;
        #pragma unroll
        for (int kk = 0; kk < 2; kk++) {
            uint32_t ah[2][4], al[2][4];
            #pragma unroll
            for (int mt = 0; mt < 2; mt++) {
                uint32_t ad = sb + AH_OFF + (wm * 32 + mt * 16 + rsel) * RS + kk * 32 + ksel;
                ldsm4(ad, ah[mt][0], ah[mt][1], ah[mt][2], ah[mt][3]);
                ldsm4(ad + (AL_OFF - AH_OFF), al[mt][0], al[mt][1], al[mt][2], al[mt][3]);
            }
            #pragma unroll
            for (int np = 0; np < 2; np++) {
                uint32_t bd = sb + BH_OFF + (wn * 32 + np * 16 + rsel) * RS + kk * 32 + ksel;
                uint32_t q0, q1, q2, q3, r0, r1, r2, r3;
                ldsm4(bd, q0, q1, q2, q3);
                ldsm4(bd + (BL_OFF - BH_OFF), r0, r1, r2, r3);
                #pragma unroll
                for (int mt = 0; mt < 2; mt++) {
                    mma_bf16(acc[mt][2*np],   ah[mt], q0, q2);
                    mma_bf16(acc[mt][2*np],   ah[mt], r0, r2);
                    mma_bf16(acc[mt][2*np],   al[mt], q0, q2);
                    mma_bf16(acc[mt][2*np+1], ah[mt], q1, q3);
                    mma_bf16(acc[mt][2*np+1], ah[mt], r1, r3);
                    mma_bf16(acc[mt][2*np+1], al[mt], q1, q3);
                }
            }
        }
    };

    issue(0);
    if (nch > 1) issue(1);
    for (int it = 0; it < nch; it++) {
        if (it + 1 < nch) asm volatile("cp.async.wait_group 1;");
        else              asm volatile("cp.async.wait_group 0;");
        __syncthreads();
        if (it + 2 < nch) issue(it + 2);
        do_mma(it % 3);
    }

    const int er = lane >> 2, eq = lane & 3;
    float* F  = ep.f  ? ep.f  + (long)z     * ep.sF : (float*)0;
    bf16* Ph  = ep.ph ? ep.ph + (long)batch * ep.sP : (bf16*)0;
    bf16* Pl  = ep.pl ? ep.pl + (long)batch * ep.sP : (bf16*)0;
    bf16* Th  = ep.th ? ep.th + (long)batch * ep.sT : (bf16*)0;
    bf16* Tl  = ep.tl ? ep.tl + (long)batch * ep.sT : (bf16*)0;

    #pragma unroll
    for (int mt = 0; mt < 2; mt++)
        #pragma unroll
        for (int nt = 0; nt < 4; nt++) {
            int gr0 = row0 + wm * 32 + mt * 16 + er;
            int gc  = col0 + wn * 32 + nt * 8 + 2 * eq;
            #pragma unroll
            for (int half = 0; half < 2; half++) {
                int gr = gr0 + 8 * half;
                if (gr >= M) continue;
                epi_write(ep, F, Ph, Pl, Th, Tl, gr, gc,
                          acc[mt][nt][2 * half], acc[mt][nt][2 * half + 1]);
            }
        }
}

// =======================================================================
// gemm_p2: 256x64x32 tile, 2-stage, 8 warps (4m x 2n), warp 64x32.
// Used for big-M single-batch GEMMs.
// =======================================================================
#define P2_AH   0
#define P2_AL   20480
#define P2_BH   40960
#define P2_BL   46080
#define P2_STG  51200
#define GP2_SMEM (2 * P2_STG)

__global__ void __launch_bounds__(256, 2)
gemm_p2(const bf16* __restrict__ Ah, const bf16* __restrict__ Al,
        const bf16* __restrict__ Bh, const bf16* __restrict__ Bl,
        int M, int K, int lda, int ldb,
        EpiOut ep)
{
    extern __shared__ __align__(16) char sm[];
    const uint32_t sb0 = smem_to_u32(sm);
    const int tid = threadIdx.x, warp = tid >> 5, lane = tid & 31;
    const int wm = warp & 3, wn = warp >> 2;

    const int row0 = blockIdx.y * 256, col0 = blockIdx.x * 64;
    const int nch = K >> 5;

    float acc[4][4][4];
    #pragma unroll
    for (int i = 0; i < 4; i++)
        #pragma unroll
        for (int j = 0; j < 4; j++)
            #pragma unroll
            for (int q = 0; q < 4; q++) acc[i][j][q] = 0.f;

    auto issue = [&](int it) {
        const uint32_t sb = sb0 + (it & 1) * P2_STG;
        const int kc = it * 32;
        #pragma unroll
        for (int rep = 0; rep < 4; rep++) {
            int c = tid + rep * 256;
            int row = c >> 2, seg = c & 3;
            int gm = row0 + row;
            long go = (long)gm * lda + kc + seg * 8;
            int sz = (gm < M) ? 16 : 0;
            cpa16(sb + P2_AH + row * RS + seg * 16, Ah + go, sz);
            cpa16(sb + P2_AL + row * RS + seg * 16, Al + go, sz);
        }
        {
            int n = tid >> 2, seg = tid & 3;
            long go = (long)(col0 + n) * ldb + kc + seg * 8;
            cpa16(sb + P2_BH + n * RS + seg * 16, Bh + go, 16);
            cpa16(sb + P2_BL + n * RS + seg * 16, Bl + go, 16);
        }
        asm volatile("cp.async.commit_group;");
    };

    const int rsel = (lane & 7) + ((lane >> 3) & 1) * 8;
    const int ksel = ((lane >> 4) & 1) * 16;
    auto do_mma = [&](int stg) {
        uint32_t sb = sb0 + stg * P2_STG;
        #pragma unroll
        for (int kk = 0; kk < 2; kk++) {
            uint32_t ah[4][4], al[4][4];
            #pragma unroll
            for (int mt = 0; mt < 4; mt++) {
                uint32_t ad = sb + P2_AH + (wm * 64 + mt * 16 + rsel) * RS + kk * 32 + ksel;
                ldsm4(ad, ah[mt][0], ah[mt][1], ah[mt][2], ah[mt][3]);
                ldsm4(ad + (P2_AL - P2_AH), al[mt][0], al[mt][1], al[mt][2], al[mt][3]);
            }
            #pragma unroll
            for (int np = 0; np < 2; np++) {
                uint32_t bd = sb + P2_BH + (wn * 32 + np * 16 + rsel) * RS + kk * 32 + ksel;
                uint32_t q0, q1, q2, q3, r0, r1, r2, r3;
                ldsm4(bd, q0, q1, q2, q3);
                ldsm4(bd + (P2_BL - P2_BH), r0, r1, r2, r3);
                #pragma unroll
                for (int mt = 0; mt < 4; mt++) {
                    mma_bf16(acc[mt][2*np],   ah[mt], q0, q2);
                    mma_bf16(acc[mt][2*np],   ah[mt], r0, r2);
                    mma_bf16(acc[mt][2*np],   al[mt], q0, q2);
                    mma_bf16(acc[mt][2*np+1], ah[mt], q1, q3);
                    mma_bf16(acc[mt][2*np+1], ah[mt], r1, r3);
                    mma_bf16(acc[mt][2*np+1], al[mt], q1, q3);
                }
            }
        }
    };

    issue(0);
    for (int it = 0; it < nch; it++) {
        if (it + 1 < nch) { issue(it + 1); asm volatile("cp.async.wait_group 1;"); }
        else              { asm volatile("cp.async.wait_group 0;"); }
        __syncthreads();
        do_mma(it & 1);
        __syncthreads();
    }

    const int er = lane >> 2, eq = lane & 3;
    float* F  = ep.f;
    bf16* Ph  = ep.ph;  bf16* Pl = ep.pl;
    bf16* Th  = ep.th;  bf16* Tl = ep.tl;

    #pragma unroll
    for (int mt = 0; mt < 4; mt++)
        #pragma unroll
        for (int nt = 0; nt < 4; nt++) {
            int gr0 = row0 + wm * 64 + mt * 16 + er;
            int gc  = col0 + wn * 32 + nt * 8 + 2 * eq;
            #pragma unroll
            for (int half = 0; half < 2; half++) {
                int gr = gr0 + 8 * half;
                if (gr >= M) continue;
                epi_write(ep, F, Ph, Pl, Th, Tl, gr, gc,
                          acc[mt][nt][2 * half], acc[mt][nt][2 * half + 1]);
            }
        }
}

static EpiOut epi0() { EpiOut e{}; return e; }
static void gemmP(const bf16* Ah, const bf16* Al, const bf16* Bh, const bf16* Bl,
                  int M, int N, int K, int lda, int ldb, long sA, long sB,
                  int batch, int ksplit, EpiOut ep)
{
    if (batch == 1 && M >= 512) {
        dim3 g(N / 64, (M + 255) / 256, 1), b(256);
        gemm_p2<<<g, b, GP2_SMEM>>>(Ah, Al, Bh, Bl, M, K, lda, ldb, ep);
    } else {
        dim3 g(N / 64, (M + 127) / 128, batch * ksplit), b(256);
        gemm_p<<<g, b, GP_SMEM>>>(Ah, Al, Bh, Bl, M, K, lda, ldb, sA, sB, ep, ksplit);
    }
}

// =======================================================================
// flash-fused S3 path (unchanged)
// =======================================================================
#define FL_RS   144
#define FL_QH   0
#define FL_QL   18432
#define FL_K(b) (36864 + (b) * 18432)
#define FL_V(b) (73728 + (b) * 18432)
#define FL_PH   110592
#define FL_PL   129024
#define FL_SMEM 147456
#define FL_NCH  ((NP / NSPLIT) / 64)

__global__ void __launch_bounds__(128)
flash3_k(const bf16* __restrict__ qlh, const bf16* __restrict__ qll,
         const bf16* __restrict__ qkvh, const bf16* __restrict__ qkvl,
         const bf16* __restrict__ vth, const bf16* __restrict__ vtl,
         float* __restrict__ pO, float* __restrict__ pm, float* __restrict__ ps)
{
    extern __shared__ __align__(16) char sm[];
    const uint32_t sb = smem_to_u32(sm);
    const int tid = threadIdx.x, warp = tid >> 5, lane = tid & 31;
    const int split = blockIdx.x, rowHalf = blockIdx.y, head = blockIdx.z;
    const int tb0 = split * (NP / NSPLIT);

    const bf16* Qh = qlh + ((long)head * MM + rowHalf * 128) * DH;
    const bf16* Ql = qll + ((long)head * MM + rowHalf * 128) * DH;
    #pragma unroll
    for (int i = 0; i < 8; i++) {
        int s = tid + 128 * i;
        int r = s >> 3, seg = s & 7;
        long go = (long)r * DH + seg * 8;
        cpa16(sb + FL_QH + r * FL_RS + seg * 16, Qh + go, 16);
        cpa16(sb + FL_QL + r * FL_RS + seg * 16, Ql + go, 16);
    }

    const bf16* Kh = qkvh + head * DH + 512;
    const bf16* Kl = qkvl + head * DH + 512;
    const bf16* Vh = vth + (long)head * DH * NP;
    const bf16* Vl = vtl + (long)head * DH * NP;

    auto kissue = [&](int j) {
        int buf = j & 1;
        int tb = tb0 + j * 64;
        uint32_t kb = sb + FL_K(buf);
        uint32_t vb = sb + FL_V(buf);
        #pragma unroll
        for (int i = 0; i < 4; i++) {
            int s = tid + 128 * i;
            int r = s >> 3, seg = s & 7;
            long gk = (long)(tb + r) * QKVW + seg * 8;
            cpa16(kb + r * FL_RS + seg * 16, Kh + gk, 16);
            cpa16(kb + 9216 + r * FL_RS + seg * 16, Kl + gk, 16);
            long gv = (long)r * NP + tb + seg * 8;
            cpa16(vb + r * FL_RS + seg * 16, Vh + gv, 16);
            cpa16(vb + 9216 + r * FL_RS + seg * 16, Vl + gv, 16);
        }
        asm volatile("cp.async.commit_group;");
    };
    kissue(0);
    kissue(1);

    const int rsel = (lane & 7) + ((lane >> 3) & 1) * 8;
    const int ksel = ((lane >> 4) & 1) * 16;
    const int er = lane >> 2, eq = lane & 3;

    float m_run[4] = {-1e30f, -1e30f, -1e30f, -1e30f};
    float s_run[4] = {0.f, 0.f, 0.f, 0.f};
    float oacc[2][8][4];
    #pragma unroll
    for (int a = 0; a < 2; a++)
        #pragma unroll
        for (int b = 0; b < 8; b++)
            #pragma unroll
            for (int c = 0; c < 4; c++) oacc[a][b][c] = 0.f;

    for (int j = 0; j < FL_NCH; j++) {
        if (j + 1 < FL_NCH) asm volatile("cp.async.wait_group 1;");
        else                asm volatile("cp.async.wait_group 0;");
        __syncthreads();
        uint32_t kb = sb + FL_K(j & 1);
        uint32_t vb = sb + FL_V(j & 1);

        float sacc[2][8][4];
        #pragma unroll
        for (int a = 0; a < 2; a++)
            #pragma unroll
            for (int b = 0; b < 8; b++)
                #pragma unroll
                for (int c = 0; c < 4; c++) sacc[a][b][c] = 0.f;

        #pragma unroll
        for (int k16 = 0; k16 < 4; k16++) {
            uint32_t ah[2][4], al[2][4];
            #pragma unroll
            for (int mt = 0; mt < 2; mt++) {
                uint32_t ad = sb + FL_QH + (warp * 32 + mt * 16 + rsel) * FL_RS + k16 * 32 + ksel;
                ldsm4(ad, ah[mt][0], ah[mt][1], ah[mt][2], ah[mt][3]);
                ldsm4(ad + (FL_QL - FL_QH), al[mt][0], al[mt][1], al[mt][2], al[mt][3]);
            }
            #pragma unroll
            for (int n16 = 0; n16 < 4; n16++) {
                uint32_t bd = kb + (n16 * 16 + rsel) * FL_RS + k16 * 32 + ksel;
                uint32_t q0, q1, q2, q3, p0, p1, p2, p3;
                ldsm4(bd, q0, q1, q2, q3);
                ldsm4(bd + 9216, p0, p1, p2, p3);
                #pragma unroll
                for (int mt = 0; mt < 2; mt++) {
                    mma_bf16(sacc[mt][2*n16],   ah[mt], q0, q2);
                    mma_bf16(sacc[mt][2*n16],   ah[mt], p0, p2);
                    mma_bf16(sacc[mt][2*n16],   al[mt], q0, q2);
                    mma_bf16(sacc[mt][2*n16+1], ah[mt], q1, q3);
                    mma_bf16(sacc[mt][2*n16+1], ah[mt], p1, p3);
                    mma_bf16(sacc[mt][2*n16+1], al[mt], q1, q3);
                }
            }
        }

        #pragma unroll
        for (int mt = 0; mt < 2; mt++) {
            float cm0 = -1e30f, cm1 = -1e30f;
            #pragma unroll
            for (int nt = 0; nt < 8; nt++) {
                cm0 = fmaxf(cm0, fmaxf(sacc[mt][nt][0], sacc[mt][nt][1]));
                cm1 = fmaxf(cm1, fmaxf(sacc[mt][nt][2], sacc[mt][nt][3]));
            }
            #pragma unroll
            for (int o = 1; o <= 2; o <<= 1) {
                cm0 = fmaxf(cm0, __shfl_xor_sync(0xffffffffu, cm0, o));
                cm1 = fmaxf(cm1, __shfl_xor_sync(0xffffffffu, cm1, o));
            }
            float mn0 = fmaxf(m_run[2*mt],     cm0);
            float mn1 = fmaxf(m_run[2*mt + 1], cm1);
            float sc0 = __expf(m_run[2*mt]     - mn0);
            float sc1 = __expf(m_run[2*mt + 1] - mn1);
            m_run[2*mt] = mn0; m_run[2*mt + 1] = mn1;
            float ls0 = 0.f, ls1 = 0.f;
            int pr = warp * 32 + mt * 16 + er;
            #pragma unroll
            for (int nt = 0; nt < 8; nt++) {
                float e0 = __expf(sacc[mt][nt][0] - mn0);
                float e1 = __expf(sacc[mt][nt][1] - mn0);
                float e2 = __expf(sacc[mt][nt][2] - mn1);
                float e3 = __expf(sacc[mt][nt][3] - mn1);
                ls0 += e0 + e1; ls1 += e2 + e3;
                oacc[mt][nt][0] *= sc0; oacc[mt][nt][1] *= sc0;
                oacc[mt][nt][2] *= sc1; oacc[mt][nt][3] *= sc1;
                int col = nt * 8 + 2 * eq;
                float h0, l0, h1, l1;
                split_bf(e0, h0, l0); split_bf(e1, h1, l1);
                *reinterpret_cast<uint32_t*>(sm + FL_PH + pr * FL_RS + col * 2) = pack2(h0, h1);
                *reinterpret_cast<uint32_t*>(sm + FL_PL + pr * FL_RS + col * 2) = pack2(l0, l1);
                split_bf(e2, h0, l0); split_bf(e3, h1, l1);
                *reinterpret_cast<uint32_t*>(sm + FL_PH + (pr + 8) * FL_RS + col * 2) = pack2(h0, h1);
                *reinterpret_cast<uint32_t*>(sm + FL_PL + (pr + 8) * FL_RS + col * 2) = pack2(l0, l1);
            }
            #pragma unroll
            for (int o = 1; o <= 2; o <<= 1) {
                ls0 += __shfl_xor_sync(0xffffffffu, ls0, o);
                ls1 += __shfl_xor_sync(0xffffffffu, ls1, o);
            }
            s_run[2*mt]     = s_run[2*mt]     * sc0 + ls0;
            s_run[2*mt + 1] = s_run[2*mt + 1] * sc1 + ls1;
        }
        __syncthreads();

        #pragma unroll
        for (int k16 = 0; k16 < 4; k16++) {
            uint32_t ph[2][4], pl[2][4];
            #pragma unroll
            for (int mt = 0; mt < 2; mt++) {
                uint32_t ad = sb + FL_PH + (warp * 32 + mt * 16 + rsel) * FL_RS + k16 * 32 + ksel;
                ldsm4(ad, ph[mt][0], ph[mt][1], ph[mt][2], ph[mt][3]);
                ldsm4(ad + (FL_PL - FL_PH), pl[mt][0], pl[mt][1], pl[mt][2], pl[mt][3]);
            }
            #pragma unroll
            for (int n16 = 0; n16 < 4; n16++) {
                uint32_t bd = vb + (n16 * 16 + rsel) * FL_RS + k16 * 32 + ksel;
                uint32_t q0, q1, q2, q3, r0, r1, r2, r3;
                ldsm4(bd, q0, q1, q2, q3);
                ldsm4(bd + 9216, r0, r1, r2, r3);
                #pragma unroll
                for (int mt = 0; mt < 2; mt++) {
                    mma_bf16(oacc[mt][2*n16],   ph[mt], q0, q2);
                    mma_bf16(oacc[mt][2*n16],   ph[mt], r0, r2);
                    mma_bf16(oacc[mt][2*n16],   pl[mt], q0, q2);
                    mma_bf16(oacc[mt][2*n16+1], ph[mt], q1, q3);
                    mma_bf16(oacc[mt][2*n16+1], ph[mt], r1, r3);
                    mma_bf16(oacc[mt][2*n16+1], pl[mt], q1, q3);
                }
            }
        }
        __syncthreads();
        if (j + 2 < FL_NCH) kissue(j + 2);
    }

    const int base = (split * HEADS + head) * MM + rowHalf * 128;
    #pragma unroll
    for (int mt = 0; mt < 2; mt++) {
        int r0 = base + warp * 32 + mt * 16 + er;
        #pragma unroll
        for (int nt = 0; nt < 8; nt++) {
            int d = nt * 8 + 2 * eq;
            *reinterpret_cast<float2*>(pO + (long)r0 * DH + d) =
                make_float2(oacc[mt][nt][0], oacc[mt][nt][1]);
            *reinterpret_cast<float2*>(pO + (long)(r0 + 8) * DH + d) =
                make_float2(oacc[mt][nt][2], oacc[mt][nt][3]);
        }
        if (eq == 0) {
            pm[r0] = m_run[2*mt];     ps[r0] = s_run[2*mt];
            pm[r0 + 8] = m_run[2*mt + 1]; ps[r0 + 8] = s_run[2*mt + 1];
        }
    }
}

__global__ void flash_merge_k(const float* __restrict__ pO, const float* __restrict__ pm,
                              const float* __restrict__ ps,
                              bf16* __restrict__ oh, bf16* __restrict__ ol)
{
    int row = blockIdx.x, head = blockIdx.y, d = threadIdx.x;
    float mx = -1e30f;
    #pragma unroll
    for (int i = 0; i < NSPLIT; i++)
        mx = fmaxf(mx, pm[(i * HEADS + head) * MM + row]);
    float den = 0.f, acc = 0.f;
    #pragma unroll
    for (int i = 0; i < NSPLIT; i++) {
        int r = (i * HEADS + head) * MM + row;
        float w = __expf(pm[r] - mx);
        den += w * ps[r];
        acc += w * pO[(long)r * DH + d];
    }
    float v = acc / den;
    float hi, lo; split_bf(v, hi, lo);
    long o = ((long)head << 14) + d * MM + row;
    oh[o] = __float2bfloat16(hi);
    ol[o] = __float2bfloat16(lo);
}

// =======================================================================
// fused S1 -> softmax -> O1 (unchanged)
// =======================================================================
#define FA_RS1  144
#define FA_AH   0
#define FA_AL   9216
#define FA_BH   18432
#define FA_BL   55296
#define FA_PH   0
#define FA_PL   33792
#define FA_WS   67584
#define FA_WST  10240
#define FA_SMEM 98304

__global__ void __launch_bounds__(128)
fused_attn1_k(const bf16* __restrict__ qh, const bf16* __restrict__ ql_,
              const bf16* __restrict__ klh, const bf16* __restrict__ kll,
              const bf16* __restrict__ Wth, const bf16* __restrict__ Wtl,
              float* __restrict__ attn)
{
    extern __shared__ __align__(16) char sm[];
    const uint32_t sb = smem_to_u32(sm);
    const int tid = threadIdx.x, warp = tid >> 5, lane = tid & 31;
    const int row0 = blockIdx.x * 64;
    const int head = blockIdx.y;

    const bf16* qsh = qh  + (long)row0 * QKVW + head * DH;
    const bf16* qsl = ql_ + (long)row0 * QKVW + head * DH;
    #pragma unroll
    for (int i = 0; i < 4; i++) {
        int s = tid + 128 * i;
        int r = s >> 3, seg = s & 7;
        long go = (long)r * QKVW + seg * 8;
        cpa16(sb + FA_AH + r * FA_RS1 + seg * 16, qsh + go, 16);
        cpa16(sb + FA_AL + r * FA_RS1 + seg * 16, qsl + go, 16);
    }
    const bf16* ksh = klh + (long)head * MM * DH;
    const bf16* ksl = kll + (long)head * MM * DH;
    #pragma unroll
    for (int i = 0; i < 16; i++) {
        int s = tid + 128 * i;
        int r = s >> 3, seg = s & 7;
        long go = (long)r * DH + seg * 8;
        cpa16(sb + FA_BH + r * FA_RS1 + seg * 16, ksh + go, 16);
        cpa16(sb + FA_BL + r * FA_RS1 + seg * 16, ksl + go, 16);
    }
    asm volatile("cp.async.commit_group;");
    asm volatile("cp.async.wait_group 0;");
    __syncthreads();

    const int rsel = (lane & 7) + ((lane >> 3) & 1) * 8;
    const int ksel = ((lane >> 4) & 1) * 16;
    float sacc[32][4];
    #pragma unroll
    for (int i = 0; i < 32; i++)
        #pragma unroll
        for (int j = 0; j < 4; j++) sacc[i][j] = 0.f;

    #pragma unroll
    for (int k16 = 0; k16 < 4; k16++) {
        uint32_t ah[4], al[4];
        uint32_t ad = sb + FA_AH + (warp * 16 + rsel) * FA_RS1 + k16 * 32 + ksel;
        ldsm4(ad, ah[0], ah[1], ah[2], ah[3]);
        ldsm4(ad + (FA_AL - FA_AH), al[0], al[1], al[2], al[3]);
        #pragma unroll
        for (int n16 = 0; n16 < 16; n16++) {
            uint32_t bd = sb + FA_BH + (n16 * 16 + rsel) * FA_RS1 + k16 * 32 + ksel;
            uint32_t q0, q1, q2, q3, p0, p1, p2, p3;
            ldsm4(bd, q0, q1, q2, q3);
            ldsm4(bd + (FA_BL - FA_BH), p0, p1, p2, p3);
            mma_bf16(sacc[2*n16],   ah, q0, q2);
            mma_bf16(sacc[2*n16],   ah, p0, p2);
            mma_bf16(sacc[2*n16],   al, q0, q2);
            mma_bf16(sacc[2*n16+1], ah, q1, q3);
            mma_bf16(sacc[2*n16+1], ah, p1, p3);
            mma_bf16(sacc[2*n16+1], al, q1, q3);
        }
    }

    float mx0 = -1e30f, mx1 = -1e30f;
    #pragma unroll
    for (int nt = 0; nt < 32; nt++) {
        #pragma unroll
        for (int j = 0; j < 4; j++) sacc[nt][j] *= 0.125f;
        mx0 = fmaxf(mx0, fmaxf(sacc[nt][0], sacc[nt][1]));
        mx1 = fmaxf(mx1, fmaxf(sacc[nt][2], sacc[nt][3]));
    }
    #pragma unroll
    for (int o = 1; o <= 2; o <<= 1) {
        mx0 = fmaxf(mx0, __shfl_xor_sync(0xffffffffu, mx0, o));
        mx1 = fmaxf(mx1, __shfl_xor_sync(0xffffffffu, mx1, o));
    }
    float sm0 = 0.f, sm1 = 0.f;
    #pragma unroll
    for (int nt = 0; nt < 32; nt++) {
        sacc[nt][0] = __expf(sacc[nt][0] - mx0);
        sacc[nt][1] = __expf(sacc[nt][1] - mx0);
        sacc[nt][2] = __expf(sacc[nt][2] - mx1);
        sacc[nt][3] = __expf(sacc[nt][3] - mx1);
        sm0 += sacc[nt][0] + sacc[nt][1];
        sm1 += sacc[nt][2] + sacc[nt][3];
    }
    #pragma unroll
    for (int o = 1; o <= 2; o <<= 1) {
        sm0 += __shfl_xor_sync(0xffffffffu, sm0, o);
        sm1 += __shfl_xor_sync(0xffffffffu, sm1, o);
    }
    __syncthreads();

    const bf16* Wsh = Wth + (long)head * DH * MM;
    const bf16* Wsl = Wtl + (long)head * DH * MM;
    auto wissue = [&](int it) {
        int stg = it % 3;
        uint32_t base = sb + FA_WS + stg * FA_WST;
        #pragma unroll
        for (int i = 0; i < 2; i++) {
            int s = tid + 128 * i;
            int r = s >> 2, seg = s & 3;
            long go = (long)r * MM + it * 32 + seg * 8;
            cpa16(base + r * 80 + seg * 16, Wsh + go, 16);
            cpa16(base + 5120 + r * 80 + seg * 16, Wsl + go, 16);
        }
        asm volatile("cp.async.commit_group;");
    };
    wissue(0); wissue(1);

    {
        int pr = warp * 16 + (lane >> 2);
        int pc = (lane & 3) * 2;
        #pragma unroll
        for (int nt = 0; nt < 32; nt++) {
            int col = nt * 8 + pc;
            float h0, l0, h1, l1;
            split_bf(sacc[nt][0], h0, l0); split_bf(sacc[nt][1], h1, l1);
            *reinterpret_cast<uint32_t*>(sm + FA_PH + pr * 528 + col * 2) = pack2(h0, h1);
            *reinterpret_cast<uint32_t*>(sm + FA_PL + pr * 528 + col * 2) = pack2(l0, l1);
            split_bf(sacc[nt][2], h0, l0); split_bf(sacc[nt][3], h1, l1);
            *reinterpret_cast<uint32_t*>(sm + FA_PH + (pr + 8) * 528 + col * 2) = pack2(h0, h1);
            *reinterpret_cast<uint32_t*>(sm + FA_PL + (pr + 8) * 528 + col * 2) = pack2(l0, l1);
        }
    }
    __syncthreads();

    float oacc[8][4];
    #pragma unroll
    for (int i = 0; i < 8; i++)
        #pragma unroll
        for (int j = 0; j < 4; j++) oacc[i][j] = 0.f;

    for (int it = 0; it < 8; it++) {
        if (it < 7) asm volatile("cp.async.wait_group 1;");
        else        asm volatile("cp.async.wait_group 0;");
        __syncthreads();
        if (it + 2 < 8) wissue(it + 2);
        uint32_t wb = sb + FA_WS + (it % 3) * FA_WST;
        #pragma unroll
        for (int k16 = 0; k16 < 2; k16++) {
            int gk = it * 2 + k16;
            uint32_t ph[4], pl[4];
            uint32_t ad = sb + FA_PH + (warp * 16 + rsel) * 528 + gk * 32 + ksel;
            ldsm4(ad, ph[0], ph[1], ph[2], ph[3]);
            ldsm4(ad + (FA_PL - FA_PH), pl[0], pl[1], pl[2], pl[3]);
            #pragma unroll
            for (int n16 = 0; n16 < 4; n16++) {
                uint32_t bd = wb + (n16 * 16 + rsel) * 80 + k16 * 32 + ksel;
                uint32_t q0, q1, q2, q3, r0, r1, r2, r3;
                ldsm4(bd, q0, q1, q2, q3);
                ldsm4(bd + 5120, r0, r1, r2, r3);
                mma_bf16(oacc[2*n16],   ph, q0, q2);
                mma_bf16(oacc[2*n16],   ph, r0, r2);
                mma_bf16(oacc[2*n16],   pl, q0, q2);
                mma_bf16(oacc[2*n16+1], ph, q1, q3);
                mma_bf16(oacc[2*n16+1], ph, r1, r3);
                mma_bf16(oacc[2*n16+1], pl, q1, q3);
            }
        }
    }

    float inv0 = 1.f / sm0, inv1 = 1.f / sm1;
    int orow = row0 + warp * 16 + (lane >> 2);
    int ocol = head * DH + (lane & 3) * 2;
    #pragma unroll
    for (int nt = 0; nt < 8; nt++) {
        int col = ocol + nt * 8;
        *reinterpret_cast<float2*>(attn + (long)orow * C + col) =
            make_float2(oacc[nt][0] * inv0, oacc[nt][1] * inv0);
        *reinterpret_cast<float2*>(attn + (long)(orow + 8) * C + col) =
            make_float2(oacc[nt][2] * inv1, oacc[nt][3] * inv1);
    }
}

// =======================================================================
// auxiliary kernels
// =======================================================================

__global__ void wconvT_k(const float* __restrict__ w, bf16* __restrict__ th,
                         bf16* __restrict__ tl, int K, int N)
{
    int i = blockIdx.x * 256 + threadIdx.x;
    if (i >= N * K) return;
    int n = i / K, k = i - n * K;
    float v = w[(long)k * N + n];
    float hi, lo; split_bf(v, hi, lo);
    th[i] = __float2bfloat16(hi);
    tl[i] = __float2bfloat16(lo);
}

__global__ void build_h_k(const float* __restrict__ feat, const float* __restrict__ cls,
                          float* __restrict__ h)
{
    long i = (long)blockIdx.x * 256 + threadIdx.x;
    if (i >= (long)NH * C) return;
    long t = i >> 9;
    int  c = (int)(i & 511);
    float v;
    if (t == 0) v = cls[c];
    else {
        long r = t - 1;
        if (r >= NFEAT) r -= NFEAT;
        v = feat[r * C + c];
    }
    h[i] = v;
}

__global__ void ln_pad_k(const float* __restrict__ h, bf16* __restrict__ xh,
                         bf16* __restrict__ xl,
                         const float* __restrict__ g, const float* __restrict__ b)
{
    int t = blockIdx.x, c = threadIdx.x;
    long o = (long)t * C;
    if (t < PADN) {
        *reinterpret_cast<uint32_t*>(xh + o + 2 * c) = 0u;
        *reinterpret_cast<uint32_t*>(xl + o + 2 * c) = 0u;
        return;
    }
    const float* row = h + (long)(t - PADN) * C;
    float a1 = row[2 * c], a2 = row[2 * c + 1];
    __shared__ float red[256];
    red[c] = a1 + a2; __syncthreads();
    for (int s = 128; s > 0; s >>= 1) { if (c < s) red[c] += red[c + s]; __syncthreads(); }
    float mu = red[0] * (1.f / 512.f);
    __syncthreads();
    float d1 = a1 - mu, d2 = a2 - mu;
    red[c] = d1 * d1 + d2 * d2; __syncthreads();
    for (int s = 128; s > 0; s >>= 1) { if (c < s) red[c] += red[c + s]; __syncthreads(); }
    float inv = rsqrtf(red[0] * (1.f / 512.f) + 1e-5f);
    float v1 = d1 * inv * g[2 * c] + b[2 * c];
    float v2 = d2 * inv * g[2 * c + 1] + b[2 * c + 1];
    float h1, l1, h2, l2;
    split_bf(v1, h1, l1); split_bf(v2, h2, l2);
    *reinterpret_cast<uint32_t*>(xh + o + 2 * c) = pack2(h1, h2);
    *reinterpret_cast<uint32_t*>(xl + o + 2 * c) = pack2(l1, l2);
}

__global__ void landmarks_k(const bf16* __restrict__ qh, const bf16* __restrict__ ql_,
                            bf16* __restrict__ qlh, bf16* __restrict__ qll,
                            bf16* __restrict__ klh, bf16* __restrict__ kll)
{
    int d = threadIdx.x;
    int m = blockIdx.x & 255;
    int hh = blockIdx.x >> 8;
    long base = (long)(m * LL) * QKVW + hh * DH + d;
    float sq = 0.f, sk = 0.f;
    for (int j = 0; j < LL; j++) {
        long o = base + (long)j * QKVW;
        sq += pairval(qh, ql_, o);
        sk += pairval(qh, ql_, o + 512);
    }
    float vq = sq * (0.125f / (float)LL);
    float vk = sk * (1.f / (float)LL);
    int oi = (hh * MM + m) * DH + d;
    float hi, lo;
    split_bf(vq, hi, lo); qlh[oi] = __float2bfloat16(hi); qll[oi] = __float2bfloat16(lo);
    split_bf(vk, hi, lo); klh[oi] = __float2bfloat16(hi); kll[oi] = __float2bfloat16(lo);
}

__global__ void softmax256_k(const float* __restrict__ in, float* __restrict__ fout,
                             bf16* __restrict__ ph, bf16* __restrict__ pl, long nrows)
{
    long row = (long)blockIdx.x * 8 + threadIdx.y;
    if (row >= nrows) return;
    const float* r = in + row * 256;
    int lane = threadIdx.x;
    float v[8], m = -1e30f;
    #pragma unroll
    for (int i = 0; i < 8; i++) { v[i] = r[lane + 32 * i]; m = fmaxf(m, v[i]); }
    #pragma unroll
    for (int o = 16; o; o >>= 1) m = fmaxf(m, __shfl_xor_sync(0xffffffffu, m, o));
    float s = 0.f;
    #pragma unroll
    for (int i = 0; i < 8; i++) { v[i] = __expf(v[i] - m); s += v[i]; }
    #pragma unroll
    for (int o = 16; o; o >>= 1) s += __shfl_xor_sync(0xffffffffu, s, o);
    float inv = 1.f / s;
    #pragma unroll
    for (int i = 0; i < 8; i++) {
        float val = v[i] * inv;
        long o = row * 256 + lane + 32 * i;
        if (fout) fout[o] = val;
        float hi, lo; split_bf(val, hi, lo);
        ph[o] = __float2bfloat16(hi);
        pl[o] = __float2bfloat16(lo);
    }
}

__global__ void pinv_sums_k(const float* __restrict__ a2,
                            float* __restrict__ rs, float* __restrict__ cs)
{
    int hh = blockIdx.x, j = threadIdx.x;
    const float* X = a2 + (long)hh * MM * MM;
    float r = 0.f, c = 0.f;
    for (int k = 0; k < MM; k++) { r += fabsf(X[j * MM + k]); c += fabsf(X[k * MM + j]); }
    rs[hh * MM + j] = r; cs[hh * MM + j] = c;
}
__global__ void pinv_scale_k(const float* __restrict__ rs, const float* __restrict__ cs,
                             float* __restrict__ scale)
{
    __shared__ float m1[256], m2[256];
    float a = -1e30f, b = -1e30f;
    for (int i = threadIdx.x; i < HEADS * MM; i += 256) { a = fmaxf(a, rs[i]); b = fmaxf(b, cs[i]); }
    m1[threadIdx.x] = a; m2[threadIdx.x] = b; __syncthreads();
    for (int s = 128; s > 0; s >>= 1) {
        if (threadIdx.x < s) {
            m1[threadIdx.x] = fmaxf(m1[threadIdx.x], m1[threadIdx.x + s]);
            m2[threadIdx.x] = fmaxf(m2[threadIdx.x], m2[threadIdx.x + s]);
        }
        __syncthreads();
    }
    if (threadIdx.x == 0) scale[0] = 1.f / (m1[0] * m2[0]);
}
__global__ void pinv_init_k(const float* __restrict__ a2, const float* __restrict__ scale,
                            bf16* __restrict__ zph, bf16* __restrict__ zpl,
                            bf16* __restrict__ zth, bf16* __restrict__ ztl)
{
    long i = (long)blockIdx.x * 256 + threadIdx.x;
    if (i >= (long)HEADS * MM * MM) return;
    float s = scale[0];
    long hb = i & ~65535L;
    int r = (int)((i >> 8) & 255), c = (int)(i & 255);
    float vt = a2[i] * s;
    float vp = a2[hb + ((long)c << 8) + r] * s;
    float hi, lo;
    split_bf(vt, hi, lo); zth[i] = __float2bfloat16(hi); ztl[i] = __float2bfloat16(lo);
    split_bf(vp, hi, lo); zph[i] = __float2bfloat16(hi); zpl[i] = __float2bfloat16(lo);
}

__global__ void vT_k(const bf16* __restrict__ qh, const bf16* __restrict__ ql_,
                     bf16* __restrict__ vth, bf16* __restrict__ vtl)
{
    __shared__ bf16 tile[32][33];
    int t0 = blockIdx.x * 32;
    int head = blockIdx.y >> 1;
    int lopart = blockIdx.y & 1;
    int d0 = blockIdx.z * 32;
    const bf16* src = (lopart ? ql_ : qh) + 1024 + head * 64 + d0;
    bf16* dst = (lopart ? vtl : vth) + (long)head * 64 * NP + (long)d0 * NP;
    int tx = threadIdx.x, ty = threadIdx.y;
    #pragma unroll
    for (int i = 0; i < 4; i++)
        tile[ty + 8 * i][tx] = src[(long)(t0 + ty + 8 * i) * QKVW + tx];
    __syncthreads();
    #pragma unroll
    for (int i = 0; i < 4; i++)
        dst[(long)(ty + 8 * i) * NP + t0 + tx] = tile[tx][ty + 8 * i];
}

__global__ void conv_add_k(const bf16* __restrict__ qh, const bf16* __restrict__ ql_,
                           const float* __restrict__ rw, const float* __restrict__ attnf,
                           bf16* __restrict__ ah, bf16* __restrict__ al)
{
    int t = blockIdx.x, c = threadIdx.x;
    int hh = c >> 6;
    float acc = attnf[(long)t * C + c];
    #pragma unroll
    for (int k = 0; k < 33; k++) {
        int tt = t + k - 16;
        if ((unsigned)tt < (unsigned)NP)
            acc += pairval(qh, ql_, (long)tt * QKVW + 1024 + c) * rw[hh * 33 + k];
    }
    float hi, lo; split_bf(acc, hi, lo);
    long o = (long)t * C + c;
    ah[o] = __float2bfloat16(hi);
    al[o] = __float2bfloat16(lo);
}

// =======================================================================
// PPEG: smem-tiled, combined 49-tap stencil (w7+w5+w3+identity), one pass.
// Block: 16x16 pixels x 32 channels, 256 threads (8 warps; warp=2 pixel rows,
// lane=channel). Tile 22x22x32 fp32 in smem, channel-contiguous.
// =======================================================================
#define PT        16
#define PTH       22                           // PT + 6 halo
#define PG_TILE   (PTH * PTH * 32 * 4)         // 61952
#define PG_WOFF   PG_TILE
#define PG_W      (49 * 32 * 4)                // 6272
#define PG_BOFF   (PG_WOFF + PG_W)
#define PG_SMEM   (PG_BOFF + 32 * 4)

__global__ void __launch_bounds__(256, 2)
ppeg_k(const float* __restrict__ h, float* __restrict__ h2,
       const float* __restrict__ w7, const float* __restrict__ b7,
       const float* __restrict__ w5, const float* __restrict__ b5,
       const float* __restrict__ w3, const float* __restrict__ b3)
{
    extern __shared__ __align__(16) char smraw[];
    float* tile  = reinterpret_cast<float*>(smraw);
    float* wcomb = reinterpret_cast<float*>(smraw + PG_WOFF);
    float* biasc = reinterpret_cast<float*>(smraw + PG_BOFF);

    const int tid = threadIdx.x;
    const int cg = blockIdx.z;              // channel group 0..15
    const int x0 = blockIdx.x * PT, y0 = blockIdx.y * PT;
    const int cb = cg * 32;

    // cls passthrough (block (0,0) of each channel group)
    if (blockIdx.x == 0 && blockIdx.y == 0 && tid < 32)
        h2[cb + tid] = h[cb + tid];

    // ---- load input tile (halo zero-padded) ----
    {
        int c = tid & 31, slot = tid >> 5;      // 8 pixel slots
        for (int pix = slot; pix < PTH * PTH; pix += 8) {
            int py = pix / PTH, px = pix - py * PTH;
            int gy = y0 + py - 3, gx = x0 + px - 3;
            float v = 0.f;
            if ((unsigned)gy < (unsigned)HW && (unsigned)gx < (unsigned)HW)
                v = h[(long)(1 + gy * HW + gx) * C + cb + c];
            tile[pix * 32 + c] = v;
        }
    }

    // ---- build combined weights + bias ----
    for (int i = tid; i < 49 * 32; i += 256) {
        int k = i >> 5, c = i & 31;
        int dy = k / 7 - 3, dx = k % 7 - 3;
        float w = w7[(cb + c) * 49 + (dy + 3) * 7 + (dx + 3)];
        if (dy >= -2 && dy <= 2 && dx >= -2 && dx <= 2)
            w += w5[(cb + c) * 25 + (dy + 2) * 5 + (dx + 2)];
        if (dy >= -1 && dy <= 1 && dx >= -1 && dx <= 1)
            w += w3[(cb + c) * 9 + (dy + 1) * 3 + (dx + 1)];
        if (dy == 0 && dx == 0) w += 1.f;      // identity
        wcomb[i] = w;
    }
    if (tid < 32) biasc[tid] = b7[cb + tid] + b5[cb + tid] + b3[cb + tid];
    __syncthreads();

    // ---- compute: warp w handles pixel rows 2w, 2w+1; lane = channel ----
    const int warp = tid >> 5, c = tid & 31;
    float acc[32];
    #pragma unroll
    for (int p = 0; p < 32; p++) acc[p] = 0.f;

    for (int k = 0; k < 49; k++) {
        float wv = wcomb[k * 32 + c];
        int dy = k / 7, dx = k - (k / 7) * 7;
        int base = ((2 * warp + dy) * PTH + dx) * 32 + c;
        #pragma unroll
        for (int p = 0; p < 32; p++) {
            int py = p >> 4, px = p & 15;
            acc[p] += tile[base + (py * PTH + px) * 32] * wv;
        }
    }

    float bv = biasc[c];
    #pragma unroll
    for (int p = 0; p < 32; p++) {
        int y = y0 + 2 * warp + (p >> 4), x = x0 + (p & 15);
        if (y < HW && x < HW)
            h2[(long)(1 + y * HW + x) * C + cb + c] = acc[p] + bv;
    }
}

// ================= host orchestration =================
struct Ptrs {
    float *h, *h2, *a2, *attn, *outl, *rowsum, *colsum, *fm, *fs, *scale;
    bf16 *xph, *xpl, *qkvh, *qkvl, *qlh, *qll, *klh, *kll,
         *a2h, *a2l, *zh, *zl, *zth, *ztl, *z2h, *z2l, *z2th, *z2tl,
         *xzh, *xzl, *tah, *tal, *tbh, *tbl, *vth, *vtl,
         *a3h, *a3l, *Wth, *Wtl, *ath, *atl,
         *w1ah, *w1al, *w2ah, *w2al, *w1bh, *w1bl, *w2bh, *w2bl;
};
#define GSYM(f, s) cudaGetSymbolAddress((void**)&p.f, s)
static void get_ptrs(Ptrs& p)
{
    GSYM(h, g_h); GSYM(h2, g_h2); GSYM(a2, g_a2);
    GSYM(attn, g_attn); GSYM(outl, g_outl);
    GSYM(rowsum, g_rowsum); GSYM(colsum, g_colsum);
    GSYM(fm, g_fm); GSYM(fs, g_fs); GSYM(scale, g_scale);
    GSYM(xph, g_xph); GSYM(xpl, g_xpl); GSYM(qkvh, g_qkvh); GSYM(qkvl, g_qkvl);
    GSYM(qlh, g_qlh); GSYM(qll, g_qll); GSYM(klh, g_klh); GSYM(kll, g_kll);
    GSYM(a2h, g_a2h); GSYM(a2l, g_a2l);
    GSYM(zh, g_zh); GSYM(zl, g_zl); GSYM(zth, g_zth); GSYM(ztl, g_ztl);
    GSYM(z2h, g_z2h); GSYM(z2l, g_z2l); GSYM(z2th, g_z2th); GSYM(z2tl, g_z2tl);
    GSYM(xzh, g_xzh); GSYM(xzl, g_xzl);
    GSYM(tah, g_tah); GSYM(tal, g_tal); GSYM(tbh, g_tbh); GSYM(tbl, g_tbl);
    GSYM(vth, g_vth); GSYM(vtl, g_vtl); GSYM(a3h, g_a3h); GSYM(a3l, g_a3l);
    GSYM(Wth, g_Wth); GSYM(Wtl, g_Wtl); GSYM(ath, g_ath); GSYM(atl, g_atl);
    GSYM(w1ah, g_w1ah); GSYM(w1al, g_w1al); GSYM(w2ah, g_w2ah); GSYM(w2al, g_w2al);
    GSYM(w1bh, g_w1bh); GSYM(w1bl, g_w1bl); GSYM(w2bh, g_w2bh); GSYM(w2bl, g_w2bl);
}

static void nystrom_tail(Ptrs& p, float* h_io,
                         const bf16* w2h, const bf16* w2l,
                         const float* b_out, const float* res_w)
{
    const long MMh = (long)MM * MM;

    landmarks_k<<<HEADS * MM, DH>>>(p.qkvh, p.qkvl, p.qlh, p.qll, p.klh, p.kll);
    vT_k<<<dim3(NP / 32, HEADS * 2, 2), dim3(32, 8)>>>(p.qkvh, p.qkvl, p.vth, p.vtl);

    { EpiOut e = epi0(); e.f = p.a2; e.falpha = 1.f; e.ldf = MM; e.sF = MMh;
      gemmP(p.qlh, p.qll, p.klh, p.kll, MM, MM, DH, DH, DH,
            (long)MM * DH, (long)MM * DH, HEADS, 1, e); }
    softmax256_k<<<(HEADS * MM + 7) / 8, dim3(32, 8)>>>(p.a2, p.a2, p.a2h, p.a2l, HEADS * MM);

    pinv_sums_k<<<HEADS, 256>>>(p.a2, p.rowsum, p.colsum);
    pinv_scale_k<<<1, 256>>>(p.rowsum, p.colsum, p.scale);
    pinv_init_k<<<(int)((HEADS * MMh + 255) / 256), 256>>>(p.a2, p.scale,
                                                           p.zh, p.zl, p.zth, p.ztl);
    bf16 *zch = p.zh, *zcl = p.zl, *zcth = p.zth, *zctl = p.ztl;
    bf16 *znh = p.z2h, *znl = p.z2l, *znth = p.z2th, *zntl = p.z2tl;
    for (int it = 0; it < 6; it++) {
        { EpiOut e = epi0();
          e.ph = p.xzh; e.pl = p.xzl; e.palpha = 1.f; e.ldp = MM; e.sP = MMh;
          e.th = p.tah; e.tl = p.tal; e.talpha = -1.f; e.tdiag = 7.f; e.ldt = MM; e.sT = MMh;
          gemmP(p.a2h, p.a2l, zcth, zctl, MM, MM, MM, MM, MM, MMh, MMh, HEADS, 1, e); }
        { EpiOut e = epi0();
          e.th = p.tbh; e.tl = p.tbl; e.talpha = -1.f; e.tdiag = 15.f; e.ldt = MM; e.sT = MMh;
          gemmP(p.xzh, p.xzl, p.tah, p.tal, MM, MM, MM, MM, MM, MMh, MMh, HEADS, 1, e); }
        { EpiOut e = epi0();
          e.th = p.tah; e.tl = p.tal; e.talpha = -1.f; e.tdiag = 13.f; e.ldt = MM; e.sT = MMh;
          gemmP(p.xzh, p.xzl, p.tbh, p.tbl, MM, MM, MM, MM, MM, MMh, MMh, HEADS, 1, e); }
        { EpiOut e = epi0();
          e.ph = znh; e.pl = znl; e.palpha = 0.25f; e.ldp = MM; e.sP = MMh;
          e.th = znth; e.tl = zntl; e.talpha = 0.25f; e.tdiag = 0.f; e.ldt = MM; e.sT = MMh;
          gemmP(zch, zcl, p.tah, p.tal, MM, MM, MM, MM, MM, MMh, MMh, HEADS, 1, e); }
        bf16* t;
        t = zch; zch = znh; znh = t;   t = zcl; zcl = znl; znl = t;
        t = zcth; zcth = znth; znth = t; t = zctl; zctl = zntl; zntl = t;
    }

    flash3_k<<<dim3(NSPLIT, 2, HEADS), 128, FL_SMEM>>>(
        p.qlh, p.qll, p.qkvh, p.qkvl, p.vth, p.vtl, p.outl, p.fm, p.fs);
    flash_merge_k<<<dim3(MM, HEADS), DH>>>(p.outl, p.fm, p.fs, p.a3h, p.a3l);

    { EpiOut e = epi0(); e.th = p.Wth; e.tl = p.Wtl; e.talpha = 1.f; e.tdiag = 0.f;
      e.ldt = MM; e.sT = (long)DH * MM;
      gemmP(zch, zcl, p.a3h, p.a3l, MM, DH, MM, MM, MM, MMh, (long)DH * MM, HEADS, 1, e); }

    fused_attn1_k<<<dim3(NP / 64, HEADS), 128, FA_SMEM>>>(
        p.qkvh, p.qkvl, p.klh, p.kll, p.Wth, p.Wtl, p.attn);

    conv_add_k<<<NP, C>>>(p.qkvh, p.qkvl, res_w, p.attn, p.ath, p.atl);

    { EpiOut e = epi0(); e.f = h_io; e.falpha = 1.f; e.ldf = C;
      e.resid = h_io; e.bias = b_out;
      gemmP(p.ath + (long)PADN * C, p.atl + (long)PADN * C, w2h, w2l,
            NH, C, C, C, C, 0, 0, 1, 1, e); }
}

extern "C" void kernel_launch(void* const* d_in, const int* in_sizes, int n_in,
                              void* d_out, int out_size)
{
    const float* features = (const float*)d_in[0];
    const float* cls      = (const float*)d_in[1];
    const float* ln1_g    = (const float*)d_in[2];
    const float* ln1_b    = (const float*)d_in[3];
    const float* qkv1_w   = (const float*)d_in[4];
    const float* out1_w   = (const float*)d_in[5];
    const float* out1_b   = (const float*)d_in[6];
    const float* res1_w   = (const float*)d_in[7];
    const float* pe_w7    = (const float*)d_in[8];
    const float* pe_b7    = (const float*)d_in[9];
    const float* pe_w5    = (const float*)d_in[10];
    const float* pe_b5    = (const float*)d_in[11];
    const float* pe_w3    = (const float*)d_in[12];
    const float* pe_b3    = (const float*)d_in[13];
    const float* ln2_g    = (const float*)d_in[14];
    const float* ln2_b    = (const float*)d_in[15];
    const float* qkv2_w   = (const float*)d_in[16];
    const float* out2_w   = (const float*)d_in[17];
    const float* out2_b   = (const float*)d_in[18];
    const float* res2_w   = (const float*)d_in[19];

    cudaFuncSetAttribute(gemm_p,  cudaFuncAttributeMaxDynamicSharedMemorySize, GP_SMEM);
    cudaFuncSetAttribute(gemm_p2, cudaFuncAttributeMaxDynamicSharedMemorySize, GP2_SMEM);
    cudaFuncSetAttribute(fused_attn1_k, cudaFuncAttributeMaxDynamicSharedMemorySize, FA_SMEM);
    cudaFuncSetAttribute(flash3_k, cudaFuncAttributeMaxDynamicSharedMemorySize, FL_SMEM);
    cudaFuncSetAttribute(ppeg_k, cudaFuncAttributeMaxDynamicSharedMemorySize, PG_SMEM);

    Ptrs p; get_ptrs(p);

    // launch order: build_h(1), wconv qkv1(2), ln_pad(3), qkv gemm(4) <- profiled
    build_h_k<<<(int)(((long)NH * C + 255) / 256), 256>>>(features, cls, p.h);
    wconvT_k<<<(QKVW * C + 255) / 256, 256>>>(qkv1_w, p.w1ah, p.w1al, C, QKVW);
    ln_pad_k<<<NP, 256>>>(p.h, p.xph, p.xpl, ln1_g, ln1_b);
    { EpiOut e = epi0(); e.ph = p.qkvh; e.pl = p.qkvl; e.palpha = 1.f; e.ldp = QKVW;
      gemmP(p.xph, p.xpl, p.w1ah, p.w1al, NP, QKVW, C, C, C, 0, 0, 1, 1, e); }

    // remaining weight converts
    wconvT_k<<<(C * C + 255) / 256, 256>>>(out1_w, p.w2ah, p.w2al, C, C);
    wconvT_k<<<(QKVW * C + 255) / 256, 256>>>(qkv2_w, p.w1bh, p.w1bl, C, QKVW);
    wconvT_k<<<(C * C + 255) / 256, 256>>>(out2_w, p.w2bh, p.w2bl, C, C);

    // layer 1 tail (after its qkv)
    nystrom_tail(p, p.h, p.w2ah, p.w2al, out1_b, res1_w);

    // PPEG (tiled)
    ppeg_k<<<dim3((HW + PT - 1) / PT, (HW + PT - 1) / PT, 16), 256, PG_SMEM>>>(
        p.h, p.h2, pe_w7, pe_b7, pe_w5, pe_b5, pe_w3, pe_b3);

    // layer 2
    ln_pad_k<<<NP, 256>>>(p.h2, p.xph, p.xpl, ln2_g, ln2_b);
    { EpiOut e = epi0(); e.ph = p.qkvh; e.pl = p.qkvl; e.palpha = 1.f; e.ldp = QKVW;
      gemmP(p.xph, p.xpl, p.w1bh, p.w1bl, NP, QKVW, C, C, C, 0, 0, 1, 1, e); }
    nystrom_tail(p, p.h2, p.w2bh, p.w2bl, out2_b, res2_w);

    cudaMemcpyAsync(d_out, p.h2, (size_t)out_size * sizeof(float),
                    cudaMemcpyDeviceToDevice);
}

// round 12
// speedup vs baseline: 1.4731x; 1.1100x over previous
#include <cuda_runtime.h>
#include <cuda_bf16.h>
#include <math.h>
#include <stdint.h>

typedef __nv_bfloat16 bf16;

// ---------------- problem constants ----------------
#define NH    22501
#define NFEAT 22400
#define HW    150
#define C     512
#define NP    22528
#define PADN  27
#define HEADS 8
#define DH    64
#define MM    256
#define LL    88
#define QKVW  1536
#define NSPLIT 16

// ---------------- fp32 scratch ----------------
__device__ float g_h   [(long)NH*C];
__device__ float g_h2  [(long)NH*C];
__device__ float g_a2  [HEADS*MM*MM];
__device__ float g_attn[(long)NP*C];
__device__ float g_outl[(long)NH*C];
__device__ float g_rowsum[HEADS*MM];
__device__ float g_colsum[HEADS*MM];
__device__ float g_fm[NSPLIT*HEADS*MM];
__device__ float g_fs[NSPLIT*HEADS*MM];
__device__ float g_scale[1];

// ---------------- bf16 hi/lo pair scratch ----------------
__device__ bf16 g_xph[(long)NP*C],     g_xpl[(long)NP*C];
__device__ bf16 g_qkvh[(long)NP*QKVW], g_qkvl[(long)NP*QKVW];
__device__ bf16 g_qlh[HEADS*MM*DH],    g_qll[HEADS*MM*DH];
__device__ bf16 g_klh[HEADS*MM*DH],    g_kll[HEADS*MM*DH];
__device__ bf16 g_a2h[HEADS*MM*MM],    g_a2l[HEADS*MM*MM];
__device__ bf16 g_zh [HEADS*MM*MM], g_zl [HEADS*MM*MM];
__device__ bf16 g_zth[HEADS*MM*MM], g_ztl[HEADS*MM*MM];
__device__ bf16 g_z2h[HEADS*MM*MM], g_z2l[HEADS*MM*MM];
__device__ bf16 g_z2th[HEADS*MM*MM], g_z2tl[HEADS*MM*MM];
__device__ bf16 g_xzh[HEADS*MM*MM], g_xzl[HEADS*MM*MM];
__device__ bf16 g_tah[HEADS*MM*MM], g_tal[HEADS*MM*MM];
__device__ bf16 g_tbh[HEADS*MM*MM], g_tbl[HEADS*MM*MM];
__device__ bf16 g_vth[(long)HEADS*DH*NP], g_vtl[(long)HEADS*DH*NP];
__device__ bf16 g_a3h[HEADS*DH*MM],    g_a3l[HEADS*DH*MM];
__device__ bf16 g_Wth[HEADS*DH*MM],    g_Wtl[HEADS*DH*MM];
__device__ bf16 g_ath[(long)NP*C],     g_atl[(long)NP*C];
__device__ bf16 g_w1ah[(long)QKVW*C],  g_w1al[(long)QKVW*C];
__device__ bf16 g_w2ah[(long)C*C],     g_w2al[(long)C*C];
__device__ bf16 g_w1bh[(long)QKVW*C],  g_w1bl[(long)QKVW*C];
__device__ bf16 g_w2bh[(long)C*C],     g_w2bl[(long)C*C];

// ---------------- small device helpers ----------------
__device__ __forceinline__ uint32_t smem_to_u32(const void* p) {
    uint32_t a;
    asm("{ .reg .u64 t; cvta.to.shared.u64 t, %1; cvt.u32.u64 %0, t; }"
        : "=r"(a) : "l"(p));
    return a;
}
__device__ __forceinline__ void ldsm4(uint32_t addr, uint32_t& r0, uint32_t& r1,
                                      uint32_t& r2, uint32_t& r3)
{
    asm volatile("ldmatrix.sync.aligned.m8n8.x4.shared.b16 {%0,%1,%2,%3}, [%4];"
                 : "=r"(r0), "=r"(r1), "=r"(r2), "=r"(r3) : "r"(addr));
}
__device__ __forceinline__ void mma_bf16(float* c, const uint32_t* a,
                                         uint32_t b0, uint32_t b1)
{
    asm volatile("mma.sync.aligned.m16n8k16.row.col.f32.bf16.bf16.f32 "
                 "{%0,%1,%2,%3},{%4,%5,%6,%7},{%8,%9},{%0,%1,%2,%3};"
                 : "+f"(c[0]), "+f"(c[1]), "+f"(c[2]), "+f"(c[3])
                 : "r"(a[0]), "r"(a[1]), "r"(a[2]), "r"(a[3]), "r"(b0), "r"(b1));
}
__device__ __forceinline__ void cpa16(uint32_t dst, const void* src, int sz)
{
    asm volatile("cp.async.cg.shared.global [%0], [%1], 16, %2;"
                 :: "r"(dst), "l"(src), "r"(sz));
}
__device__ __forceinline__ uint32_t pack2(float a, float b)   // a->low, b->high
{
    uint32_t r;
    asm("cvt.rn.bf16x2.f32 %0, %1, %2;" : "=r"(r) : "f"(b), "f"(a));
    return r;
}
__device__ __forceinline__ void split_bf(float x, float& hi, float& lo)
{
    hi = __bfloat162float(__float2bfloat16(x));
    lo = x - hi;
}
__device__ __forceinline__ float pairval(const bf16* h, const bf16* l, long i)
{
    return __bfloat162float(h[i]) + __bfloat162float(l[i]);
}

struct EpiOut {
    float* f; float falpha; int ldf; long sF;
    bf16 *ph, *pl; float palpha; int ldp; long sP;
    bf16 *th, *tl; float talpha, tdiag; int ldt; long sT;
    const float* resid;
    const float* bias;
};

__device__ __forceinline__ void epi_write(const EpiOut& ep, float* F,
                                          bf16* Ph, bf16* Pl, bf16* Th, bf16* Tl,
                                          int gr, int gc, float va, float vb)
{
    if (F) {
        float o0 = ep.falpha * va, o1 = ep.falpha * vb;
        if (ep.bias)  { o0 += ep.bias[gc]; o1 += ep.bias[gc + 1]; }
        if (ep.resid) {
            o0 += ep.resid[(long)gr * ep.ldf + gc];
            o1 += ep.resid[(long)gr * ep.ldf + gc + 1];
        }
        *reinterpret_cast<float2*>(F + (long)gr * ep.ldf + gc) = make_float2(o0, o1);
    }
    if (Ph) {
        float s0 = ep.palpha * va, s1 = ep.palpha * vb;
        float h0, l0, h1, l1;
        split_bf(s0, h0, l0); split_bf(s1, h1, l1);
        *reinterpret_cast<uint32_t*>(Ph + (long)gr * ep.ldp + gc) = pack2(h0, h1);
        *reinterpret_cast<uint32_t*>(Pl + (long)gr * ep.ldp + gc) = pack2(l0, l1);
    }
    if (Th) {
        #pragma unroll
        for (int j = 0; j < 2; j++) {
            int cc = gc + j;
            float v = (j == 0) ? va : vb;
            float s = ep.talpha * v + ((gr == cc) ? ep.tdiag : 0.f);
            float hi, lo; split_bf(s, hi, lo);
            Th[(long)cc * ep.ldt + gr] = __float2bfloat16(hi);
            Tl[(long)cc * ep.ldt + gr] = __float2bfloat16(lo);
        }
    }
}

// =======================================================================
// gemm_p: 128x64x32 tile, 3-stage, 8 warps (4m x 2n), warp 32x32.
// =======================================================================
#define RS      80
#define AH_OFF  0
#define AL_OFF  10240
#define BH_OFF  20480
#define BL_OFF  25600
#define STAGE   30720
#define GP_SMEM (3 * STAGE)

__global__ void __launch_bounds__(256, 2)
gemm_p(const bf16* __restrict__ Ah, const bf16* __restrict__ Al,
       const bf16* __restrict__ Bh, const bf16* __restrict__ Bl,
       int M, int K, int lda, int ldb, long sA, long sB,
       EpiOut ep, int ksplit)
{
    extern __shared__ __align__(16) char sm[];
    const uint32_t sb0 = smem_to_u32(sm);
    const int tid = threadIdx.x, warp = tid >> 5, lane = tid & 31;
    const int wm = warp & 3, wn = warp >> 2;

    const int z = blockIdx.z;
    const int batch = z / ksplit;
    Ah += (long)batch * sA;  Al += (long)batch * sA;
    Bh += (long)batch * sB;  Bl += (long)batch * sB;

    const int row0 = blockIdx.y * 128, col0 = blockIdx.x * 64;
    const int nch = K >> 5;

    float acc[2][4][4];
    #pragma unroll
    for (int i = 0; i < 2; i++)
        #pragma unroll
        for (int j = 0; j < 4; j++)
            #pragma unroll
            for (int q = 0; q < 4; q++) acc[i][j][q] = 0.f;

    auto issue = [&](int it) {
        const int stg = it % 3;
        const uint32_t sb = sb0 + stg * STAGE;
        const int kc = it * 32;
        #pragma unroll
        for (int rep = 0; rep < 2; rep++) {
            int c = tid + rep * 256;
            int row = c >> 2, seg = c & 3;
            int gm = row0 + row;
            long go = (long)gm * lda + kc + seg * 8;
            int sz = (gm < M) ? 16 : 0;
            cpa16(sb + AH_OFF + row * RS + seg * 16, Ah + go, sz);
            cpa16(sb + AL_OFF + row * RS + seg * 16, Al + go, sz);
        }
        {
            int n = tid >> 2, seg = tid & 3;
            long go = (long)(col0 + n) * ldb + kc + seg * 8;
            cpa16(sb + BH_OFF + n * RS + seg * 16, Bh + go, 16);
            cpa16(sb + BL_OFF + n * RS + seg * 16, Bl + go, 16);
        }
        asm volatile("cp.async.commit_group;");
    };

    const int rsel = (lane & 7) + ((lane >> 3) & 1) * 8;
    const int ksel = ((lane >> 4) & 1) * 16;
    auto do_mma = [&](int stg) {
        uint32_t sb = sb0 + stg * STAGE;
        #pragma unroll
        for (int kk = 0; kk < 2; kk++) {
            uint32_t ah[2][4], al[2][4];
            #pragma unroll
            for (int mt = 0; mt < 2; mt++) {
                uint32_t ad = sb + AH_OFF + (wm * 32 + mt * 16 + rsel) * RS + kk * 32 + ksel;
                ldsm4(ad, ah[mt][0], ah[mt][1], ah[mt][2], ah[mt][3]);
                ldsm4(ad + (AL_OFF - AH_OFF), al[mt][0], al[mt][1], al[mt][2], al[mt][3]);
            }
            #pragma unroll
            for (int np = 0; np < 2; np++) {
                uint32_t bd = sb + BH_OFF + (wn * 32 + np * 16 + rsel) * RS + kk * 32 + ksel;
                uint32_t q0, q1, q2, q3, r0, r1, r2, r3;
                ldsm4(bd, q0, q1, q2, q3);
                ldsm4(bd + (BL_OFF - BH_OFF), r0, r1, r2, r3);
                #pragma unroll
                for (int mt = 0; mt < 2; mt++) {
                    mma_bf16(acc[mt][2*np],   ah[mt], q0, q2);
                    mma_bf16(acc[mt][2*np],   ah[mt], r0, r2);
                    mma_bf16(acc[mt][2*np],   al[mt], q0, q2);
                    mma_bf16(acc[mt][2*np+1], ah[mt], q1, q3);
                    mma_bf16(acc[mt][2*np+1], ah[mt], r1, r3);
                    mma_bf16(acc[mt][2*np+1], al[mt], q1, q3);
                }
            }
        }
    };

    issue(0);
    if (nch > 1) issue(1);
    for (int it = 0; it < nch; it++) {
        if (it + 1 < nch) asm volatile("cp.async.wait_group 1;");
        else              asm volatile("cp.async.wait_group 0;");
        __syncthreads();
        if (it + 2 < nch) issue(it + 2);
        do_mma(it % 3);
    }

    const int er = lane >> 2, eq = lane & 3;
    float* F  = ep.f  ? ep.f  + (long)z     * ep.sF : (float*)0;
    bf16* Ph  = ep.ph ? ep.ph + (long)batch * ep.sP : (bf16*)0;
    bf16* Pl  = ep.pl ? ep.pl + (long)batch * ep.sP : (bf16*)0;
    bf16* Th  = ep.th ? ep.th + (long)batch * ep.sT : (bf16*)0;
    bf16* Tl  = ep.tl ? ep.tl + (long)batch * ep.sT : (bf16*)0;

    #pragma unroll
    for (int mt = 0; mt < 2; mt++)
        #pragma unroll
        for (int nt = 0; nt < 4; nt++) {
            int gr0 = row0 + wm * 32 + mt * 16 + er;
            int gc  = col0 + wn * 32 + nt * 8 + 2 * eq;
            #pragma unroll
            for (int half = 0; half < 2; half++) {
                int gr = gr0 + 8 * half;
                if (gr >= M) continue;
                epi_write(ep, F, Ph, Pl, Th, Tl, gr, gc,
                          acc[mt][nt][2 * half], acc[mt][nt][2 * half + 1]);
            }
        }
}

// =======================================================================
// gemm_p2: 256x64x32 tile, 2-stage, 8 warps (4m x 2n), warp 64x32.
// =======================================================================
#define P2_AH   0
#define P2_AL   20480
#define P2_BH   40960
#define P2_BL   46080
#define P2_STG  51200
#define GP2_SMEM (2 * P2_STG)

__global__ void __launch_bounds__(256, 2)
gemm_p2(const bf16* __restrict__ Ah, const bf16* __restrict__ Al,
        const bf16* __restrict__ Bh, const bf16* __restrict__ Bl,
        int M, int K, int lda, int ldb,
        EpiOut ep)
{
    extern __shared__ __align__(16) char sm[];
    const uint32_t sb0 = smem_to_u32(sm);
    const int tid = threadIdx.x, warp = tid >> 5, lane = tid & 31;
    const int wm = warp & 3, wn = warp >> 2;

    const int row0 = blockIdx.y * 256, col0 = blockIdx.x * 64;
    const int nch = K >> 5;

    float acc[4][4][4];
    #pragma unroll
    for (int i = 0; i < 4; i++)
        #pragma unroll
        for (int j = 0; j < 4; j++)
            #pragma unroll
            for (int q = 0; q < 4; q++) acc[i][j][q] = 0.f;

    auto issue = [&](int it) {
        const uint32_t sb = sb0 + (it & 1) * P2_STG;
        const int kc = it * 32;
        #pragma unroll
        for (int rep = 0; rep < 4; rep++) {
            int c = tid + rep * 256;
            int row = c >> 2, seg = c & 3;
            int gm = row0 + row;
            long go = (long)gm * lda + kc + seg * 8;
            int sz = (gm < M) ? 16 : 0;
            cpa16(sb + P2_AH + row * RS + seg * 16, Ah + go, sz);
            cpa16(sb + P2_AL + row * RS + seg * 16, Al + go, sz);
        }
        {
            int n = tid >> 2, seg = tid & 3;
            long go = (long)(col0 + n) * ldb + kc + seg * 8;
            cpa16(sb + P2_BH + n * RS + seg * 16, Bh + go, 16);
            cpa16(sb + P2_BL + n * RS + seg * 16, Bl + go, 16);
        }
        asm volatile("cp.async.commit_group;");
    };

    const int rsel = (lane & 7) + ((lane >> 3) & 1) * 8;
    const int ksel = ((lane >> 4) & 1) * 16;
    auto do_mma = [&](int stg) {
        uint32_t sb = sb0 + stg * P2_STG;
        #pragma unroll
        for (int kk = 0; kk < 2; kk++) {
            uint32_t ah[4][4], al[4][4];
            #pragma unroll
            for (int mt = 0; mt < 4; mt++) {
                uint32_t ad = sb + P2_AH + (wm * 64 + mt * 16 + rsel) * RS + kk * 32 + ksel;
                ldsm4(ad, ah[mt][0], ah[mt][1], ah[mt][2], ah[mt][3]);
                ldsm4(ad + (P2_AL - P2_AH), al[mt][0], al[mt][1], al[mt][2], al[mt][3]);
            }
            #pragma unroll
            for (int np = 0; np < 2; np++) {
                uint32_t bd = sb + P2_BH + (wn * 32 + np * 16 + rsel) * RS + kk * 32 + ksel;
                uint32_t q0, q1, q2, q3, r0, r1, r2, r3;
                ldsm4(bd, q0, q1, q2, q3);
                ldsm4(bd + (P2_BL - P2_BH), r0, r1, r2, r3);
                #pragma unroll
                for (int mt = 0; mt < 4; mt++) {
                    mma_bf16(acc[mt][2*np],   ah[mt], q0, q2);
                    mma_bf16(acc[mt][2*np],   ah[mt], r0, r2);
                    mma_bf16(acc[mt][2*np],   al[mt], q0, q2);
                    mma_bf16(acc[mt][2*np+1], ah[mt], q1, q3);
                    mma_bf16(acc[mt][2*np+1], ah[mt], r1, r3);
                    mma_bf16(acc[mt][2*np+1], al[mt], q1, q3);
                }
            }
        }
    };

    issue(0);
    for (int it = 0; it < nch; it++) {
        if (it + 1 < nch) { issue(it + 1); asm volatile("cp.async.wait_group 1;"); }
        else              { asm volatile("cp.async.wait_group 0;"); }
        __syncthreads();
        do_mma(it & 1);
        __syncthreads();
    }

    const int er = lane >> 2, eq = lane & 3;
    float* F  = ep.f;
    bf16* Ph  = ep.ph;  bf16* Pl = ep.pl;
    bf16* Th  = ep.th;  bf16* Tl = ep.tl;

    #pragma unroll
    for (int mt = 0; mt < 4; mt++)
        #pragma unroll
        for (int nt = 0; nt < 4; nt++) {
            int gr0 = row0 + wm * 64 + mt * 16 + er;
            int gc  = col0 + wn * 32 + nt * 8 + 2 * eq;
            #pragma unroll
            for (int half = 0; half < 2; half++) {
                int gr = gr0 + 8 * half;
                if (gr >= M) continue;
                epi_write(ep, F, Ph, Pl, Th, Tl, gr, gc,
                          acc[mt][nt][2 * half], acc[mt][nt][2 * half + 1]);
            }
        }
}

static EpiOut epi0() { EpiOut e{}; return e; }
static void gemmP(const bf16* Ah, const bf16* Al, const bf16* Bh, const bf16* Bl,
                  int M, int N, int K, int lda, int ldb, long sA, long sB,
                  int batch, int ksplit, EpiOut ep)
{
    if (batch == 1 && M >= 512) {
        dim3 g(N / 64, (M + 255) / 256, 1), b(256);
        gemm_p2<<<g, b, GP2_SMEM>>>(Ah, Al, Bh, Bl, M, K, lda, ldb, ep);
    } else {
        dim3 g(N / 64, (M + 127) / 128, batch * ksplit), b(256);
        gemm_p<<<g, b, GP_SMEM>>>(Ah, Al, Bh, Bl, M, K, lda, ldb, sA, sB, ep, ksplit);
    }
}

// =======================================================================
// flash-fused S3 path (NSPLIT=16)
// =======================================================================
#define FL_RS   144
#define FL_QH   0
#define FL_QL   18432
#define FL_K(b) (36864 + (b) * 18432)
#define FL_V(b) (73728 + (b) * 18432)
#define FL_PH   110592
#define FL_PL   129024
#define FL_SMEM 147456
#define FL_NCH  ((NP / NSPLIT) / 64)

__global__ void __launch_bounds__(128)
flash3_k(const bf16* __restrict__ qlh, const bf16* __restrict__ qll,
         const bf16* __restrict__ qkvh, const bf16* __restrict__ qkvl,
         const bf16* __restrict__ vth, const bf16* __restrict__ vtl,
         float* __restrict__ pO, float* __restrict__ pm, float* __restrict__ ps)
{
    extern __shared__ __align__(16) char sm[];
    const uint32_t sb = smem_to_u32(sm);
    const int tid = threadIdx.x, warp = tid >> 5, lane = tid & 31;
    const int split = blockIdx.x, rowHalf = blockIdx.y, head = blockIdx.z;
    const int tb0 = split * (NP / NSPLIT);

    const bf16* Qh = qlh + ((long)head * MM + rowHalf * 128) * DH;
    const bf16* Ql = qll + ((long)head * MM + rowHalf * 128) * DH;
    #pragma unroll
    for (int i = 0; i < 8; i++) {
        int s = tid + 128 * i;
        int r = s >> 3, seg = s & 7;
        long go = (long)r * DH + seg * 8;
        cpa16(sb + FL_QH + r * FL_RS + seg * 16, Qh + go, 16);
        cpa16(sb + FL_QL + r * FL_RS + seg * 16, Ql + go, 16);
    }

    const bf16* Kh = qkvh + head * DH + 512;
    const bf16* Kl = qkvl + head * DH + 512;
    const bf16* Vh = vth + (long)head * DH * NP;
    const bf16* Vl = vtl + (long)head * DH * NP;

    auto kissue = [&](int j) {
        int buf = j & 1;
        int tb = tb0 + j * 64;
        uint32_t kb = sb + FL_K(buf);
        uint32_t vb = sb + FL_V(buf);
        #pragma unroll
        for (int i = 0; i < 4; i++) {
            int s = tid + 128 * i;
            int r = s >> 3, seg = s & 7;
            long gk = (long)(tb + r) * QKVW + seg * 8;
            cpa16(kb + r * FL_RS + seg * 16, Kh + gk, 16);
            cpa16(kb + 9216 + r * FL_RS + seg * 16, Kl + gk, 16);
            long gv = (long)r * NP + tb + seg * 8;
            cpa16(vb + r * FL_RS + seg * 16, Vh + gv, 16);
            cpa16(vb + 9216 + r * FL_RS + seg * 16, Vl + gv, 16);
        }
        asm volatile("cp.async.commit_group;");
    };
    kissue(0);
    kissue(1);

    const int rsel = (lane & 7) + ((lane >> 3) & 1) * 8;
    const int ksel = ((lane >> 4) & 1) * 16;
    const int er = lane >> 2, eq = lane & 3;

    float m_run[4] = {-1e30f, -1e30f, -1e30f, -1e30f};
    float s_run[4] = {0.f, 0.f, 0.f, 0.f};
    float oacc[2][8][4];
    #pragma unroll
    for (int a = 0; a < 2; a++)
        #pragma unroll
        for (int b = 0; b < 8; b++)
            #pragma unroll
            for (int c = 0; c < 4; c++) oacc[a][b][c] = 0.f;

    for (int j = 0; j < FL_NCH; j++) {
        if (j + 1 < FL_NCH) asm volatile("cp.async.wait_group 1;");
        else                asm volatile("cp.async.wait_group 0;");
        __syncthreads();
        uint32_t kb = sb + FL_K(j & 1);
        uint32_t vb = sb + FL_V(j & 1);

        float sacc[2][8][4];
        #pragma unroll
        for (int a = 0; a < 2; a++)
            #pragma unroll
            for (int b = 0; b < 8; b++)
                #pragma unroll
                for (int c = 0; c < 4; c++) sacc[a][b][c] = 0.f;

        #pragma unroll
        for (int k16 = 0; k16 < 4; k16++) {
            uint32_t ah[2][4], al[2][4];
            #pragma unroll
            for (int mt = 0; mt < 2; mt++) {
                uint32_t ad = sb + FL_QH + (warp * 32 + mt * 16 + rsel) * FL_RS + k16 * 32 + ksel;
                ldsm4(ad, ah[mt][0], ah[mt][1], ah[mt][2], ah[mt][3]);
                ldsm4(ad + (FL_QL - FL_QH), al[mt][0], al[mt][1], al[mt][2], al[mt][3]);
            }
            #pragma unroll
            for (int n16 = 0; n16 < 4; n16++) {
                uint32_t bd = kb + (n16 * 16 + rsel) * FL_RS + k16 * 32 + ksel;
                uint32_t q0, q1, q2, q3, p0, p1, p2, p3;
                ldsm4(bd, q0, q1, q2, q3);
                ldsm4(bd + 9216, p0, p1, p2, p3);
                #pragma unroll
                for (int mt = 0; mt < 2; mt++) {
                    mma_bf16(sacc[mt][2*n16],   ah[mt], q0, q2);
                    mma_bf16(sacc[mt][2*n16],   ah[mt], p0, p2);
                    mma_bf16(sacc[mt][2*n16],   al[mt], q0, q2);
                    mma_bf16(sacc[mt][2*n16+1], ah[mt], q1, q3);
                    mma_bf16(sacc[mt][2*n16+1], ah[mt], p1, p3);
                    mma_bf16(sacc[mt][2*n16+1], al[mt], q1, q3);
                }
            }
        }

        #pragma unroll
        for (int mt = 0; mt < 2; mt++) {
            float cm0 = -1e30f, cm1 = -1e30f;
            #pragma unroll
            for (int nt = 0; nt < 8; nt++) {
                cm0 = fmaxf(cm0, fmaxf(sacc[mt][nt][0], sacc[mt][nt][1]));
                cm1 = fmaxf(cm1, fmaxf(sacc[mt][nt][2], sacc[mt][nt][3]));
            }
            #pragma unroll
            for (int o = 1; o <= 2; o <<= 1) {
                cm0 = fmaxf(cm0, __shfl_xor_sync(0xffffffffu, cm0, o));
                cm1 = fmaxf(cm1, __shfl_xor_sync(0xffffffffu, cm1, o));
            }
            float mn0 = fmaxf(m_run[2*mt],     cm0);
            float mn1 = fmaxf(m_run[2*mt + 1], cm1);
            float sc0 = __expf(m_run[2*mt]     - mn0);
            float sc1 = __expf(m_run[2*mt + 1] - mn1);
            m_run[2*mt] = mn0; m_run[2*mt + 1] = mn1;
            float ls0 = 0.f, ls1 = 0.f;
            int pr = warp * 32 + mt * 16 + er;
            #pragma unroll
            for (int nt = 0; nt < 8; nt++) {
                float e0 = __expf(sacc[mt][nt][0] - mn0);
                float e1 = __expf(sacc[mt][nt][1] - mn0);
                float e2 = __expf(sacc[mt][nt][2] - mn1);
                float e3 = __expf(sacc[mt][nt][3] - mn1);
                ls0 += e0 + e1; ls1 += e2 + e3;
                oacc[mt][nt][0] *= sc0; oacc[mt][nt][1] *= sc0;
                oacc[mt][nt][2] *= sc1; oacc[mt][nt][3] *= sc1;
                int col = nt * 8 + 2 * eq;
                float h0, l0, h1, l1;
                split_bf(e0, h0, l0); split_bf(e1, h1, l1);
                *reinterpret_cast<uint32_t*>(sm + FL_PH + pr * FL_RS + col * 2) = pack2(h0, h1);
                *reinterpret_cast<uint32_t*>(sm + FL_PL + pr * FL_RS + col * 2) = pack2(l0, l1);
                split_bf(e2, h0, l0); split_bf(e3, h1, l1);
                *reinterpret_cast<uint32_t*>(sm + FL_PH + (pr + 8) * FL_RS + col * 2) = pack2(h0, h1);
                *reinterpret_cast<uint32_t*>(sm + FL_PL + (pr + 8) * FL_RS + col * 2) = pack2(l0, l1);
            }
            #pragma unroll
            for (int o = 1; o <= 2; o <<= 1) {
                ls0 += __shfl_xor_sync(0xffffffffu, ls0, o);
                ls1 += __shfl_xor_sync(0xffffffffu, ls1, o);
            }
            s_run[2*mt]     = s_run[2*mt]     * sc0 + ls0;
            s_run[2*mt + 1] = s_run[2*mt + 1] * sc1 + ls1;
        }
        __syncthreads();

        #pragma unroll
        for (int k16 = 0; k16 < 4; k16++) {
            uint32_t ph[2][4], pl[2][4];
            #pragma unroll
            for (int mt = 0; mt < 2; mt++) {
                uint32_t ad = sb + FL_PH + (warp * 32 + mt * 16 + rsel) * FL_RS + k16 * 32 + ksel;
                ldsm4(ad, ph[mt][0], ph[mt][1], ph[mt][2], ph[mt][3]);
                ldsm4(ad + (FL_PL - FL_PH), pl[mt][0], pl[mt][1], pl[mt][2], pl[mt][3]);
            }
            #pragma unroll
            for (int n16 = 0; n16 < 4; n16++) {
                uint32_t bd = vb + (n16 * 16 + rsel) * FL_RS + k16 * 32 + ksel;
                uint32_t q0, q1, q2, q3, r0, r1, r2, r3;
                ldsm4(bd, q0, q1, q2, q3);
                ldsm4(bd + 9216, r0, r1, r2, r3);
                #pragma unroll
                for (int mt = 0; mt < 2; mt++) {
                    mma_bf16(oacc[mt][2*n16],   ph[mt], q0, q2);
                    mma_bf16(oacc[mt][2*n16],   ph[mt], r0, r2);
                    mma_bf16(oacc[mt][2*n16],   pl[mt], q0, q2);
                    mma_bf16(oacc[mt][2*n16+1], ph[mt], q1, q3);
                    mma_bf16(oacc[mt][2*n16+1], ph[mt], r1, r3);
                    mma_bf16(oacc[mt][2*n16+1], pl[mt], q1, q3);
                }
            }
        }
        __syncthreads();
        if (j + 2 < FL_NCH) kissue(j + 2);
    }

    const int base = (split * HEADS + head) * MM + rowHalf * 128;
    #pragma unroll
    for (int mt = 0; mt < 2; mt++) {
        int r0 = base + warp * 32 + mt * 16 + er;
        #pragma unroll
        for (int nt = 0; nt < 8; nt++) {
            int d = nt * 8 + 2 * eq;
            *reinterpret_cast<float2*>(pO + (long)r0 * DH + d) =
                make_float2(oacc[mt][nt][0], oacc[mt][nt][1]);
            *reinterpret_cast<float2*>(pO + (long)(r0 + 8) * DH + d) =
                make_float2(oacc[mt][nt][2], oacc[mt][nt][3]);
        }
        if (eq == 0) {
            pm[r0] = m_run[2*mt];     ps[r0] = s_run[2*mt];
            pm[r0 + 8] = m_run[2*mt + 1]; ps[r0 + 8] = s_run[2*mt + 1];
        }
    }
}

__global__ void flash_merge_k(const float* __restrict__ pO, const float* __restrict__ pm,
                              const float* __restrict__ ps,
                              bf16* __restrict__ oh, bf16* __restrict__ ol)
{
    int row = blockIdx.x, head = blockIdx.y, d = threadIdx.x;
    float mx = -1e30f;
    #pragma unroll
    for (int i = 0; i < NSPLIT; i++)
        mx = fmaxf(mx, pm[(i * HEADS + head) * MM + row]);
    float den = 0.f, acc = 0.f;
    #pragma unroll
    for (int i = 0; i < NSPLIT; i++) {
        int r = (i * HEADS + head) * MM + row;
        float w = __expf(pm[r] - mx);
        den += w * ps[r];
        acc += w * pO[(long)r * DH + d];
    }
    float v = acc / den;
    float hi, lo; split_bf(v, hi, lo);
    long o = ((long)head << 14) + d * MM + row;
    oh[o] = __float2bfloat16(hi);
    ol[o] = __float2bfloat16(lo);
}

// =======================================================================
// fused S1 -> softmax -> O1 (unchanged)
// =======================================================================
#define FA_RS1  144
#define FA_AH   0
#define FA_AL   9216
#define FA_BH   18432
#define FA_BL   55296
#define FA_PH   0
#define FA_PL   33792
#define FA_WS   67584
#define FA_WST  10240
#define FA_SMEM 98304

__global__ void __launch_bounds__(128)
fused_attn1_k(const bf16* __restrict__ qh, const bf16* __restrict__ ql_,
              const bf16* __restrict__ klh, const bf16* __restrict__ kll,
              const bf16* __restrict__ Wth, const bf16* __restrict__ Wtl,
              float* __restrict__ attn)
{
    extern __shared__ __align__(16) char sm[];
    const uint32_t sb = smem_to_u32(sm);
    const int tid = threadIdx.x, warp = tid >> 5, lane = tid & 31;
    const int row0 = blockIdx.x * 64;
    const int head = blockIdx.y;

    const bf16* qsh = qh  + (long)row0 * QKVW + head * DH;
    const bf16* qsl = ql_ + (long)row0 * QKVW + head * DH;
    #pragma unroll
    for (int i = 0; i < 4; i++) {
        int s = tid + 128 * i;
        int r = s >> 3, seg = s & 7;
        long go = (long)r * QKVW + seg * 8;
        cpa16(sb + FA_AH + r * FA_RS1 + seg * 16, qsh + go, 16);
        cpa16(sb + FA_AL + r * FA_RS1 + seg * 16, qsl + go, 16);
    }
    const bf16* ksh = klh + (long)head * MM * DH;
    const bf16* ksl = kll + (long)head * MM * DH;
    #pragma unroll
    for (int i = 0; i < 16; i++) {
        int s = tid + 128 * i;
        int r = s >> 3, seg = s & 7;
        long go = (long)r * DH + seg * 8;
        cpa16(sb + FA_BH + r * FA_RS1 + seg * 16, ksh + go, 16);
        cpa16(sb + FA_BL + r * FA_RS1 + seg * 16, ksl + go, 16);
    }
    asm volatile("cp.async.commit_group;");
    asm volatile("cp.async.wait_group 0;");
    __syncthreads();

    const int rsel = (lane & 7) + ((lane >> 3) & 1) * 8;
    const int ksel = ((lane >> 4) & 1) * 16;
    float sacc[32][4];
    #pragma unroll
    for (int i = 0; i < 32; i++)
        #pragma unroll
        for (int j = 0; j < 4; j++) sacc[i][j] = 0.f;

    #pragma unroll
    for (int k16 = 0; k16 < 4; k16++) {
        uint32_t ah[4], al[4];
        uint32_t ad = sb + FA_AH + (warp * 16 + rsel) * FA_RS1 + k16 * 32 + ksel;
        ldsm4(ad, ah[0], ah[1], ah[2], ah[3]);
        ldsm4(ad + (FA_AL - FA_AH), al[0], al[1], al[2], al[3]);
        #pragma unroll
        for (int n16 = 0; n16 < 16; n16++) {
            uint32_t bd = sb + FA_BH + (n16 * 16 + rsel) * FA_RS1 + k16 * 32 + ksel;
            uint32_t q0, q1, q2, q3, p0, p1, p2, p3;
            ldsm4(bd, q0, q1, q2, q3);
            ldsm4(bd + (FA_BL - FA_BH), p0, p1, p2, p3);
            mma_bf16(sacc[2*n16],   ah, q0, q2);
            mma_bf16(sacc[2*n16],   ah, p0, p2);
            mma_bf16(sacc[2*n16],   al, q0, q2);
            mma_bf16(sacc[2*n16+1], ah, q1, q3);
            mma_bf16(sacc[2*n16+1], ah, p1, p3);
            mma_bf16(sacc[2*n16+1], al, q1, q3);
        }
    }

    float mx0 = -1e30f, mx1 = -1e30f;
    #pragma unroll
    for (int nt = 0; nt < 32; nt++) {
        #pragma unroll
        for (int j = 0; j < 4; j++) sacc[nt][j] *= 0.125f;
        mx0 = fmaxf(mx0, fmaxf(sacc[nt][0], sacc[nt][1]));
        mx1 = fmaxf(mx1, fmaxf(sacc[nt][2], sacc[nt][3]));
    }
    #pragma unroll
    for (int o = 1; o <= 2; o <<= 1) {
        mx0 = fmaxf(mx0, __shfl_xor_sync(0xffffffffu, mx0, o));
        mx1 = fmaxf(mx1, __shfl_xor_sync(0xffffffffu, mx1, o));
    }
    float sm0 = 0.f, sm1 = 0.f;
    #pragma unroll
    for (int nt = 0; nt < 32; nt++) {
        sacc[nt][0] = __expf(sacc[nt][0] - mx0);
        sacc[nt][1] = __expf(sacc[nt][1] - mx0);
        sacc[nt][2] = __expf(sacc[nt][2] - mx1);
        sacc[nt][3] = __expf(sacc[nt][3] - mx1);
        sm0 += sacc[nt][0] + sacc[nt][1];
        sm1 += sacc[nt][2] + sacc[nt][3];
    }
    #pragma unroll
    for (int o = 1; o <= 2; o <<= 1) {
        sm0 += __shfl_xor_sync(0xffffffffu, sm0, o);
        sm1 += __shfl_xor_sync(0xffffffffu, sm1, o);
    }
    __syncthreads();

    const bf16* Wsh = Wth + (long)head * DH * MM;
    const bf16* Wsl = Wtl + (long)head * DH * MM;
    auto wissue = [&](int it) {
        int stg = it % 3;
        uint32_t base = sb + FA_WS + stg * FA_WST;
        #pragma unroll
        for (int i = 0; i < 2; i++) {
            int s = tid + 128 * i;
            int r = s >> 2, seg = s & 3;
            long go = (long)r * MM + it * 32 + seg * 8;
            cpa16(base + r * 80 + seg * 16, Wsh + go, 16);
            cpa16(base + 5120 + r * 80 + seg * 16, Wsl + go, 16);
        }
        asm volatile("cp.async.commit_group;");
    };
    wissue(0); wissue(1);

    {
        int pr = warp * 16 + (lane >> 2);
        int pc = (lane & 3) * 2;
        #pragma unroll
        for (int nt = 0; nt < 32; nt++) {
            int col = nt * 8 + pc;
            float h0, l0, h1, l1;
            split_bf(sacc[nt][0], h0, l0); split_bf(sacc[nt][1], h1, l1);
            *reinterpret_cast<uint32_t*>(sm + FA_PH + pr * 528 + col * 2) = pack2(h0, h1);
            *reinterpret_cast<uint32_t*>(sm + FA_PL + pr * 528 + col * 2) = pack2(l0, l1);
            split_bf(sacc[nt][2], h0, l0); split_bf(sacc[nt][3], h1, l1);
            *reinterpret_cast<uint32_t*>(sm + FA_PH + (pr + 8) * 528 + col * 2) = pack2(h0, h1);
            *reinterpret_cast<uint32_t*>(sm + FA_PL + (pr + 8) * 528 + col * 2) = pack2(l0, l1);
        }
    }
    __syncthreads();

    float oacc[8][4];
    #pragma unroll
    for (int i = 0; i < 8; i++)
        #pragma unroll
        for (int j = 0; j < 4; j++) oacc[i][j] = 0.f;

    for (int it = 0; it < 8; it++) {
        if (it < 7) asm volatile("cp.async.wait_group 1;");
        else        asm volatile("cp.async.wait_group 0;");
        __syncthreads();
        if (it + 2 < 8) wissue(it + 2);
        uint32_t wb = sb + FA_WS + (it % 3) * FA_WST;
        #pragma unroll
        for (int k16 = 0; k16 < 2; k16++) {
            int gk = it * 2 + k16;
            uint32_t ph[4], pl[4];
            uint32_t ad = sb + FA_PH + (warp * 16 + rsel) * 528 + gk * 32 + ksel;
            ldsm4(ad, ph[0], ph[1], ph[2], ph[3]);
            ldsm4(ad + (FA_PL - FA_PH), pl[0], pl[1], pl[2], pl[3]);
            #pragma unroll
            for (int n16 = 0; n16 < 4; n16++) {
                uint32_t bd = wb + (n16 * 16 + rsel) * 80 + k16 * 32 + ksel;
                uint32_t q0, q1, q2, q3, r0, r1, r2, r3;
                ldsm4(bd, q0, q1, q2, q3);
                ldsm4(bd + 5120, r0, r1, r2, r3);
                mma_bf16(oacc[2*n16],   ph, q0, q2);
                mma_bf16(oacc[2*n16],   ph, r0, r2);
                mma_bf16(oacc[2*n16],   pl, q0, q2);
                mma_bf16(oacc[2*n16+1], ph, q1, q3);
                mma_bf16(oacc[2*n16+1], ph, r1, r3);
                mma_bf16(oacc[2*n16+1], pl, q1, q3);
            }
        }
    }

    float inv0 = 1.f / sm0, inv1 = 1.f / sm1;
    int orow = row0 + warp * 16 + (lane >> 2);
    int ocol = head * DH + (lane & 3) * 2;
    #pragma unroll
    for (int nt = 0; nt < 8; nt++) {
        int col = ocol + nt * 8;
        *reinterpret_cast<float2*>(attn + (long)orow * C + col) =
            make_float2(oacc[nt][0] * inv0, oacc[nt][1] * inv0);
        *reinterpret_cast<float2*>(attn + (long)(orow + 8) * C + col) =
            make_float2(oacc[nt][2] * inv1, oacc[nt][3] * inv1);
    }
}

// =======================================================================
// auxiliary kernels
// =======================================================================

__global__ void wconvT_k(const float* __restrict__ w, bf16* __restrict__ th,
                         bf16* __restrict__ tl, int K, int N)
{
    int i = blockIdx.x * 256 + threadIdx.x;
    if (i >= N * K) return;
    int n = i / K, k = i - n * K;
    float v = w[(long)k * N + n];
    float hi, lo; split_bf(v, hi, lo);
    th[i] = __float2bfloat16(hi);
    tl[i] = __float2bfloat16(lo);
}

__global__ void build_h_k(const float* __restrict__ feat, const float* __restrict__ cls,
                          float* __restrict__ h)
{
    long i = (long)blockIdx.x * 256 + threadIdx.x;
    if (i >= (long)NH * C) return;
    long t = i >> 9;
    int  c = (int)(i & 511);
    float v;
    if (t == 0) v = cls[c];
    else {
        long r = t - 1;
        if (r >= NFEAT) r -= NFEAT;
        v = feat[r * C + c];
    }
    h[i] = v;
}

__global__ void ln_pad_k(const float* __restrict__ h, bf16* __restrict__ xh,
                         bf16* __restrict__ xl,
                         const float* __restrict__ g, const float* __restrict__ b)
{
    int t = blockIdx.x, c = threadIdx.x;
    long o = (long)t * C;
    if (t < PADN) {
        *reinterpret_cast<uint32_t*>(xh + o + 2 * c) = 0u;
        *reinterpret_cast<uint32_t*>(xl + o + 2 * c) = 0u;
        return;
    }
    const float* row = h + (long)(t - PADN) * C;
    float a1 = row[2 * c], a2 = row[2 * c + 1];
    __shared__ float red[256];
    red[c] = a1 + a2; __syncthreads();
    for (int s = 128; s > 0; s >>= 1) { if (c < s) red[c] += red[c + s]; __syncthreads(); }
    float mu = red[0] * (1.f / 512.f);
    __syncthreads();
    float d1 = a1 - mu, d2 = a2 - mu;
    red[c] = d1 * d1 + d2 * d2; __syncthreads();
    for (int s = 128; s > 0; s >>= 1) { if (c < s) red[c] += red[c + s]; __syncthreads(); }
    float inv = rsqrtf(red[0] * (1.f / 512.f) + 1e-5f);
    float v1 = d1 * inv * g[2 * c] + b[2 * c];
    float v2 = d2 * inv * g[2 * c + 1] + b[2 * c + 1];
    float h1, l1, h2, l2;
    split_bf(v1, h1, l1); split_bf(v2, h2, l2);
    *reinterpret_cast<uint32_t*>(xh + o + 2 * c) = pack2(h1, h2);
    *reinterpret_cast<uint32_t*>(xl + o + 2 * c) = pack2(l1, l2);
}

__global__ void landmarks_k(const bf16* __restrict__ qh, const bf16* __restrict__ ql_,
                            bf16* __restrict__ qlh, bf16* __restrict__ qll,
                            bf16* __restrict__ klh, bf16* __restrict__ kll)
{
    int d = threadIdx.x;
    int m = blockIdx.x & 255;
    int hh = blockIdx.x >> 8;
    long base = (long)(m * LL) * QKVW + hh * DH + d;
    float sq = 0.f, sk = 0.f;
    for (int j = 0; j < LL; j++) {
        long o = base + (long)j * QKVW;
        sq += pairval(qh, ql_, o);
        sk += pairval(qh, ql_, o + 512);
    }
    float vq = sq * (0.125f / (float)LL);
    float vk = sk * (1.f / (float)LL);
    int oi = (hh * MM + m) * DH + d;
    float hi, lo;
    split_bf(vq, hi, lo); qlh[oi] = __float2bfloat16(hi); qll[oi] = __float2bfloat16(lo);
    split_bf(vk, hi, lo); klh[oi] = __float2bfloat16(hi); kll[oi] = __float2bfloat16(lo);
}

__global__ void softmax256_k(const float* __restrict__ in, float* __restrict__ fout,
                             bf16* __restrict__ ph, bf16* __restrict__ pl, long nrows)
{
    long row = (long)blockIdx.x * 8 + threadIdx.y;
    if (row >= nrows) return;
    const float* r = in + row * 256;
    int lane = threadIdx.x;
    float v[8], m = -1e30f;
    #pragma unroll
    for (int i = 0; i < 8; i++) { v[i] = r[lane + 32 * i]; m = fmaxf(m, v[i]); }
    #pragma unroll
    for (int o = 16; o; o >>= 1) m = fmaxf(m, __shfl_xor_sync(0xffffffffu, m, o));
    float s = 0.f;
    #pragma unroll
    for (int i = 0; i < 8; i++) { v[i] = __expf(v[i] - m); s += v[i]; }
    #pragma unroll
    for (int o = 16; o; o >>= 1) s += __shfl_xor_sync(0xffffffffu, s, o);
    float inv = 1.f / s;
    #pragma unroll
    for (int i = 0; i < 8; i++) {
        float val = v[i] * inv;
        long o = row * 256 + lane + 32 * i;
        if (fout) fout[o] = val;
        float hi, lo; split_bf(val, hi, lo);
        ph[o] = __float2bfloat16(hi);
        pl[o] = __float2bfloat16(lo);
    }
}

__global__ void pinv_sums_k(const float* __restrict__ a2,
                            float* __restrict__ rs, float* __restrict__ cs)
{
    int hh = blockIdx.x, j = threadIdx.x;
    const float* X = a2 + (long)hh * MM * MM;
    float r = 0.f, c = 0.f;
    for (int k = 0; k < MM; k++) { r += fabsf(X[j * MM + k]); c += fabsf(X[k * MM + j]); }
    rs[hh * MM + j] = r; cs[hh * MM + j] = c;
}
__global__ void pinv_scale_k(const float* __restrict__ rs, const float* __restrict__ cs,
                             float* __restrict__ scale)
{
    __shared__ float m1[256], m2[256];
    float a = -1e30f, b = -1e30f;
    for (int i = threadIdx.x; i < HEADS * MM; i += 256) { a = fmaxf(a, rs[i]); b = fmaxf(b, cs[i]); }
    m1[threadIdx.x] = a; m2[threadIdx.x] = b; __syncthreads();
    for (int s = 128; s > 0; s >>= 1) {
        if (threadIdx.x < s) {
            m1[threadIdx.x] = fmaxf(m1[threadIdx.x], m1[threadIdx.x + s]);
            m2[threadIdx.x] = fmaxf(m2[threadIdx.x], m2[threadIdx.x + s]);
        }
        __syncthreads();
    }
    if (threadIdx.x == 0) scale[0] = 1.f / (m1[0] * m2[0]);
}
__global__ void pinv_init_k(const float* __restrict__ a2, const float* __restrict__ scale,
                            bf16* __restrict__ zph, bf16* __restrict__ zpl,
                            bf16* __restrict__ zth, bf16* __restrict__ ztl)
{
    long i = (long)blockIdx.x * 256 + threadIdx.x;
    if (i >= (long)HEADS * MM * MM) return;
    float s = scale[0];
    long hb = i & ~65535L;
    int r = (int)((i >> 8) & 255), c = (int)(i & 255);
    float vt = a2[i] * s;
    float vp = a2[hb + ((long)c << 8) + r] * s;
    float hi, lo;
    split_bf(vt, hi, lo); zth[i] = __float2bfloat16(hi); ztl[i] = __float2bfloat16(lo);
    split_bf(vp, hi, lo); zph[i] = __float2bfloat16(hi); zpl[i] = __float2bfloat16(lo);
}

__global__ void vT_k(const bf16* __restrict__ qh, const bf16* __restrict__ ql_,
                     bf16* __restrict__ vth, bf16* __restrict__ vtl)
{
    __shared__ bf16 tile[32][33];
    int t0 = blockIdx.x * 32;
    int head = blockIdx.y >> 1;
    int lopart = blockIdx.y & 1;
    int d0 = blockIdx.z * 32;
    const bf16* src = (lopart ? ql_ : qh) + 1024 + head * 64 + d0;
    bf16* dst = (lopart ? vtl : vth) + (long)head * 64 * NP + (long)d0 * NP;
    int tx = threadIdx.x, ty = threadIdx.y;
    #pragma unroll
    for (int i = 0; i < 4; i++)
        tile[ty + 8 * i][tx] = src[(long)(t0 + ty + 8 * i) * QKVW + tx];
    __syncthreads();
    #pragma unroll
    for (int i = 0; i < 4; i++)
        dst[(long)(ty + 8 * i) * NP + t0 + tx] = tile[tx][ty + 8 * i];
}

// =======================================================================
// conv_add: smem-tiled depthwise 33-tap over tokens.
// Block: 64 tokens x 128 channels, 256 threads. Tile 96 rows x 64 ch-pairs.
// =======================================================================
#define CA_ROWS 64
#define CA_HALO 96
#define CA_SMEM (CA_HALO * 64 * 8)   // float2 tile = 49152 B

__global__ void __launch_bounds__(256)
conv_add_k(const bf16* __restrict__ qh, const bf16* __restrict__ ql_,
           const float* __restrict__ rw, const float* __restrict__ attnf,
           bf16* __restrict__ ah, bf16* __restrict__ al)
{
    extern __shared__ __align__(16) float2 vt[];   // [96][64]
    const int tid = threadIdx.x;
    const int t0 = blockIdx.x * CA_ROWS;
    const int cb = blockIdx.y * 128;

    // load tile: 96 rows x 64 channel-pairs (summed hi+lo in fp32)
    for (int idx = tid; idx < CA_HALO * 64; idx += 256) {
        int row = idx >> 6, c2 = idx & 63;
        int gt = t0 + row - 16;
        float2 v = make_float2(0.f, 0.f);
        if ((unsigned)gt < (unsigned)NP) {
            long o = (long)gt * QKVW + 1024 + cb + 2 * c2;
            __nv_bfloat162 h2 = *reinterpret_cast<const __nv_bfloat162*>(qh + o);
            __nv_bfloat162 l2 = *reinterpret_cast<const __nv_bfloat162*>(ql_ + o);
            v.x = __bfloat162float(h2.x) + __bfloat162float(l2.x);
            v.y = __bfloat162float(h2.y) + __bfloat162float(l2.y);
        }
        vt[idx] = v;
    }
    __syncthreads();

    const int c2 = tid & 63;          // channel pair within 128-ch group
    const int tsub = tid >> 6;        // 0..3 -> 16 tokens each
    const int head = (cb + 2 * c2) >> 6;
    float w[33];
    #pragma unroll
    for (int k = 0; k < 33; k++) w[k] = rw[head * 33 + k];

    for (int i = 0; i < 16; i++) {
        int tloc = tsub * 16 + i;
        int t = t0 + tloc;
        float2 a = *reinterpret_cast<const float2*>(attnf + (long)t * C + cb + 2 * c2);
        float acc0 = a.x, acc1 = a.y;
        #pragma unroll
        for (int k = 0; k < 33; k++) {
            float2 v = vt[(tloc + k) * 64 + c2];
            acc0 += v.x * w[k];
            acc1 += v.y * w[k];
        }
        float h0, l0, h1, l1;
        split_bf(acc0, h0, l0); split_bf(acc1, h1, l1);
        long o = (long)t * C + cb + 2 * c2;
        *reinterpret_cast<uint32_t*>(ah + o) = pack2(h0, h1);
        *reinterpret_cast<uint32_t*>(al + o) = pack2(l0, l1);
    }
}

// =======================================================================
// PPEG: smem-tiled combined 49-tap stencil (unchanged from R11)
// =======================================================================
#define PT        16
#define PTH       22
#define PG_TILE   (PTH * PTH * 32 * 4)
#define PG_WOFF   PG_TILE
#define PG_W      (49 * 32 * 4)
#define PG_BOFF   (PG_WOFF + PG_W)
#define PG_SMEM   (PG_BOFF + 32 * 4)

__global__ void __launch_bounds__(256, 2)
ppeg_k(const float* __restrict__ h, float* __restrict__ h2,
       const float* __restrict__ w7, const float* __restrict__ b7,
       const float* __restrict__ w5, const float* __restrict__ b5,
       const float* __restrict__ w3, const float* __restrict__ b3)
{
    extern __shared__ __align__(16) char smraw[];
    float* tile  = reinterpret_cast<float*>(smraw);
    float* wcomb = reinterpret_cast<float*>(smraw + PG_WOFF);
    float* biasc = reinterpret_cast<float*>(smraw + PG_BOFF);

    const int tid = threadIdx.x;
    const int cg = blockIdx.z;
    const int x0 = blockIdx.x * PT, y0 = blockIdx.y * PT;
    const int cb = cg * 32;

    if (blockIdx.x == 0 && blockIdx.y == 0 && tid < 32)
        h2[cb + tid] = h[cb + tid];

    {
        int c = tid & 31, slot = tid >> 5;
        for (int pix = slot; pix < PTH * PTH; pix += 8) {
            int py = pix / PTH, px = pix - py * PTH;
            int gy = y0 + py - 3, gx = x0 + px - 3;
            float v = 0.f;
            if ((unsigned)gy < (unsigned)HW && (unsigned)gx < (unsigned)HW)
                v = h[(long)(1 + gy * HW + gx) * C + cb + c];
            tile[pix * 32 + c] = v;
        }
    }

    for (int i = tid; i < 49 * 32; i += 256) {
        int k = i >> 5, c = i & 31;
        int dy = k / 7 - 3, dx = k % 7 - 3;
        float w = w7[(cb + c) * 49 + (dy + 3) * 7 + (dx + 3)];
        if (dy >= -2 && dy <= 2 && dx >= -2 && dx <= 2)
            w += w5[(cb + c) * 25 + (dy + 2) * 5 + (dx + 2)];
        if (dy >= -1 && dy <= 1 && dx >= -1 && dx <= 1)
            w += w3[(cb + c) * 9 + (dy + 1) * 3 + (dx + 1)];
        if (dy == 0 && dx == 0) w += 1.f;
        wcomb[i] = w;
    }
    if (tid < 32) biasc[tid] = b7[cb + tid] + b5[cb + tid] + b3[cb + tid];
    __syncthreads();

    const int warp = tid >> 5, c = tid & 31;
    float acc[32];
    #pragma unroll
    for (int p = 0; p < 32; p++) acc[p] = 0.f;

    for (int k = 0; k < 49; k++) {
        float wv = wcomb[k * 32 + c];
        int dy = k / 7, dx = k - (k / 7) * 7;
        int base = ((2 * warp + dy) * PTH + dx) * 32 + c;
        #pragma unroll
        for (int p = 0; p < 32; p++) {
            int py = p >> 4, px = p & 15;
            acc[p] += tile[base + (py * PTH + px) * 32] * wv;
        }
    }

    float bv = biasc[c];
    #pragma unroll
    for (int p = 0; p < 32; p++) {
        int y = y0 + 2 * warp + (p >> 4), x = x0 + (p & 15);
        if (y < HW && x < HW)
            h2[(long)(1 + y * HW + x) * C + cb + c] = acc[p] + bv;
    }
}

// ================= host orchestration =================
struct Ptrs {
    float *h, *h2, *a2, *attn, *outl, *rowsum, *colsum, *fm, *fs, *scale;
    bf16 *xph, *xpl, *qkvh, *qkvl, *qlh, *qll, *klh, *kll,
         *a2h, *a2l, *zh, *zl, *zth, *ztl, *z2h, *z2l, *z2th, *z2tl,
         *xzh, *xzl, *tah, *tal, *tbh, *tbl, *vth, *vtl,
         *a3h, *a3l, *Wth, *Wtl, *ath, *atl,
         *w1ah, *w1al, *w2ah, *w2al, *w1bh, *w1bl, *w2bh, *w2bl;
};
#define GSYM(f, s) cudaGetSymbolAddress((void**)&p.f, s)
static void get_ptrs(Ptrs& p)
{
    GSYM(h, g_h); GSYM(h2, g_h2); GSYM(a2, g_a2);
    GSYM(attn, g_attn); GSYM(outl, g_outl);
    GSYM(rowsum, g_rowsum); GSYM(colsum, g_colsum);
    GSYM(fm, g_fm); GSYM(fs, g_fs); GSYM(scale, g_scale);
    GSYM(xph, g_xph); GSYM(xpl, g_xpl); GSYM(qkvh, g_qkvh); GSYM(qkvl, g_qkvl);
    GSYM(qlh, g_qlh); GSYM(qll, g_qll); GSYM(klh, g_klh); GSYM(kll, g_kll);
    GSYM(a2h, g_a2h); GSYM(a2l, g_a2l);
    GSYM(zh, g_zh); GSYM(zl, g_zl); GSYM(zth, g_zth); GSYM(ztl, g_ztl);
    GSYM(z2h, g_z2h); GSYM(z2l, g_z2l); GSYM(z2th, g_z2th); GSYM(z2tl, g_z2tl);
    GSYM(xzh, g_xzh); GSYM(xzl, g_xzl);
    GSYM(tah, g_tah); GSYM(tal, g_tal); GSYM(tbh, g_tbh); GSYM(tbl, g_tbl);
    GSYM(vth, g_vth); GSYM(vtl, g_vtl); GSYM(a3h, g_a3h); GSYM(a3l, g_a3l);
    GSYM(Wth, g_Wth); GSYM(Wtl, g_Wtl); GSYM(ath, g_ath); GSYM(atl, g_atl);
    GSYM(w1ah, g_w1ah); GSYM(w1al, g_w1al); GSYM(w2ah, g_w2ah); GSYM(w2al, g_w2al);
    GSYM(w1bh, g_w1bh); GSYM(w1bl, g_w1bl); GSYM(w2bh, g_w2bh); GSYM(w2bl, g_w2bl);
}

static void nystrom_tail(Ptrs& p, float* h_io,
                         const bf16* w2h, const bf16* w2l,
                         const float* b_out, const float* res_w)
{
    const long MMh = (long)MM * MM;

    landmarks_k<<<HEADS * MM, DH>>>(p.qkvh, p.qkvl, p.qlh, p.qll, p.klh, p.kll);
    vT_k<<<dim3(NP / 32, HEADS * 2, 2), dim3(32, 8)>>>(p.qkvh, p.qkvl, p.vth, p.vtl);

    { EpiOut e = epi0(); e.f = p.a2; e.falpha = 1.f; e.ldf = MM; e.sF = MMh;
      gemmP(p.qlh, p.qll, p.klh, p.kll, MM, MM, DH, DH, DH,
            (long)MM * DH, (long)MM * DH, HEADS, 1, e); }
    softmax256_k<<<(HEADS * MM + 7) / 8, dim3(32, 8)>>>(p.a2, p.a2, p.a2h, p.a2l, HEADS * MM);

    pinv_sums_k<<<HEADS, 256>>>(p.a2, p.rowsum, p.colsum);
    pinv_scale_k<<<1, 256>>>(p.rowsum, p.colsum, p.scale);
    pinv_init_k<<<(int)((HEADS * MMh + 255) / 256), 256>>>(p.a2, p.scale,
                                                           p.zh, p.zl, p.zth, p.ztl);
    bf16 *zch = p.zh, *zcl = p.zl, *zcth = p.zth, *zctl = p.ztl;
    bf16 *znh = p.z2h, *znl = p.z2l, *znth = p.z2th, *zntl = p.z2tl;
    for (int it = 0; it < 6; it++) {
        { EpiOut e = epi0();
          e.ph = p.xzh; e.pl = p.xzl; e.palpha = 1.f; e.ldp = MM; e.sP = MMh;
          e.th = p.tah; e.tl = p.tal; e.talpha = -1.f; e.tdiag = 7.f; e.ldt = MM; e.sT = MMh;
          gemmP(p.a2h, p.a2l, zcth, zctl, MM, MM, MM, MM, MM, MMh, MMh, HEADS, 1, e); }
        { EpiOut e = epi0();
          e.th = p.tbh; e.tl = p.tbl; e.talpha = -1.f; e.tdiag = 15.f; e.ldt = MM; e.sT = MMh;
          gemmP(p.xzh, p.xzl, p.tah, p.tal, MM, MM, MM, MM, MM, MMh, MMh, HEADS, 1, e); }
        { EpiOut e = epi0();
          e.th = p.tah; e.tl = p.tal; e.talpha = -1.f; e.tdiag = 13.f; e.ldt = MM; e.sT = MMh;
          gemmP(p.xzh, p.xzl, p.tbh, p.tbl, MM, MM, MM, MM, MM, MMh, MMh, HEADS, 1, e); }
        { EpiOut e = epi0();
          e.ph = znh; e.pl = znl; e.palpha = 0.25f; e.ldp = MM; e.sP = MMh;
          e.th = znth; e.tl = zntl; e.talpha = 0.25f; e.tdiag = 0.f; e.ldt = MM; e.sT = MMh;
          gemmP(zch, zcl, p.tah, p.tal, MM, MM, MM, MM, MM, MMh, MMh, HEADS, 1, e); }
        bf16* t;
        t = zch; zch = znh; znh = t;   t = zcl; zcl = znl; znl = t;
        t = zcth; zcth = znth; znth = t; t = zctl; zctl = zntl; zntl = t;
    }

    flash3_k<<<dim3(NSPLIT, 2, HEADS), 128, FL_SMEM>>>(
        p.qlh, p.qll, p.qkvh, p.qkvl, p.vth, p.vtl, p.outl, p.fm, p.fs);
    flash_merge_k<<<dim3(MM, HEADS), DH>>>(p.outl, p.fm, p.fs, p.a3h, p.a3l);

    { EpiOut e = epi0(); e.th = p.Wth; e.tl = p.Wtl; e.talpha = 1.f; e.tdiag = 0.f;
      e.ldt = MM; e.sT = (long)DH * MM;
      gemmP(zch, zcl, p.a3h, p.a3l, MM, DH, MM, MM, MM, MMh, (long)DH * MM, HEADS, 1, e); }

    fused_attn1_k<<<dim3(NP / 64, HEADS), 128, FA_SMEM>>>(
        p.qkvh, p.qkvl, p.klh, p.kll, p.Wth, p.Wtl, p.attn);

    conv_add_k<<<dim3(NP / CA_ROWS, C / 128), 256, CA_SMEM>>>(
        p.qkvh, p.qkvl, res_w, p.attn, p.ath, p.atl);

    { EpiOut e = epi0(); e.f = h_io; e.falpha = 1.f; e.ldf = C;
      e.resid = h_io; e.bias = b_out;
      gemmP(p.ath + (long)PADN * C, p.atl + (long)PADN * C, w2h, w2l,
            NH, C, C, C, C, 0, 0, 1, 1, e); }
}

extern "C" void kernel_launch(void* const* d_in, const int* in_sizes, int n_in,
                              void* d_out, int out_size)
{
    const float* features = (const float*)d_in[0];
    const float* cls      = (const float*)d_in[1];
    const float* ln1_g    = (const float*)d_in[2];
    const float* ln1_b    = (const float*)d_in[3];
    const float* qkv1_w   = (const float*)d_in[4];
    const float* out1_w   = (const float*)d_in[5];
    const float* out1_b   = (const float*)d_in[6];
    const float* res1_w   = (const float*)d_in[7];
    const float* pe_w7    = (const float*)d_in[8];
    const float* pe_b7    = (const float*)d_in[9];
    const float* pe_w5    = (const float*)d_in[10];
    const float* pe_b5    = (const float*)d_in[11];
    const float* pe_w3    = (const float*)d_in[12];
    const float* pe_b3    = (const float*)d_in[13];
    const float* ln2_g    = (const float*)d_in[14];
    const float* ln2_b    = (const float*)d_in[15];
    const float* qkv2_w   = (const float*)d_in[16];
    const float* out2_w   = (const float*)d_in[17];
    const float* out2_b   = (const float*)d_in[18];
    const float* res2_w   = (const float*)d_in[19];

    cudaFuncSetAttribute(gemm_p,  cudaFuncAttributeMaxDynamicSharedMemorySize, GP_SMEM);
    cudaFuncSetAttribute(gemm_p2, cudaFuncAttributeMaxDynamicSharedMemorySize, GP2_SMEM);
    cudaFuncSetAttribute(fused_attn1_k, cudaFuncAttributeMaxDynamicSharedMemorySize, FA_SMEM);
    cudaFuncSetAttribute(flash3_k, cudaFuncAttributeMaxDynamicSharedMemorySize, FL_SMEM);
    cudaFuncSetAttribute(ppeg_k, cudaFuncAttributeMaxDynamicSharedMemorySize, PG_SMEM);
    cudaFuncSetAttribute(conv_add_k, cudaFuncAttributeMaxDynamicSharedMemorySize, CA_SMEM);

    Ptrs p; get_ptrs(p);

    build_h_k<<<(int)(((long)NH * C + 255) / 256), 256>>>(features, cls, p.h);
    wconvT_k<<<(QKVW * C + 255) / 256, 256>>>(qkv1_w, p.w1ah, p.w1al, C, QKVW);
    ln_pad_k<<<NP, 256>>>(p.h, p.xph, p.xpl, ln1_g, ln1_b);
    { EpiOut e = epi0(); e.ph = p.qkvh; e.pl = p.qkvl; e.palpha = 1.f; e.ldp = QKVW;
      gemmP(p.xph, p.xpl, p.w1ah, p.w1al, NP, QKVW, C, C, C, 0, 0, 1, 1, e); }

    wconvT_k<<<(C * C + 255) / 256, 256>>>(out1_w, p.w2ah, p.w2al, C, C);
    wconvT_k<<<(QKVW * C + 255) / 256, 256>>>(qkv2_w, p.w1bh, p.w1bl, C, QKVW);
    wconvT_k<<<(C * C + 255) / 256, 256>>>(out2_w, p.w2bh, p.w2bl, C, C);

    nystrom_tail(p, p.h, p.w2ah, p.w2al, out1_b, res1_w);

    ppeg_k<<<dim3((HW + PT - 1) / PT, (HW + PT - 1) / PT, 16), 256, PG_SMEM>>>(
        p.h, p.h2, pe_w7, pe_b7, pe_w5, pe_b5, pe_w3, pe_b3);

    ln_pad_k<<<NP, 256>>>(p.h2, p.xph, p.xpl, ln2_g, ln2_b);
    { EpiOut e = epi0(); e.ph = p.qkvh; e.pl = p.qkvl; e.palpha = 1.f; e.ldp = QKVW;
      gemmP(p.xph, p.xpl, p.w1bh, p.w1bl, NP, QKVW, C, C, C, 0, 0, 1, 1, e); }
    nystrom_tail(p, p.h2, p.w2bh, p.w2bl, out2_b, res2_w);

    cudaMemcpyAsync(d_out, p.h2, (size_t)out_size * sizeof(float),
                    cudaMemcpyDeviceToDevice);
}

// round 16
// speedup vs baseline: 1.4881x; 1.0101x over previous
#include <cuda_runtime.h>
#include <cuda_bf16.h>
#include <math.h>
#include <stdint.h>

typedef __nv_bfloat16 bf16;

// ---------------- problem constants ----------------
#define NH    22501
#define NFEAT 22400
#define HW    150
#define C     512
#define NP    22528
#define PADN  27
#define HEADS 8
#define DH    64
#define MM    256
#define LL    88
#define QKVW  1536
#define NSPLIT 16

// ---------------- fp32 scratch ----------------
__device__ float g_h   [(long)NH*C];
__device__ float g_h2  [(long)NH*C];
__device__ float g_a2  [HEADS*MM*MM];
__device__ float g_attn[(long)NP*C];
__device__ float g_outl[(long)NH*C];
__device__ float g_rowsum[HEADS*MM];
__device__ float g_colsum[HEADS*MM];
__device__ float g_fm[NSPLIT*HEADS*MM];
__device__ float g_fs[NSPLIT*HEADS*MM];
__device__ float g_scale[1];

// ---------------- bf16 hi/lo pair scratch ----------------
__device__ bf16 g_xph[(long)NP*C],     g_xpl[(long)NP*C];
__device__ bf16 g_qkvh[(long)NP*QKVW], g_qkvl[(long)NP*QKVW];
__device__ bf16 g_qlh[HEADS*MM*DH],    g_qll[HEADS*MM*DH];
__device__ bf16 g_klh[HEADS*MM*DH],    g_kll[HEADS*MM*DH];
__device__ bf16 g_a2h[HEADS*MM*MM],    g_a2l[HEADS*MM*MM];
__device__ bf16 g_zh [HEADS*MM*MM], g_zl [HEADS*MM*MM];
__device__ bf16 g_zth[HEADS*MM*MM], g_ztl[HEADS*MM*MM];
__device__ bf16 g_z2h[HEADS*MM*MM], g_z2l[HEADS*MM*MM];
__device__ bf16 g_z2th[HEADS*MM*MM], g_z2tl[HEADS*MM*MM];
__device__ bf16 g_xzh[HEADS*MM*MM], g_xzl[HEADS*MM*MM];
__device__ bf16 g_tah[HEADS*MM*MM], g_tal[HEADS*MM*MM];
__device__ bf16 g_tbh[HEADS*MM*MM], g_tbl[HEADS*MM*MM];
__device__ bf16 g_vth[(long)HEADS*DH*NP], g_vtl[(long)HEADS*DH*NP];
__device__ bf16 g_a3h[HEADS*DH*MM],    g_a3l[HEADS*DH*MM];
__device__ bf16 g_Wth[HEADS*DH*MM],    g_Wtl[HEADS*DH*MM];
__device__ bf16 g_ath[(long)NP*C],     g_atl[(long)NP*C];
__device__ bf16 g_w1ah[(long)QKVW*C],  g_w1al[(long)QKVW*C];
__device__ bf16 g_w2ah[(long)C*C],     g_w2al[(long)C*C];
__device__ bf16 g_w1bh[(long)QKVW*C],  g_w1bl[(long)QKVW*C];
__device__ bf16 g_w2bh[(long)C*C],     g_w2bl[(long)C*C];

// ---------------- small device helpers ----------------
__device__ __forceinline__ uint32_t smem_to_u32(const void* p) {
    uint32_t a;
    asm("{ .reg .u64 t; cvta.to.shared.u64 t, %1; cvt.u32.u64 %0, t; }"
        : "=r"(a) : "l"(p));
    return a;
}
__device__ __forceinline__ void ldsm4(uint32_t addr, uint32_t& r0, uint32_t& r1,
                                      uint32_t& r2, uint32_t& r3)
{
    asm volatile("ldmatrix.sync.aligned.m8n8.x4.shared.b16 {%0,%1,%2,%3}, [%4];"
                 : "=r"(r0), "=r"(r1), "=r"(r2), "=r"(r3) : "r"(addr));
}
__device__ __forceinline__ void mma_bf16(float* c, const uint32_t* a,
                                         uint32_t b0, uint32_t b1)
{
    asm volatile("mma.sync.aligned.m16n8k16.row.col.f32.bf16.bf16.f32 "
                 "{%0,%1,%2,%3},{%4,%5,%6,%7},{%8,%9},{%0,%1,%2,%3};"
                 : "+f"(c[0]), "+f"(c[1]), "+f"(c[2]), "+f"(c[3])
                 : "r"(a[0]), "r"(a[1]), "r"(a[2]), "r"(a[3]), "r"(b0), "r"(b1));
}
__device__ __forceinline__ void cpa16(uint32_t dst, const void* src, int sz)
{
    asm volatile("cp.async.cg.shared.global [%0], [%1], 16, %2;"
                 :: "r"(dst), "l"(src), "r"(sz));
}
__device__ __forceinline__ uint32_t pack2(float a, float b)   // a->low, b->high
{
    uint32_t r;
    asm("cvt.rn.bf16x2.f32 %0, %1, %2;" : "=r"(r) : "f"(b), "f"(a));
    return r;
}
__device__ __forceinline__ void split_bf(float x, float& hi, float& lo)
{
    hi = __bfloat162float(__float2bfloat16(x));
    lo = x - hi;
}
__device__ __forceinline__ float pairval(const bf16* h, const bf16* l, long i)
{
    return __bfloat162float(h[i]) + __bfloat162float(l[i]);
}

struct EpiOut {
    float* f; float falpha; int ldf; long sF;
    bf16 *ph, *pl; float palpha; int ldp; long sP;
    bf16 *th, *tl; float talpha, tdiag; int ldt; long sT;
    const float* resid;
    const float* bias;
};

__device__ __forceinline__ void epi_write(const EpiOut& ep, float* F,
                                          bf16* Ph, bf16* Pl, bf16* Th, bf16* Tl,
                                          int gr, int gc, float va, float vb)
{
    if (F) {
        float o0 = ep.falpha * va, o1 = ep.falpha * vb;
        if (ep.bias)  { o0 += ep.bias[gc]; o1 += ep.bias[gc + 1]; }
        if (ep.resid) {
            o0 += ep.resid[(long)gr * ep.ldf + gc];
            o1 += ep.resid[(long)gr * ep.ldf + gc + 1];
        }
        *reinterpret_cast<float2*>(F + (long)gr * ep.ldf + gc) = make_float2(o0, o1);
    }
    if (Ph) {
        float s0 = ep.palpha * va, s1 = ep.palpha * vb;
        float h0, l0, h1, l1;
        split_bf(s0, h0, l0); split_bf(s1, h1, l1);
        *reinterpret_cast<uint32_t*>(Ph + (long)gr * ep.ldp + gc) = pack2(h0, h1);
        *reinterpret_cast<uint32_t*>(Pl + (long)gr * ep.ldp + gc) = pack2(l0, l1);
    }
    if (Th) {
        #pragma unroll
        for (int j = 0; j < 2; j++) {
            int cc = gc + j;
            float v = (j == 0) ? va : vb;
            float s = ep.talpha * v + ((gr == cc) ? ep.tdiag : 0.f);
            float hi, lo; split_bf(s, hi, lo);
            Th[(long)cc * ep.ldt + gr] = __float2bfloat16(hi);
            Tl[(long)cc * ep.ldt + gr] = __float2bfloat16(lo);
        }
    }
}

// =======================================================================
// gemm_p: 128x64x32 tile, 3-stage, 8 warps (4m x 2n), warp 32x32.
// =======================================================================
#define RS      80
#define AH_OFF  0
#define AL_OFF  10240
#define BH_OFF  20480
#define BL_OFF  25600
#define STAGE   30720
#define GP_SMEM (3 * STAGE)

__global__ void __launch_bounds__(256, 2)
gemm_p(const bf16* __restrict__ Ah, const bf16* __restrict__ Al,
       const bf16* __restrict__ Bh, const bf16* __restrict__ Bl,
       int M, int K, int lda, int ldb, long sA, long sB,
       EpiOut ep, int ksplit)
{
    extern __shared__ __align__(16) char sm[];
    const uint32_t sb0 = smem_to_u32(sm);
    const int tid = threadIdx.x, warp = tid >> 5, lane = tid & 31;
    const int wm = warp & 3, wn = warp >> 2;

    const int z = blockIdx.z;
    const int batch = z / ksplit;
    Ah += (long)batch * sA;  Al += (long)batch * sA;
    Bh += (long)batch * sB;  Bl += (long)batch * sB;

    const int row0 = blockIdx.y * 128, col0 = blockIdx.x * 64;
    const int nch = K >> 5;

    float acc[2][4][4];
    #pragma unroll
    for (int i = 0; i < 2; i++)
        #pragma unroll
        for (int j = 0; j < 4; j++)
            #pragma unroll
            for (int q = 0; q < 4; q++) acc[i][j][q] = 0.f;

    auto issue = [&](int it) {
        const int stg = it % 3;
        const uint32_t sb = sb0 + stg * STAGE;
        const int kc = it * 32;
        #pragma unroll
        for (int rep = 0; rep < 2; rep++) {
            int c = tid + rep * 256;
            int row = c >> 2, seg = c & 3;
            int gm = row0 + row;
            long go = (long)gm * lda + kc + seg * 8;
            int sz = (gm < M) ? 16 : 0;
            cpa16(sb + AH_OFF + row * RS + seg * 16, Ah + go, sz);
            cpa16(sb + AL_OFF + row * RS + seg * 16, Al + go, sz);
        }
        {
            int n = tid >> 2, seg = tid & 3;
            long go = (long)(col0 + n) * ldb + kc + seg * 8;
            cpa16(sb + BH_OFF + n * RS + seg * 16, Bh + go, 16);
            cpa16(sb + BL_OFF + n * RS + seg * 16, Bl + go, 16);
        }
        asm volatile("cp.async.commit_group;");
    };

    const int rsel = (lane & 7) + ((lane >> 3) & 1) * 8;
    const int ksel = ((lane >> 4) & 1) * 16;
    auto do_mma = [&](int stg) {
        uint32_t sb = sb0 + stg * STAGE;
        #pragma unroll
        for (int kk = 0; kk < 2; kk++) {
            uint32_t ah[2][4], al[2][4];
            #pragma unroll
            for (int mt = 0; mt < 2; mt++) {
                uint32_t ad = sb + AH_OFF + (wm * 32 + mt * 16 + rsel) * RS + kk * 32 + ksel;
                ldsm4(ad, ah[mt][0], ah[mt][1], ah[mt][2], ah[mt][3]);
                ldsm4(ad + (AL_OFF - AH_OFF), al[mt][0], al[mt][1], al[mt][2], al[mt][3]);
            }
            #pragma unroll
            for (int np = 0; np < 2; np++) {
                uint32_t bd = sb + BH_OFF + (wn * 32 + np * 16 + rsel) * RS + kk * 32 + ksel;
                uint32_t q0, q1, q2, q3, r0, r1, r2, r3;
                ldsm4(bd, q0, q1, q2, q3);
                ldsm4(bd + (BL_OFF - BH_OFF), r0, r1, r2, r3);
                #pragma unroll
                for (int mt = 0; mt < 2; mt++) {
                    mma_bf16(acc[mt][2*np],   ah[mt], q0, q2);
                    mma_bf16(acc[mt][2*np],   ah[mt], r0, r2);
                    mma_bf16(acc[mt][2*np],   al[mt], q0, q2);
                    mma_bf16(acc[mt][2*np+1], ah[mt], q1, q3);
                    mma_bf16(acc[mt][2*np+1], ah[mt], r1, r3);
                    mma_bf16(acc[mt][2*np+1], al[mt], q1, q3);
                }
            }
        }
    };

    issue(0);
    if (nch > 1) issue(1);
    for (int it = 0; it < nch; it++) {
        if (it + 1 < nch) asm volatile("cp.async.wait_group 1;");
        else              asm volatile("cp.async.wait_group 0;");
        __syncthreads();
        if (it + 2 < nch) issue(it + 2);
        do_mma(it % 3);
    }

    const int er = lane >> 2, eq = lane & 3;
    float* F  = ep.f  ? ep.f  + (long)z     * ep.sF : (float*)0;
    bf16* Ph  = ep.ph ? ep.ph + (long)batch * ep.sP : (bf16*)0;
    bf16* Pl  = ep.pl ? ep.pl + (long)batch * ep.sP : (bf16*)0;
    bf16* Th  = ep.th ? ep.th + (long)batch * ep.sT : (bf16*)0;
    bf16* Tl  = ep.tl ? ep.tl + (long)batch * ep.sT : (bf16*)0;

    #pragma unroll
    for (int mt = 0; mt < 2; mt++)
        #pragma unroll
        for (int nt = 0; nt < 4; nt++) {
            int gr0 = row0 + wm * 32 + mt * 16 + er;
            int gc  = col0 + wn * 32 + nt * 8 + 2 * eq;
            #pragma unroll
            for (int half = 0; half < 2; half++) {
                int gr = gr0 + 8 * half;
                if (gr >= M) continue;
                epi_write(ep, F, Ph, Pl, Th, Tl, gr, gc,
                          acc[mt][nt][2 * half], acc[mt][nt][2 * half + 1]);
            }
        }
}

// =======================================================================
// gemm_p2: 256x64x32 tile, 2-stage, 8 warps (4m x 2n), warp 64x32.
// =======================================================================
#define P2_AH   0
#define P2_AL   20480
#define P2_BH   40960
#define P2_BL   46080
#define P2_STG  51200
#define GP2_SMEM (2 * P2_STG)

__global__ void __launch_bounds__(256, 2)
gemm_p2(const bf16* __restrict__ Ah, const bf16* __restrict__ Al,
        const bf16* __restrict__ Bh, const bf16* __restrict__ Bl,
        int M, int K, int lda, int ldb,
        EpiOut ep)
{
    extern __shared__ __align__(16) char sm[];
    const uint32_t sb0 = smem_to_u32(sm);
    const int tid = threadIdx.x, warp = tid >> 5, lane = tid & 31;
    const int wm = warp & 3, wn = warp >> 2;

    const int row0 = blockIdx.y * 256, col0 = blockIdx.x * 64;
    const int nch = K >> 5;

    float acc[4][4][4];
    #pragma unroll
    for (int i = 0; i < 4; i++)
        #pragma unroll
        for (int j = 0; j < 4; j++)
            #pragma unroll
            for (int q = 0; q < 4; q++) acc[i][j][q] = 0.f;

    auto issue = [&](int it) {
        const uint32_t sb = sb0 + (it & 1) * P2_STG;
        const int kc = it * 32;
        #pragma unroll
        for (int rep = 0; rep < 4; rep++) {
            int c = tid + rep * 256;
            int row = c >> 2, seg = c & 3;
            int gm = row0 + row;
            long go = (long)gm * lda + kc + seg * 8;
            int sz = (gm < M) ? 16 : 0;
            cpa16(sb + P2_AH + row * RS + seg * 16, Ah + go, sz);
            cpa16(sb + P2_AL + row * RS + seg * 16, Al + go, sz);
        }
        {
            int n = tid >> 2, seg = tid & 3;
            long go = (long)(col0 + n) * ldb + kc + seg * 8;
            cpa16(sb + P2_BH + n * RS + seg * 16, Bh + go, 16);
            cpa16(sb + P2_BL + n * RS + seg * 16, Bl + go, 16);
        }
        asm volatile("cp.async.commit_group;");
    };

    const int rsel = (lane & 7) + ((lane >> 3) & 1) * 8;
    const int ksel = ((lane >> 4) & 1) * 16;
    auto do_mma = [&](int stg) {
        uint32_t sb = sb0 + stg * P2_STG;
        #pragma unroll
        for (int kk = 0; kk < 2; kk++) {
            uint32_t ah[4][4], al[4][4];
            #pragma unroll
            for (int mt = 0; mt < 4; mt++) {
                uint32_t ad = sb + P2_AH + (wm * 64 + mt * 16 + rsel) * RS + kk * 32 + ksel;
                ldsm4(ad, ah[mt][0], ah[mt][1], ah[mt][2], ah[mt][3]);
                ldsm4(ad + (P2_AL - P2_AH), al[mt][0], al[mt][1], al[mt][2], al[mt][3]);
            }
            #pragma unroll
            for (int np = 0; np < 2; np++) {
                uint32_t bd = sb + P2_BH + (wn * 32 + np * 16 + rsel) * RS + kk * 32 + ksel;
                uint32_t q0, q1, q2, q3, r0, r1, r2, r3;
                ldsm4(bd, q0, q1, q2, q3);
                ldsm4(bd + (P2_BL - P2_BH), r0, r1, r2, r3);
                #pragma unroll
                for (int mt = 0; mt < 4; mt++) {
                    mma_bf16(acc[mt][2*np],   ah[mt], q0, q2);
                    mma_bf16(acc[mt][2*np],   ah[mt], r0, r2);
                    mma_bf16(acc[mt][2*np],   al[mt], q0, q2);
                    mma_bf16(acc[mt][2*np+1], ah[mt], q1, q3);
                    mma_bf16(acc[mt][2*np+1], ah[mt], r1, r3);
                    mma_bf16(acc[mt][2*np+1], al[mt], q1, q3);
                }
            }
        }
    };

    issue(0);
    for (int it = 0; it < nch; it++) {
        if (it + 1 < nch) { issue(it + 1); asm volatile("cp.async.wait_group 1;"); }
        else              { asm volatile("cp.async.wait_group 0;"); }
        __syncthreads();
        do_mma(it & 1);
        __syncthreads();
    }

    const int er = lane >> 2, eq = lane & 3;
    float* F  = ep.f;
    bf16* Ph  = ep.ph;  bf16* Pl = ep.pl;
    bf16* Th  = ep.th;  bf16* Tl = ep.tl;

    #pragma unroll
    for (int mt = 0; mt < 4; mt++)
        #pragma unroll
        for (int nt = 0; nt < 4; nt++) {
            int gr0 = row0 + wm * 64 + mt * 16 + er;
            int gc  = col0 + wn * 32 + nt * 8 + 2 * eq;
            #pragma unroll
            for (int half = 0; half < 2; half++) {
                int gr = gr0 + 8 * half;
                if (gr >= M) continue;
                epi_write(ep, F, Ph, Pl, Th, Tl, gr, gc,
                          acc[mt][nt][2 * half], acc[mt][nt][2 * half + 1]);
            }
        }
}

static EpiOut epi0() { EpiOut e{}; return e; }
static void gemmP(const bf16* Ah, const bf16* Al, const bf16* Bh, const bf16* Bl,
                  int M, int N, int K, int lda, int ldb, long sA, long sB,
                  int batch, int ksplit, EpiOut ep)
{
    if (batch == 1 && M >= 512) {
        dim3 g(N / 64, (M + 255) / 256, 1), b(256);
        gemm_p2<<<g, b, GP2_SMEM>>>(Ah, Al, Bh, Bl, M, K, lda, ldb, ep);
    } else {
        dim3 g(N / 64, (M + 127) / 128, batch * ksplit), b(256);
        gemm_p<<<g, b, GP_SMEM>>>(Ah, Al, Bh, Bl, M, K, lda, ldb, sA, sB, ep, ksplit);
    }
}

// =======================================================================
// flash-fused S3 path (R12-proven: NSPLIT=16, 64-token chunks, 147KB smem)
// =======================================================================
#define FL_RS   144
#define FL_QH   0
#define FL_QL   18432
#define FL_K(b) (36864 + (b) * 18432)
#define FL_V(b) (73728 + (b) * 18432)
#define FL_PH   110592
#define FL_PL   129024
#define FL_SMEM 147456
#define FL_NCH  ((NP / NSPLIT) / 64)      // 22

__global__ void __launch_bounds__(128)
flash3_k(const bf16* __restrict__ qlh, const bf16* __restrict__ qll,
         const bf16* __restrict__ qkvh, const bf16* __restrict__ qkvl,
         const bf16* __restrict__ vth, const bf16* __restrict__ vtl,
         float* __restrict__ pO, float* __restrict__ pm, float* __restrict__ ps)
{
    extern __shared__ __align__(16) char sm[];
    const uint32_t sb = smem_to_u32(sm);
    const int tid = threadIdx.x, warp = tid >> 5, lane = tid & 31;
    const int split = blockIdx.x, rowHalf = blockIdx.y, head = blockIdx.z;
    const int tb0 = split * (NP / NSPLIT);

    const bf16* Qh = qlh + ((long)head * MM + rowHalf * 128) * DH;
    const bf16* Ql = qll + ((long)head * MM + rowHalf * 128) * DH;
    #pragma unroll
    for (int i = 0; i < 8; i++) {
        int s = tid + 128 * i;
        int r = s >> 3, seg = s & 7;
        long go = (long)r * DH + seg * 8;
        cpa16(sb + FL_QH + r * FL_RS + seg * 16, Qh + go, 16);
        cpa16(sb + FL_QL + r * FL_RS + seg * 16, Ql + go, 16);
    }

    const bf16* Kh = qkvh + head * DH + 512;
    const bf16* Kl = qkvl + head * DH + 512;
    const bf16* Vh = vth + (long)head * DH * NP;
    const bf16* Vl = vtl + (long)head * DH * NP;

    auto kissue = [&](int j) {
        int buf = j & 1;
        int tb = tb0 + j * 64;
        uint32_t kb = sb + FL_K(buf);
        uint32_t vb = sb + FL_V(buf);
        #pragma unroll
        for (int i = 0; i < 4; i++) {
            int s = tid + 128 * i;
            int r = s >> 3, seg = s & 7;
            long gk = (long)(tb + r) * QKVW + seg * 8;
            cpa16(kb + r * FL_RS + seg * 16, Kh + gk, 16);
            cpa16(kb + 9216 + r * FL_RS + seg * 16, Kl + gk, 16);
            long gv = (long)r * NP + tb + seg * 8;
            cpa16(vb + r * FL_RS + seg * 16, Vh + gv, 16);
            cpa16(vb + 9216 + r * FL_RS + seg * 16, Vl + gv, 16);
        }
        asm volatile("cp.async.commit_group;");
    };
    kissue(0);
    kissue(1);

    const int rsel = (lane & 7) + ((lane >> 3) & 1) * 8;
    const int ksel = ((lane >> 4) & 1) * 16;
    const int er = lane >> 2, eq = lane & 3;

    float m_run[4] = {-1e30f, -1e30f, -1e30f, -1e30f};
    float s_run[4] = {0.f, 0.f, 0.f, 0.f};
    float oacc[2][8][4];
    #pragma unroll
    for (int a = 0; a < 2; a++)
        #pragma unroll
        for (int b = 0; b < 8; b++)
            #pragma unroll
            for (int c = 0; c < 4; c++) oacc[a][b][c] = 0.f;

    for (int j = 0; j < FL_NCH; j++) {
        if (j + 1 < FL_NCH) asm volatile("cp.async.wait_group 1;");
        else                asm volatile("cp.async.wait_group 0;");
        __syncthreads();
        uint32_t kb = sb + FL_K(j & 1);
        uint32_t vb = sb + FL_V(j & 1);

        float sacc[2][8][4];
        #pragma unroll
        for (int a = 0; a < 2; a++)
            #pragma unroll
            for (int b = 0; b < 8; b++)
                #pragma unroll
                for (int c = 0; c < 4; c++) sacc[a][b][c] = 0.f;

        #pragma unroll
        for (int k16 = 0; k16 < 4; k16++) {
            uint32_t ah[2][4], al[2][4];
            #pragma unroll
            for (int mt = 0; mt < 2; mt++) {
                uint32_t ad = sb + FL_QH + (warp * 32 + mt * 16 + rsel) * FL_RS + k16 * 32 + ksel;
                ldsm4(ad, ah[mt][0], ah[mt][1], ah[mt][2], ah[mt][3]);
                ldsm4(ad + (FL_QL - FL_QH), al[mt][0], al[mt][1], al[mt][2], al[mt][3]);
            }
            #pragma unroll
            for (int n16 = 0; n16 < 4; n16++) {
                uint32_t bd = kb + (n16 * 16 + rsel) * FL_RS + k16 * 32 + ksel;
                uint32_t q0, q1, q2, q3, p0, p1, p2, p3;
                ldsm4(bd, q0, q1, q2, q3);
                ldsm4(bd + 9216, p0, p1, p2, p3);
                #pragma unroll
                for (int mt = 0; mt < 2; mt++) {
                    mma_bf16(sacc[mt][2*n16],   ah[mt], q0, q2);
                    mma_bf16(sacc[mt][2*n16],   ah[mt], p0, p2);
                    mma_bf16(sacc[mt][2*n16],   al[mt], q0, q2);
                    mma_bf16(sacc[mt][2*n16+1], ah[mt], q1, q3);
                    mma_bf16(sacc[mt][2*n16+1], ah[mt], p1, p3);
                    mma_bf16(sacc[mt][2*n16+1], al[mt], q1, q3);
                }
            }
        }

        #pragma unroll
        for (int mt = 0; mt < 2; mt++) {
            float cm0 = -1e30f, cm1 = -1e30f;
            #pragma unroll
            for (int nt = 0; nt < 8; nt++) {
                cm0 = fmaxf(cm0, fmaxf(sacc[mt][nt][0], sacc[mt][nt][1]));
                cm1 = fmaxf(cm1, fmaxf(sacc[mt][nt][2], sacc[mt][nt][3]));
            }
            #pragma unroll
            for (int o = 1; o <= 2; o <<= 1) {
                cm0 = fmaxf(cm0, __shfl_xor_sync(0xffffffffu, cm0, o));
                cm1 = fmaxf(cm1, __shfl_xor_sync(0xffffffffu, cm1, o));
            }
            float mn0 = fmaxf(m_run[2*mt],     cm0);
            float mn1 = fmaxf(m_run[2*mt + 1], cm1);
            float sc0 = __expf(m_run[2*mt]     - mn0);
            float sc1 = __expf(m_run[2*mt + 1] - mn1);
            m_run[2*mt] = mn0; m_run[2*mt + 1] = mn1;
            float ls0 = 0.f, ls1 = 0.f;
            int pr = warp * 32 + mt * 16 + er;
            #pragma unroll
            for (int nt = 0; nt < 8; nt++) {
                float e0 = __expf(sacc[mt][nt][0] - mn0);
                float e1 = __expf(sacc[mt][nt][1] - mn0);
                float e2 = __expf(sacc[mt][nt][2] - mn1);
                float e3 = __expf(sacc[mt][nt][3] - mn1);
                ls0 += e0 + e1; ls1 += e2 + e3;
                oacc[mt][nt][0] *= sc0; oacc[mt][nt][1] *= sc0;
                oacc[mt][nt][2] *= sc1; oacc[mt][nt][3] *= sc1;
                int col = nt * 8 + 2 * eq;
                float h0, l0, h1, l1;
                split_bf(e0, h0, l0); split_bf(e1, h1, l1);
                *reinterpret_cast<uint32_t*>(sm + FL_PH + pr * FL_RS + col * 2) = pack2(h0, h1);
                *reinterpret_cast<uint32_t*>(sm + FL_PL + pr * FL_RS + col * 2) = pack2(l0, l1);
                split_bf(e2, h0, l0); split_bf(e3, h1, l1);
                *reinterpret_cast<uint32_t*>(sm + FL_PH + (pr + 8) * FL_RS + col * 2) = pack2(h0, h1);
                *reinterpret_cast<uint32_t*>(sm + FL_PL + (pr + 8) * FL_RS + col * 2) = pack2(l0, l1);
            }
            #pragma unroll
            for (int o = 1; o <= 2; o <<= 1) {
                ls0 += __shfl_xor_sync(0xffffffffu, ls0, o);
                ls1 += __shfl_xor_sync(0xffffffffu, ls1, o);
            }
            s_run[2*mt]     = s_run[2*mt]     * sc0 + ls0;
            s_run[2*mt + 1] = s_run[2*mt + 1] * sc1 + ls1;
        }
        __syncthreads();

        #pragma unroll
        for (int k16 = 0; k16 < 4; k16++) {
            uint32_t ph[2][4], pl[2][4];
            #pragma unroll
            for (int mt = 0; mt < 2; mt++) {
                uint32_t ad = sb + FL_PH + (warp * 32 + mt * 16 + rsel) * FL_RS + k16 * 32 + ksel;
                ldsm4(ad, ph[mt][0], ph[mt][1], ph[mt][2], ph[mt][3]);
                ldsm4(ad + (FL_PL - FL_PH), pl[mt][0], pl[mt][1], pl[mt][2], pl[mt][3]);
            }
            #pragma unroll
            for (int n16 = 0; n16 < 4; n16++) {
                uint32_t bd = vb + (n16 * 16 + rsel) * FL_RS + k16 * 32 + ksel;
                uint32_t q0, q1, q2, q3, r0, r1, r2, r3;
                ldsm4(bd, q0, q1, q2, q3);
                ldsm4(bd + 9216, r0, r1, r2, r3);
                #pragma unroll
                for (int mt = 0; mt < 2; mt++) {
                    mma_bf16(oacc[mt][2*n16],   ph[mt], q0, q2);
                    mma_bf16(oacc[mt][2*n16],   ph[mt], r0, r2);
                    mma_bf16(oacc[mt][2*n16],   pl[mt], q0, q2);
                    mma_bf16(oacc[mt][2*n16+1], ph[mt], q1, q3);
                    mma_bf16(oacc[mt][2*n16+1], ph[mt], r1, r3);
                    mma_bf16(oacc[mt][2*n16+1], pl[mt], q1, q3);
                }
            }
        }
        __syncthreads();
        if (j + 2 < FL_NCH) kissue(j + 2);
    }

    const int base = (split * HEADS + head) * MM + rowHalf * 128;
    #pragma unroll
    for (int mt = 0; mt < 2; mt++) {
        int r0 = base + warp * 32 + mt * 16 + er;
        #pragma unroll
        for (int nt = 0; nt < 8; nt++) {
            int d = nt * 8 + 2 * eq;
            *reinterpret_cast<float2*>(pO + (long)r0 * DH + d) =
                make_float2(oacc[mt][nt][0], oacc[mt][nt][1]);
            *reinterpret_cast<float2*>(pO + (long)(r0 + 8) * DH + d) =
                make_float2(oacc[mt][nt][2], oacc[mt][nt][3]);
        }
        if (eq == 0) {
            pm[r0] = m_run[2*mt];     ps[r0] = s_run[2*mt];
            pm[r0 + 8] = m_run[2*mt + 1]; ps[r0 + 8] = s_run[2*mt + 1];
        }
    }
}

__global__ void flash_merge_k(const float* __restrict__ pO, const float* __restrict__ pm,
                              const float* __restrict__ ps,
                              bf16* __restrict__ oh, bf16* __restrict__ ol)
{
    int row = blockIdx.x, head = blockIdx.y, d = threadIdx.x;
    float mx = -1e30f;
    #pragma unroll
    for (int i = 0; i < NSPLIT; i++)
        mx = fmaxf(mx, pm[(i * HEADS + head) * MM + row]);
    float den = 0.f, acc = 0.f;
    #pragma unroll
    for (int i = 0; i < NSPLIT; i++) {
        int r = (i * HEADS + head) * MM + row;
        float w = __expf(pm[r] - mx);
        den += w * ps[r];
        acc += w * pO[(long)r * DH + d];
    }
    float v = acc / den;
    float hi, lo; split_bf(v, hi, lo);
    long o = ((long)head << 14) + d * MM + row;
    oh[o] = __float2bfloat16(hi);
    ol[o] = __float2bfloat16(lo);
}

// =======================================================================
// fused S1 -> softmax -> O1
// =======================================================================
#define FA_RS1  144
#define FA_AH   0
#define FA_AL   9216
#define FA_BH   18432
#define FA_BL   55296
#define FA_PH   0
#define FA_PL   33792
#define FA_WS   67584
#define FA_WST  10240
#define FA_SMEM 98304

__global__ void __launch_bounds__(128)
fused_attn1_k(const bf16* __restrict__ qh, const bf16* __restrict__ ql_,
              const bf16* __restrict__ klh, const bf16* __restrict__ kll,
              const bf16* __restrict__ Wth, const bf16* __restrict__ Wtl,
              float* __restrict__ attn)
{
    extern __shared__ __align__(16) char sm[];
    const uint32_t sb = smem_to_u32(sm);
    const int tid = threadIdx.x, warp = tid >> 5, lane = tid & 31;
    const int row0 = blockIdx.x * 64;
    const int head = blockIdx.y;

    const bf16* qsh = qh  + (long)row0 * QKVW + head * DH;
    const bf16* qsl = ql_ + (long)row0 * QKVW + head * DH;
    #pragma unroll
    for (int i = 0; i < 4; i++) {
        int s = tid + 128 * i;
        int r = s >> 3, seg = s & 7;
        long go = (long)r * QKVW + seg * 8;
        cpa16(sb + FA_AH + r * FA_RS1 + seg * 16, qsh + go, 16);
        cpa16(sb + FA_AL + r * FA_RS1 + seg * 16, qsl + go, 16);
    }
    const bf16* ksh = klh + (long)head * MM * DH;
    const bf16* ksl = kll + (long)head * MM * DH;
    #pragma unroll
    for (int i = 0; i < 16; i++) {
        int s = tid + 128 * i;
        int r = s >> 3, seg = s & 7;
        long go = (long)r * DH + seg * 8;
        cpa16(sb + FA_BH + r * FA_RS1 + seg * 16, ksh + go, 16);
        cpa16(sb + FA_BL + r * FA_RS1 + seg * 16, ksl + go, 16);
    }
    asm volatile("cp.async.commit_group;");
    asm volatile("cp.async.wait_group 0;");
    __syncthreads();

    const int rsel = (lane & 7) + ((lane >> 3) & 1) * 8;
    const int ksel = ((lane >> 4) & 1) * 16;
    float sacc[32][4];
    #pragma unroll
    for (int i = 0; i < 32; i++)
        #pragma unroll
        for (int j = 0; j < 4; j++) sacc[i][j] = 0.f;

    #pragma unroll
    for (int k16 = 0; k16 < 4; k16++) {
        uint32_t ah[4], al[4];
        uint32_t ad = sb + FA_AH + (warp * 16 + rsel) * FA_RS1 + k16 * 32 + ksel;
        ldsm4(ad, ah[0], ah[1], ah[2], ah[3]);
        ldsm4(ad + (FA_AL - FA_AH), al[0], al[1], al[2], al[3]);
        #pragma unroll
        for (int n16 = 0; n16 < 16; n16++) {
            uint32_t bd = sb + FA_BH + (n16 * 16 + rsel) * FA_RS1 + k16 * 32 + ksel;
            uint32_t q0, q1, q2, q3, p0, p1, p2, p3;
            ldsm4(bd, q0, q1, q2, q3);
            ldsm4(bd + (FA_BL - FA_BH), p0, p1, p2, p3);
            mma_bf16(sacc[2*n16],   ah, q0, q2);
            mma_bf16(sacc[2*n16],   ah, p0, p2);
            mma_bf16(sacc[2*n16],   al, q0, q2);
            mma_bf16(sacc[2*n16+1], ah, q1, q3);
            mma_bf16(sacc[2*n16+1], ah, p1, p3);
            mma_bf16(sacc[2*n16+1], al, q1, q3);
        }
    }

    float mx0 = -1e30f, mx1 = -1e30f;
    #pragma unroll
    for (int nt = 0; nt < 32; nt++) {
        #pragma unroll
        for (int j = 0; j < 4; j++) sacc[nt][j] *= 0.125f;
        mx0 = fmaxf(mx0, fmaxf(sacc[nt][0], sacc[nt][1]));
        mx1 = fmaxf(mx1, fmaxf(sacc[nt][2], sacc[nt][3]));
    }
    #pragma unroll
    for (int o = 1; o <= 2; o <<= 1) {
        mx0 = fmaxf(mx0, __shfl_xor_sync(0xffffffffu, mx0, o));
        mx1 = fmaxf(mx1, __shfl_xor_sync(0xffffffffu, mx1, o));
    }
    float sm0 = 0.f, sm1 = 0.f;
    #pragma unroll
    for (int nt = 0; nt < 32; nt++) {
        sacc[nt][0] = __expf(sacc[nt][0] - mx0);
        sacc[nt][1] = __expf(sacc[nt][1] - mx0);
        sacc[nt][2] = __expf(sacc[nt][2] - mx1);
        sacc[nt][3] = __expf(sacc[nt][3] - mx1);
        sm0 += sacc[nt][0] + sacc[nt][1];
        sm1 += sacc[nt][2] + sacc[nt][3];
    }
    #pragma unroll
    for (int o = 1; o <= 2; o <<= 1) {
        sm0 += __shfl_xor_sync(0xffffffffu, sm0, o);
        sm1 += __shfl_xor_sync(0xffffffffu, sm1, o);
    }
    __syncthreads();

    const bf16* Wsh = Wth + (long)head * DH * MM;
    const bf16* Wsl = Wtl + (long)head * DH * MM;
    auto wissue = [&](int it) {
        int stg = it % 3;
        uint32_t base = sb + FA_WS + stg * FA_WST;
        #pragma unroll
        for (int i = 0; i < 2; i++) {
            int s = tid + 128 * i;
            int r = s >> 2, seg = s & 3;
            long go = (long)r * MM + it * 32 + seg * 8;
            cpa16(base + r * 80 + seg * 16, Wsh + go, 16);
            cpa16(base + 5120 + r * 80 + seg * 16, Wsl + go, 16);
        }
        asm volatile("cp.async.commit_group;");
    };
    wissue(0); wissue(1);

    {
        int pr = warp * 16 + (lane >> 2);
        int pc = (lane & 3) * 2;
        #pragma unroll
        for (int nt = 0; nt < 32; nt++) {
            int col = nt * 8 + pc;
            float h0, l0, h1, l1;
            split_bf(sacc[nt][0], h0, l0); split_bf(sacc[nt][1], h1, l1);
            *reinterpret_cast<uint32_t*>(sm + FA_PH + pr * 528 + col * 2) = pack2(h0, h1);
            *reinterpret_cast<uint32_t*>(sm + FA_PL + pr * 528 + col * 2) = pack2(l0, l1);
            split_bf(sacc[nt][2], h0, l0); split_bf(sacc[nt][3], h1, l1);
            *reinterpret_cast<uint32_t*>(sm + FA_PH + (pr + 8) * 528 + col * 2) = pack2(h0, h1);
            *reinterpret_cast<uint32_t*>(sm + FA_PL + (pr + 8) * 528 + col * 2) = pack2(l0, l1);
        }
    }
    __syncthreads();

    float oacc[8][4];
    #pragma unroll
    for (int i = 0; i < 8; i++)
        #pragma unroll
        for (int j = 0; j < 4; j++) oacc[i][j] = 0.f;

    for (int it = 0; it < 8; it++) {
        if (it < 7) asm volatile("cp.async.wait_group 1;");
        else        asm volatile("cp.async.wait_group 0;");
        __syncthreads();
        if (it + 2 < 8) wissue(it + 2);
        uint32_t wb = sb + FA_WS + (it % 3) * FA_WST;
        #pragma unroll
        for (int k16 = 0; k16 < 2; k16++) {
            int gk = it * 2 + k16;
            uint32_t ph[4], pl[4];
            uint32_t ad = sb + FA_PH + (warp * 16 + rsel) * 528 + gk * 32 + ksel;
            ldsm4(ad, ph[0], ph[1], ph[2], ph[3]);
            ldsm4(ad + (FA_PL - FA_PH), pl[0], pl[1], pl[2], pl[3]);
            #pragma unroll
            for (int n16 = 0; n16 < 4; n16++) {
                uint32_t bd = wb + (n16 * 16 + rsel) * 80 + k16 * 32 + ksel;
                uint32_t q0, q1, q2, q3, r0, r1, r2, r3;
                ldsm4(bd, q0, q1, q2, q3);
                ldsm4(bd + 5120, r0, r1, r2, r3);
                mma_bf16(oacc[2*n16],   ph, q0, q2);
                mma_bf16(oacc[2*n16],   ph, r0, r2);
                mma_bf16(oacc[2*n16],   pl, q0, q2);
                mma_bf16(oacc[2*n16+1], ph, q1, q3);
                mma_bf16(oacc[2*n16+1], ph, r1, r3);
                mma_bf16(oacc[2*n16+1], pl, q1, q3);
            }
        }
    }

    float inv0 = 1.f / sm0, inv1 = 1.f / sm1;
    int orow = row0 + warp * 16 + (lane >> 2);
    int ocol = head * DH + (lane & 3) * 2;
    #pragma unroll
    for (int nt = 0; nt < 8; nt++) {
        int col = ocol + nt * 8;
        *reinterpret_cast<float2*>(attn + (long)orow * C + col) =
            make_float2(oacc[nt][0] * inv0, oacc[nt][1] * inv0);
        *reinterpret_cast<float2*>(attn + (long)(orow + 8) * C + col) =
            make_float2(oacc[nt][2] * inv1, oacc[nt][3] * inv1);
    }
}

// =======================================================================
// auxiliary kernels
// =======================================================================

__global__ void wconvT_k(const float* __restrict__ w, bf16* __restrict__ th,
                         bf16* __restrict__ tl, int K, int N)
{
    int i = blockIdx.x * 256 + threadIdx.x;
    if (i >= N * K) return;
    int n = i / K, k = i - n * K;
    float v = w[(long)k * N + n];
    float hi, lo; split_bf(v, hi, lo);
    th[i] = __float2bfloat16(hi);
    tl[i] = __float2bfloat16(lo);
}

__global__ void build_h_k(const float* __restrict__ feat, const float* __restrict__ cls,
                          float* __restrict__ h)
{
    long i = (long)blockIdx.x * 256 + threadIdx.x;
    if (i >= (long)NH * C) return;
    long t = i >> 9;
    int  c = (int)(i & 511);
    float v;
    if (t == 0) v = cls[c];
    else {
        long r = t - 1;
        if (r >= NFEAT) r -= NFEAT;
        v = feat[r * C + c];
    }
    h[i] = v;
}

__global__ void ln_pad_k(const float* __restrict__ h, bf16* __restrict__ xh,
                         bf16* __restrict__ xl,
                         const float* __restrict__ g, const float* __restrict__ b)
{
    int t = blockIdx.x, c = threadIdx.x;
    long o = (long)t * C;
    if (t < PADN) {
        *reinterpret_cast<uint32_t*>(xh + o + 2 * c) = 0u;
        *reinterpret_cast<uint32_t*>(xl + o + 2 * c) = 0u;
        return;
    }
    const float* row = h + (long)(t - PADN) * C;
    float a1 = row[2 * c], a2 = row[2 * c + 1];
    __shared__ float red[256];
    red[c] = a1 + a2; __syncthreads();
    for (int s = 128; s > 0; s >>= 1) { if (c < s) red[c] += red[c + s]; __syncthreads(); }
    float mu = red[0] * (1.f / 512.f);
    __syncthreads();
    float d1 = a1 - mu, d2 = a2 - mu;
    red[c] = d1 * d1 + d2 * d2; __syncthreads();
    for (int s = 128; s > 0; s >>= 1) { if (c < s) red[c] += red[c + s]; __syncthreads(); }
    float inv = rsqrtf(red[0] * (1.f / 512.f) + 1e-5f);
    float v1 = d1 * inv * g[2 * c] + b[2 * c];
    float v2 = d2 * inv * g[2 * c + 1] + b[2 * c + 1];
    float h1, l1, h2, l2;
    split_bf(v1, h1, l1); split_bf(v2, h2, l2);
    *reinterpret_cast<uint32_t*>(xh + o + 2 * c) = pack2(h1, h2);
    *reinterpret_cast<uint32_t*>(xl + o + 2 * c) = pack2(l1, l2);
}

__global__ void landmarks_k(const bf16* __restrict__ qh, const bf16* __restrict__ ql_,
                            bf16* __restrict__ qlh, bf16* __restrict__ qll,
                            bf16* __restrict__ klh, bf16* __restrict__ kll)
{
    int d = threadIdx.x;
    int m = blockIdx.x & 255;
    int hh = blockIdx.x >> 8;
    long base = (long)(m * LL) * QKVW + hh * DH + d;
    float sq = 0.f, sk = 0.f;
    for (int j = 0; j < LL; j++) {
        long o = base + (long)j * QKVW;
        sq += pairval(qh, ql_, o);
        sk += pairval(qh, ql_, o + 512);
    }
    float vq = sq * (0.125f / (float)LL);
    float vk = sk * (1.f / (float)LL);
    int oi = (hh * MM + m) * DH + d;
    float hi, lo;
    split_bf(vq, hi, lo); qlh[oi] = __float2bfloat16(hi); qll[oi] = __float2bfloat16(lo);
    split_bf(vk, hi, lo); klh[oi] = __float2bfloat16(hi); kll[oi] = __float2bfloat16(lo);
}

__global__ void softmax256_k(const float* __restrict__ in, float* __restrict__ fout,
                             bf16* __restrict__ ph, bf16* __restrict__ pl, long nrows)
{
    long row = (long)blockIdx.x * 8 + threadIdx.y;
    if (row >= nrows) return;
    const float* r = in + row * 256;
    int lane = threadIdx.x;
    float v[8], m = -1e30f;
    #pragma unroll
    for (int i = 0; i < 8; i++) { v[i] = r[lane + 32 * i]; m = fmaxf(m, v[i]); }
    #pragma unroll
    for (int o = 16; o; o >>= 1) m = fmaxf(m, __shfl_xor_sync(0xffffffffu, m, o));
    float s = 0.f;
    #pragma unroll
    for (int i = 0; i < 8; i++) { v[i] = __expf(v[i] - m); s += v[i]; }
    #pragma unroll
    for (int o = 16; o; o >>= 1) s += __shfl_xor_sync(0xffffffffu, s, o);
    float inv = 1.f / s;
    #pragma unroll
    for (int i = 0; i < 8; i++) {
        float val = v[i] * inv;
        long o = row * 256 + lane + 32 * i;
        if (fout) fout[o] = val;
        float hi, lo; split_bf(val, hi, lo);
        ph[o] = __float2bfloat16(hi);
        pl[o] = __float2bfloat16(lo);
    }
}

__global__ void pinv_sums_k(const float* __restrict__ a2,
                            float* __restrict__ rs, float* __restrict__ cs)
{
    int hh = blockIdx.x, j = threadIdx.x;
    const float* X = a2 + (long)hh * MM * MM;
    float r = 0.f, c = 0.f;
    for (int k = 0; k < MM; k++) { r += fabsf(X[j * MM + k]); c += fabsf(X[k * MM + j]); }
    rs[hh * MM + j] = r; cs[hh * MM + j] = c;
}
__global__ void pinv_scale_k(const float* __restrict__ rs, const float* __restrict__ cs,
                             float* __restrict__ scale)
{
    __shared__ float m1[256], m2[256];
    float a = -1e30f, b = -1e30f;
    for (int i = threadIdx.x; i < HEADS * MM; i += 256) { a = fmaxf(a, rs[i]); b = fmaxf(b, cs[i]); }
    m1[threadIdx.x] = a; m2[threadIdx.x] = b; __syncthreads();
    for (int s = 128; s > 0; s >>= 1) {
        if (threadIdx.x < s) {
            m1[threadIdx.x] = fmaxf(m1[threadIdx.x], m1[threadIdx.x + s]);
            m2[threadIdx.x] = fmaxf(m2[threadIdx.x], m2[threadIdx.x + s]);
        }
        __syncthreads();
    }
    if (threadIdx.x == 0) scale[0] = 1.f / (m1[0] * m2[0]);
}
__global__ void pinv_init_k(const float* __restrict__ a2, const float* __restrict__ scale,
                            bf16* __restrict__ zph, bf16* __restrict__ zpl,
                            bf16* __restrict__ zth, bf16* __restrict__ ztl)
{
    long i = (long)blockIdx.x * 256 + threadIdx.x;
    if (i >= (long)HEADS * MM * MM) return;
    float s = scale[0];
    long hb = i & ~65535L;
    int r = (int)((i >> 8) & 255), c = (int)(i & 255);
    float vt = a2[i] * s;
    float vp = a2[hb + ((long)c << 8) + r] * s;
    float hi, lo;
    split_bf(vt, hi, lo); zth[i] = __float2bfloat16(hi); ztl[i] = __float2bfloat16(lo);
    split_bf(vp, hi, lo); zph[i] = __float2bfloat16(hi); zpl[i] = __float2bfloat16(lo);
}

__global__ void vT_k(const bf16* __restrict__ qh, const bf16* __restrict__ ql_,
                     bf16* __restrict__ vth, bf16* __restrict__ vtl)
{
    __shared__ bf16 tile[32][33];
    int t0 = blockIdx.x * 32;
    int head = blockIdx.y >> 1;
    int lopart = blockIdx.y & 1;
    int d0 = blockIdx.z * 32;
    const bf16* src = (lopart ? ql_ : qh) + 1024 + head * 64 + d0;
    bf16* dst = (lopart ? vtl : vth) + (long)head * 64 * NP + (long)d0 * NP;
    int tx = threadIdx.x, ty = threadIdx.y;
    #pragma unroll
    for (int i = 0; i < 4; i++)
        tile[ty + 8 * i][tx] = src[(long)(t0 + ty + 8 * i) * QKVW + tx];
    __syncthreads();
    #pragma unroll
    for (int i = 0; i < 4; i++)
        dst[(long)(ty + 8 * i) * NP + t0 + tx] = tile[tx][ty + 8 * i];
}

// =======================================================================
// conv_add: smem-tiled depthwise 33-tap over tokens.
// =======================================================================
#define CA_ROWS 64
#define CA_HALO 96
#define CA_SMEM (CA_HALO * 64 * 8)

__global__ void __launch_bounds__(256)
conv_add_k(const bf16* __restrict__ qh, const bf16* __restrict__ ql_,
           const float* __restrict__ rw, const float* __restrict__ attnf,
           bf16* __restrict__ ah, bf16* __restrict__ al)
{
    extern __shared__ __align__(16) float2 vt[];
    const int tid = threadIdx.x;
    const int t0 = blockIdx.x * CA_ROWS;
    const int cb = blockIdx.y * 128;

    for (int idx = tid; idx < CA_HALO * 64; idx += 256) {
        int row = idx >> 6, c2 = idx & 63;
        int gt = t0 + row - 16;
        float2 v = make_float2(0.f, 0.f);
        if ((unsigned)gt < (unsigned)NP) {
            long o = (long)gt * QKVW + 1024 + cb + 2 * c2;
            __nv_bfloat162 h2 = *reinterpret_cast<const __nv_bfloat162*>(qh + o);
            __nv_bfloat162 l2 = *reinterpret_cast<const __nv_bfloat162*>(ql_ + o);
            v.x = __bfloat162float(h2.x) + __bfloat162float(l2.x);
            v.y = __bfloat162float(h2.y) + __bfloat162float(l2.y);
        }
        vt[idx] = v;
    }
    __syncthreads();

    const int c2 = tid & 63;
    const int tsub = tid >> 6;
    const int head = (cb + 2 * c2) >> 6;
    float w[33];
    #pragma unroll
    for (int k = 0; k < 33; k++) w[k] = rw[head * 33 + k];

    for (int i = 0; i < 16; i++) {
        int tloc = tsub * 16 + i;
        int t = t0 + tloc;
        float2 a = *reinterpret_cast<const float2*>(attnf + (long)t * C + cb + 2 * c2);
        float acc0 = a.x, acc1 = a.y;
        #pragma unroll
        for (int k = 0; k < 33; k++) {
            float2 v = vt[(tloc + k) * 64 + c2];
            acc0 += v.x * w[k];
            acc1 += v.y * w[k];
        }
        float h0, l0, h1, l1;
        split_bf(acc0, h0, l0); split_bf(acc1, h1, l1);
        long o = (long)t * C + cb + 2 * c2;
        *reinterpret_cast<uint32_t*>(ah + o) = pack2(h0, h1);
        *reinterpret_cast<uint32_t*>(al + o) = pack2(l0, l1);
    }
}

// =======================================================================
// PPEG: smem-tiled combined 49-tap stencil
// =======================================================================
#define PT        16
#define PTH       22
#define PG_TILE   (PTH * PTH * 32 * 4)
#define PG_WOFF   PG_TILE
#define PG_W      (49 * 32 * 4)
#define PG_BOFF   (PG_WOFF + PG_W)
#define PG_SMEM   (PG_BOFF + 32 * 4)

__global__ void __launch_bounds__(256, 2)
ppeg_k(const float* __restrict__ h, float* __restrict__ h2,
       const float* __restrict__ w7, const float* __restrict__ b7,
       const float* __restrict__ w5, const float* __restrict__ b5,
       const float* __restrict__ w3, const float* __restrict__ b3)
{
    extern __shared__ __align__(16) char smraw[];
    float* tile  = reinterpret_cast<float*>(smraw);
    float* wcomb = reinterpret_cast<float*>(smraw + PG_WOFF);
    float* biasc = reinterpret_cast<float*>(smraw + PG_BOFF);

    const int tid = threadIdx.x;
    const int cg = blockIdx.z;
    const int x0 = blockIdx.x * PT, y0 = blockIdx.y * PT;
    const int cb = cg * 32;

    if (blockIdx.x == 0 && blockIdx.y == 0 && tid < 32)
        h2[cb + tid] = h[cb + tid];

    {
        int c = tid & 31, slot = tid >> 5;
        for (int pix = slot; pix < PTH * PTH; pix += 8) {
            int py = pix / PTH, px = pix - py * PTH;
            int gy = y0 + py - 3, gx = x0 + px - 3;
            float v = 0.f;
            if ((unsigned)gy < (unsigned)HW && (unsigned)gx < (unsigned)HW)
                v = h[(long)(1 + gy * HW + gx) * C + cb + c];
            tile[pix * 32 + c] = v;
        }
    }

    for (int i = tid; i < 49 * 32; i += 256) {
        int k = i >> 5, c = i & 31;
        int dy = k / 7 - 3, dx = k % 7 - 3;
        float w = w7[(cb + c) * 49 + (dy + 3) * 7 + (dx + 3)];
        if (dy >= -2 && dy <= 2 && dx >= -2 && dx <= 2)
            w += w5[(cb + c) * 25 + (dy + 2) * 5 + (dx + 2)];
        if (dy >= -1 && dy <= 1 && dx >= -1 && dx <= 1)
            w += w3[(cb + c) * 9 + (dy + 1) * 3 + (dx + 1)];
        if (dy == 0 && dx == 0) w += 1.f;
        wcomb[i] = w;
    }
    if (tid < 32) biasc[tid] = b7[cb + tid] + b5[cb + tid] + b3[cb + tid];
    __syncthreads();

    const int warp = tid >> 5, c = tid & 31;
    float acc[32];
    #pragma unroll
    for (int p = 0; p < 32; p++) acc[p] = 0.f;

    for (int k = 0; k < 49; k++) {
        float wv = wcomb[k * 32 + c];
        int dy = k / 7, dx = k - (k / 7) * 7;
        int base = ((2 * warp + dy) * PTH + dx) * 32 + c;
        #pragma unroll
        for (int p = 0; p < 32; p++) {
            int py = p >> 4, px = p & 15;
            acc[p] += tile[base + (py * PTH + px) * 32] * wv;
        }
    }

    float bv = biasc[c];
    #pragma unroll
    for (int p = 0; p < 32; p++) {
        int y = y0 + 2 * warp + (p >> 4), x = x0 + (p & 15);
        if (y < HW && x < HW)
            h2[(long)(1 + y * HW + x) * C + cb + c] = acc[p] + bv;
    }
}

// ================= host orchestration =================
struct Ptrs {
    float *h, *h2, *a2, *attn, *outl, *rowsum, *colsum, *fm, *fs, *scale;
    bf16 *xph, *xpl, *qkvh, *qkvl, *qlh, *qll, *klh, *kll,
         *a2h, *a2l, *zh, *zl, *zth, *ztl, *z2h, *z2l, *z2th, *z2tl,
         *xzh, *xzl, *tah, *tal, *tbh, *tbl, *vth, *vtl,
         *a3h, *a3l, *Wth, *Wtl, *ath, *atl,
         *w1ah, *w1al, *w2ah, *w2al, *w1bh, *w1bl, *w2bh, *w2bl;
};
#define GSYM(f, s) cudaGetSymbolAddress((void**)&p.f, s)
static void get_ptrs(Ptrs& p)
{
    GSYM(h, g_h); GSYM(h2, g_h2); GSYM(a2, g_a2);
    GSYM(attn, g_attn); GSYM(outl, g_outl);
    GSYM(rowsum, g_rowsum); GSYM(colsum, g_colsum);
    GSYM(fm, g_fm); GSYM(fs, g_fs); GSYM(scale, g_scale);
    GSYM(xph, g_xph); GSYM(xpl, g_xpl); GSYM(qkvh, g_qkvh); GSYM(qkvl, g_qkvl);
    GSYM(qlh, g_qlh); GSYM(qll, g_qll); GSYM(klh, g_klh); GSYM(kll, g_kll);
    GSYM(a2h, g_a2h); GSYM(a2l, g_a2l);
    GSYM(zh, g_zh); GSYM(zl, g_zl); GSYM(zth, g_zth); GSYM(ztl, g_ztl);
    GSYM(z2h, g_z2h); GSYM(z2l, g_z2l); GSYM(z2th, g_z2th); GSYM(z2tl, g_z2tl);
    GSYM(xzh, g_xzh); GSYM(xzl, g_xzl);
    GSYM(tah, g_tah); GSYM(tal, g_tal); GSYM(tbh, g_tbh); GSYM(tbl, g_tbl);
    GSYM(vth, g_vth); GSYM(vtl, g_vtl); GSYM(a3h, g_a3h); GSYM(a3l, g_a3l);
    GSYM(Wth, g_Wth); GSYM(Wtl, g_Wtl); GSYM(ath, g_ath); GSYM(atl, g_atl);
    GSYM(w1ah, g_w1ah); GSYM(w1al, g_w1al); GSYM(w2ah, g_w2ah); GSYM(w2al, g_w2al);
    GSYM(w1bh, g_w1bh); GSYM(w1bl, g_w1bl); GSYM(w2bh, g_w2bh); GSYM(w2bl, g_w2bl);
}

// final GEMM writes `fout` with residual read from `resid_src`
static void nystrom_tail(Ptrs& p, float* resid_src, float* fout,
                         const bf16* w2h, const bf16* w2l,
                         const float* b_out, const float* res_w)
{
    const long MMh = (long)MM * MM;

    landmarks_k<<<HEADS * MM, DH>>>(p.qkvh, p.qkvl, p.qlh, p.qll, p.klh, p.kll);
    vT_k<<<dim3(NP / 32, HEADS * 2, 2), dim3(32, 8)>>>(p.qkvh, p.qkvl, p.vth, p.vtl);

    { EpiOut e = epi0(); e.f = p.a2; e.falpha = 1.f; e.ldf = MM; e.sF = MMh;
      gemmP(p.qlh, p.qll, p.klh, p.kll, MM, MM, DH, DH, DH,
            (long)MM * DH, (long)MM * DH, HEADS, 1, e); }
    softmax256_k<<<(HEADS * MM + 7) / 8, dim3(32, 8)>>>(p.a2, p.a2, p.a2h, p.a2l, HEADS * MM);

    pinv_sums_k<<<HEADS, 256>>>(p.a2, p.rowsum, p.colsum);
    pinv_scale_k<<<1, 256>>>(p.rowsum, p.colsum, p.scale);
    pinv_init_k<<<(int)((HEADS * MMh + 255) / 256), 256>>>(p.a2, p.scale,
                                                           p.zh, p.zl, p.zth, p.ztl);
    bf16 *zch = p.zh, *zcl = p.zl, *zcth = p.zth, *zctl = p.ztl;
    bf16 *znh = p.z2h, *znl = p.z2l, *znth = p.z2th, *zntl = p.z2tl;
    for (int it = 0; it < 6; it++) {
        { EpiOut e = epi0();
          e.ph = p.xzh; e.pl = p.xzl; e.palpha = 1.f; e.ldp = MM; e.sP = MMh;
          e.th = p.tah; e.tl = p.tal; e.talpha = -1.f; e.tdiag = 7.f; e.ldt = MM; e.sT = MMh;
          gemmP(p.a2h, p.a2l, zcth, zctl, MM, MM, MM, MM, MM, MMh, MMh, HEADS, 1, e); }
        { EpiOut e = epi0();
          e.th = p.tbh; e.tl = p.tbl; e.talpha = -1.f; e.tdiag = 15.f; e.ldt = MM; e.sT = MMh;
          gemmP(p.xzh, p.xzl, p.tah, p.tal, MM, MM, MM, MM, MM, MMh, MMh, HEADS, 1, e); }
        { EpiOut e = epi0();
          e.th = p.tah; e.tl = p.tal; e.talpha = -1.f; e.tdiag = 13.f; e.ldt = MM; e.sT = MMh;
          gemmP(p.xzh, p.xzl, p.tbh, p.tbl, MM, MM, MM, MM, MM, MMh, MMh, HEADS, 1, e); }
        { EpiOut e = epi0();
          e.ph = znh; e.pl = znl; e.palpha = 0.25f; e.ldp = MM; e.sP = MMh;
          e.th = znth; e.tl = zntl; e.talpha = 0.25f; e.tdiag = 0.f; e.ldt = MM; e.sT = MMh;
          gemmP(zch, zcl, p.tah, p.tal, MM, MM, MM, MM, MM, MMh, MMh, HEADS, 1, e); }
        bf16* t;
        t = zch; zch = znh; znh = t;   t = zcl; zcl = znl; znl = t;
        t = zcth; zcth = znth; znth = t; t = zctl; zctl = zntl; zntl = t;
    }

    flash3_k<<<dim3(NSPLIT, 2, HEADS), 128, FL_SMEM>>>(
        p.qlh, p.qll, p.qkvh, p.qkvl, p.vth, p.vtl, p.outl, p.fm, p.fs);
    flash_merge_k<<<dim3(MM, HEADS), DH>>>(p.outl, p.fm, p.fs, p.a3h, p.a3l);

    { EpiOut e = epi0(); e.th = p.Wth; e.tl = p.Wtl; e.talpha = 1.f; e.tdiag = 0.f;
      e.ldt = MM; e.sT = (long)DH * MM;
      gemmP(zch, zcl, p.a3h, p.a3l, MM, DH, MM, MM, MM, MMh, (long)DH * MM, HEADS, 1, e); }

    fused_attn1_k<<<dim3(NP / 64, HEADS), 128, FA_SMEM>>>(
        p.qkvh, p.qkvl, p.klh, p.kll, p.Wth, p.Wtl, p.attn);

    conv_add_k<<<dim3(NP / CA_ROWS, C / 128), 256, CA_SMEM>>>(
        p.qkvh, p.qkvl, res_w, p.attn, p.ath, p.atl);

    { EpiOut e = epi0(); e.f = fout; e.falpha = 1.f; e.ldf = C;
      e.resid = resid_src; e.bias = b_out;
      gemmP(p.ath + (long)PADN * C, p.atl + (long)PADN * C, w2h, w2l,
            NH, C, C, C, C, 0, 0, 1, 1, e); }
}

extern "C" void kernel_launch(void* const* d_in, const int* in_sizes, int n_in,
                              void* d_out, int out_size)
{
    const float* features = (const float*)d_in[0];
    const float* cls      = (const float*)d_in[1];
    const float* ln1_g    = (const float*)d_in[2];
    const float* ln1_b    = (const float*)d_in[3];
    const float* qkv1_w   = (const float*)d_in[4];
    const float* out1_w   = (const float*)d_in[5];
    const float* out1_b   = (const float*)d_in[6];
    const float* res1_w   = (const float*)d_in[7];
    const float* pe_w7    = (const float*)d_in[8];
    const float* pe_b7    = (const float*)d_in[9];
    const float* pe_w5    = (const float*)d_in[10];
    const float* pe_b5    = (const float*)d_in[11];
    const float* pe_w3    = (const float*)d_in[12];
    const float* pe_b3    = (const float*)d_in[13];
    const float* ln2_g    = (const float*)d_in[14];
    const float* ln2_b    = (const float*)d_in[15];
    const float* qkv2_w   = (const float*)d_in[16];
    const float* out2_w   = (const float*)d_in[17];
    const float* out2_b   = (const float*)d_in[18];
    const float* res2_w   = (const float*)d_in[19];

    cudaFuncSetAttribute(gemm_p,  cudaFuncAttributeMaxDynamicSharedMemorySize, GP_SMEM);
    cudaFuncSetAttribute(gemm_p2, cudaFuncAttributeMaxDynamicSharedMemorySize, GP2_SMEM);
    cudaFuncSetAttribute(fused_attn1_k, cudaFuncAttributeMaxDynamicSharedMemorySize, FA_SMEM);
    cudaFuncSetAttribute(flash3_k, cudaFuncAttributeMaxDynamicSharedMemorySize, FL_SMEM);
    cudaFuncSetAttribute(ppeg_k, cudaFuncAttributeMaxDynamicSharedMemorySize, PG_SMEM);
    cudaFuncSetAttribute(conv_add_k, cudaFuncAttributeMaxDynamicSharedMemorySize, CA_SMEM);

    Ptrs p; get_ptrs(p);
    float* outp = (float*)d_out;

    build_h_k<<<(int)(((long)NH * C + 255) / 256), 256>>>(features, cls, p.h);
    wconvT_k<<<(QKVW * C + 255) / 256, 256>>>(qkv1_w, p.w1ah, p.w1al, C, QKVW);
    ln_pad_k<<<NP, 256>>>(p.h, p.xph, p.xpl, ln1_g, ln1_b);
    { EpiOut e = epi0(); e.ph = p.qkvh; e.pl = p.qkvl; e.palpha = 1.f; e.ldp = QKVW;
      gemmP(p.xph, p.xpl, p.w1ah, p.w1al, NP, QKVW, C, C, C, 0, 0, 1, 1, e); }

    wconvT_k<<<(C * C + 255) / 256, 256>>>(out1_w, p.w2ah, p.w2al, C, C);
    wconvT_k<<<(QKVW * C + 255) / 256, 256>>>(qkv2_w, p.w1bh, p.w1bl, C, QKVW);
    wconvT_k<<<(C * C + 255) / 256, 256>>>(out2_w, p.w2bh, p.w2bl, C, C);

    // layer 1 tail: h += ... (in place)
    nystrom_tail(p, p.h, p.h, p.w2ah, p.w2al, out1_b, res1_w);

    ppeg_k<<<dim3((HW + PT - 1) / PT, (HW + PT - 1) / PT, 16), 256, PG_SMEM>>>(
        p.h, p.h2, pe_w7, pe_b7, pe_w5, pe_b5, pe_w3, pe_b3);

    ln_pad_k<<<NP, 256>>>(p.h2, p.xph, p.xpl, ln2_g, ln2_b);
    { EpiOut e = epi0(); e.ph = p.qkvh; e.pl = p.qkvl; e.palpha = 1.f; e.ldp = QKVW;
      gemmP(p.xph, p.xpl, p.w1bh, p.w1bl, NP, QKVW, C, C, C, 0, 0, 1, 1, e); }
    // layer 2 tail: d_out = h2 + proj(...)
    nystrom_tail(p, p.h2, outp, p.w2bh, p.w2bl, out2_b, res2_w);
}